// round 1
// baseline (speedup 1.0000x reference)
#include <cuda_runtime.h>
#include <math.h>

#define CC 96
#define DD 40
#define HH 48
#define WW_ 40
#define BB 2
#define WIN_D 5
#define WIN_H 6
#define WIN_W 5
#define NT 150
#define NWD 8
#define NWH 8
#define NWW 8
#define NWIN 1024
#define SPD (DD*HH*WW_)   /* 76800 */
#define TOT (BB*SPD)      /* 153600 */
#define HID 384

// ---------------- scratch (device globals; no allocation) ----------------
__device__ __align__(128) float g_xt [TOT*CC];        // transposed I_m (shortcut)
__device__ __align__(128) float g_q  [NWIN*NT*CC];
__device__ __align__(128) float g_k  [NWIN*NT*CC];
__device__ __align__(128) float g_v  [NWIN*NT*CC];
__device__ __align__(128) float g_x2 [TOT*CC];        // after attention residual
__device__ __align__(128) float g_x3 [TOT*CC];        // after MLP residual
__device__ __align__(128) float g_act[TOT*HID];       // MLP hidden
__device__ __align__(128) float g_bias[NT*NT];        // rel-pos bias matrix

__device__ __forceinline__ float warp_sum(float v) {
    #pragma unroll
    for (int o = 16; o > 0; o >>= 1) v += __shfl_xor_sync(0xffffffffu, v, o);
    return v;
}
__device__ __forceinline__ float warp_max(float v) {
    #pragma unroll
    for (int o = 16; o > 0; o >>= 1) v = fmaxf(v, __shfl_xor_sync(0xffffffffu, v, o));
    return v;
}
__device__ __forceinline__ float gelu_tanh(float x) {
    float x3 = x * x * x;
    return 0.5f * x * (1.0f + tanhf(0.79788456080286535588f * (x + 0.044715f * x3)));
}

// ---------------- K0: relative position bias table ----------------
__global__ void bias_kernel(const float* __restrict__ rel_bias) {
    int i = blockIdx.x * blockDim.x + threadIdx.x;
    if (i >= NT * NT) return;
    int n = i / NT, m = i % NT;
    int nd = n / 30, nh = (n / 5) % 6, nw = n % 5;
    int md = m / 30, mh = (m / 5) % 6, mw = m % 5;
    int idx = (nd - md + 4) * 99 + (nh - mh + 5) * 9 + (nw - mw + 4);
    g_bias[i] = rel_bias[idx];
}

// ---------------- K1/K2: transpose + LN + projection (window layout) ----------------
// block = 256 threads (8 warps), 32 consecutive tokens per block.
// dyn smem: tile[96*33] | sW[96*COUT] | sB[COUT] | sLN[8*4*96]
template<int COUT, bool ISQ>
__global__ void lnproj_kernel(const float* __restrict__ in,      // (B, C, SPD)
                              const float* __restrict__ gamma,
                              const float* __restrict__ beta,
                              const float* __restrict__ wmat,    // (C, COUT)
                              const float* __restrict__ bvec) {  // (COUT)
    extern __shared__ float sm[];
    float* tile = sm;                 // 96*33
    float* sW   = tile + 96 * 33;     // 96*COUT
    float* sB   = sW + 96 * COUT;     // COUT
    float* sLN  = sB + COUT;          // 8*4*96

    int tid = threadIdx.x, warp = tid >> 5, lane = tid & 31;
    long t0 = (long)blockIdx.x * 32;
    int b  = (int)(t0 / SPD);
    int s0 = (int)(t0 % SPD);

    for (int i = tid; i < 96 * COUT; i += 256) sW[i] = wmat[i];
    for (int i = tid; i < COUT; i += 256)      sB[i] = bvec[i];
    const float* inb = in + (long)b * 96 * SPD + s0;
    for (int i = tid; i < 96 * 32; i += 256) {
        int c = i >> 5, j = i & 31;
        tile[c * 33 + j] = inb[(long)c * SPD + j];
    }
    __syncthreads();

    if (ISQ) {  // write transposed shortcut
        for (int i = tid; i < 96 * 32; i += 256) {
            int c = i % 96, j = i / 96;
            g_xt[(t0 + j) * 96 + c] = tile[c * 33 + j];
        }
    }

    // LN for this warp's 4 tokens
    float* myLN = sLN + warp * 4 * 96;
    #pragma unroll
    for (int tt = 0; tt < 4; tt++) {
        int j = warp * 4 + tt;
        float v0 = tile[lane * 33 + j];
        float v1 = tile[(lane + 32) * 33 + j];
        float v2 = tile[(lane + 64) * 33 + j];
        float mean = warp_sum(v0 + v1 + v2) * (1.0f / 96.0f);
        float var  = warp_sum(v0 * v0 + v1 * v1 + v2 * v2) * (1.0f / 96.0f) - mean * mean;
        float inv  = rsqrtf(var + 1e-5f);
        myLN[tt * 96 + lane]      = (v0 - mean) * inv * gamma[lane]      + beta[lane];
        myLN[tt * 96 + lane + 32] = (v1 - mean) * inv * gamma[lane + 32] + beta[lane + 32];
        myLN[tt * 96 + lane + 64] = (v2 - mean) * inv * gamma[lane + 64] + beta[lane + 64];
    }
    __syncwarp();

    // window-layout addresses for the 4 tokens
    long addr[4];
    #pragma unroll
    for (int tt = 0; tt < 4; tt++) {
        long t = t0 + warp * 4 + tt;
        int s = (int)(t % SPD);
        int d = s / (HH * WW_), h = (s / WW_) % HH, w = s % WW_;
        int wi = ((b * NWD + d / WIN_D) * NWH + h / WIN_H) * NWW + w / WIN_W;
        int n  = (d % WIN_D) * (WIN_H * WIN_W) + (h % WIN_H) * WIN_W + (w % WIN_W);
        addr[tt] = ((long)wi * NT + n) * 96;
    }

    const float4* L0 = (const float4*)(myLN);
    const float4* L1 = (const float4*)(myLN + 96);
    const float4* L2 = (const float4*)(myLN + 192);
    const float4* L3 = (const float4*)(myLN + 288);
    for (int jj = lane; jj < COUT; jj += 32) {
        float a0 = 0.f, a1 = 0.f, a2 = 0.f, a3 = 0.f;
        #pragma unroll 6
        for (int c4 = 0; c4 < 24; c4++) {
            float4 l0 = L0[c4], l1 = L1[c4], l2 = L2[c4], l3 = L3[c4];
            const float* wp = sW + c4 * 4 * COUT + jj;
            float w0 = wp[0], w1 = wp[COUT], w2 = wp[2 * COUT], w3 = wp[3 * COUT];
            a0 += l0.x * w0 + l0.y * w1 + l0.z * w2 + l0.w * w3;
            a1 += l1.x * w0 + l1.y * w1 + l1.z * w2 + l1.w * w3;
            a2 += l2.x * w0 + l2.y * w1 + l2.z * w2 + l2.w * w3;
            a3 += l3.x * w0 + l3.y * w1 + l3.z * w2 + l3.w * w3;
        }
        float bb = sB[jj];
        a0 += bb; a1 += bb; a2 += bb; a3 += bb;
        if (COUT == 96) {
            g_q[addr[0] + jj] = a0; g_q[addr[1] + jj] = a1;
            g_q[addr[2] + jj] = a2; g_q[addr[3] + jj] = a3;
        } else {
            float* dst = (jj < 96) ? g_k : g_v;
            int j2 = (jj < 96) ? jj : jj - 96;
            dst[addr[0] + j2] = a0; dst[addr[1] + j2] = a1;
            dst[addr[2] + j2] = a2; dst[addr[3] + j2] = a3;
        }
    }
}

// ---------------- K3: per-window attention + out-proj + residual ----------------
// block = 512 threads (16 warps) per window. dyn smem:
//   sQ[150*96] | sKV[150*96] | sS[150*150]  (wproj/bproj overlay sS in phase E)
__global__ void attn_kernel(const float* __restrict__ wproj,
                            const float* __restrict__ bproj) {
    extern __shared__ float sm[];
    float* sQ  = sm;
    float* sKV = sQ + NT * 96;
    float* sS  = sKV + NT * 96;
    int tid = threadIdx.x, warp = tid >> 5, lane = tid & 31;
    int wi = blockIdx.x;

    float4* sQ4  = (float4*)sQ;
    float4* sKV4 = (float4*)sKV;
    const float4* gq = (const float4*)(g_q + (long)wi * NT * 96);
    const float4* gk = (const float4*)(g_k + (long)wi * NT * 96);
    const float4* gv = (const float4*)(g_v + (long)wi * NT * 96);
    for (int i = tid; i < NT * 24; i += 512) { sQ4[i] = gq[i]; sKV4[i] = gk[i]; }
    __syncthreads();

    const float scale = 0.102062072615965696f;  // 96^-0.5

    // S = scale*Q.K^T + bias; softmax per row (one warp per row)
    for (int n = warp; n < NT; n += 16) {
        float acc[5] = {0.f, 0.f, 0.f, 0.f, 0.f};
        const float4* qrow = (const float4*)(sQ + n * 96);
        #pragma unroll 4
        for (int c4 = 0; c4 < 24; c4++) {
            float4 q4 = qrow[c4];
            #pragma unroll
            for (int kk = 0; kk < 5; kk++) {
                int m = lane + 32 * kk;
                if (m < NT) {
                    float4 k4 = ((const float4*)(sKV + m * 96))[c4];
                    acc[kk] += q4.x * k4.x + q4.y * k4.y + q4.z * k4.z + q4.w * k4.w;
                }
            }
        }
        float sval[5];
        float mx = -1e30f;
        #pragma unroll
        for (int kk = 0; kk < 5; kk++) {
            int m = lane + 32 * kk;
            if (m < NT) {
                sval[kk] = acc[kk] * scale + g_bias[n * NT + m];
                mx = fmaxf(mx, sval[kk]);
            }
        }
        mx = warp_max(mx);
        float sum = 0.f;
        #pragma unroll
        for (int kk = 0; kk < 5; kk++) {
            int m = lane + 32 * kk;
            if (m < NT) { sval[kk] = __expf(sval[kk] - mx); sum += sval[kk]; }
        }
        sum = warp_sum(sum);
        float inv = 1.0f / sum;
        #pragma unroll
        for (int kk = 0; kk < 5; kk++) {
            int m = lane + 32 * kk;
            if (m < NT) sS[n * NT + m] = sval[kk] * inv;
        }
    }
    __syncthreads();

    // V over K
    for (int i = tid; i < NT * 24; i += 512) sKV4[i] = gv[i];
    __syncthreads();

    // O = P @ V into sQ (Q no longer needed)
    for (int n = warp; n < NT; n += 16) {
        float4 acc = make_float4(0.f, 0.f, 0.f, 0.f);
        if (lane < 24) {
            const float* prow = sS + n * NT;
            for (int m = 0; m < NT; m++) {
                float p = prow[m];
                float4 v4 = ((const float4*)(sKV + m * 96))[lane];
                acc.x += p * v4.x; acc.y += p * v4.y;
                acc.z += p * v4.z; acc.w += p * v4.w;
            }
            ((float4*)(sQ + n * 96))[lane] = acc;
        }
    }
    __syncthreads();

    // wproj / bproj overlay the (now dead) sS region
    float* sW  = sS;
    float* sBp = sS + 96 * 96;
    for (int i = tid; i < 96 * 96; i += 512) sW[i] = wproj[i];
    if (tid < 96) sBp[tid] = bproj[tid];
    __syncthreads();

    int iww = wi & 7, iwh = (wi >> 3) & 7, iwd = (wi >> 6) & 7, b = wi >> 9;
    for (int n = warp; n < NT; n += 16) {
        if (lane < 24) {
            float4 acc = make_float4(0.f, 0.f, 0.f, 0.f);
            const float4* orow = (const float4*)(sQ + n * 96);
            #pragma unroll 4
            for (int c4 = 0; c4 < 24; c4++) {
                float4 o4 = orow[c4];
                int cb = c4 * 4;
                float4 w0 = ((const float4*)(sW + (cb + 0) * 96))[lane];
                float4 w1 = ((const float4*)(sW + (cb + 1) * 96))[lane];
                float4 w2 = ((const float4*)(sW + (cb + 2) * 96))[lane];
                float4 w3 = ((const float4*)(sW + (cb + 3) * 96))[lane];
                acc.x += o4.x * w0.x + o4.y * w1.x + o4.z * w2.x + o4.w * w3.x;
                acc.y += o4.x * w0.y + o4.y * w1.y + o4.z * w2.y + o4.w * w3.y;
                acc.z += o4.x * w0.z + o4.y * w1.z + o4.z * w2.z + o4.w * w3.z;
                acc.w += o4.x * w0.w + o4.y * w1.w + o4.z * w2.w + o4.w * w3.w;
            }
            int zd = n / 30, zh = (n / 5) % 6, zw = n % 5;
            int d = iwd * WIN_D + zd, h = iwh * WIN_H + zh, w = iww * WIN_W + zw;
            long t = (long)b * SPD + ((long)d * HH + h) * WW_ + w;
            float4 bp = ((const float4*)sBp)[lane];
            float4 sc = ((const float4*)(g_xt + t * 96))[lane];
            float4 r;
            r.x = sc.x + acc.x + bp.x; r.y = sc.y + acc.y + bp.y;
            r.z = sc.z + acc.z + bp.z; r.w = sc.w + acc.w + bp.w;
            ((float4*)(g_x2 + t * 96))[lane] = r;
        }
    }
}

// ---------------- K4: LN2 + fc1 + gelu ----------------
// block = 512 (16 warps) x 4 tokens each. dyn smem: sW1[96*384] | sB1[384] | sH[16*96]
__global__ void mlp1_kernel(const float* __restrict__ g2, const float* __restrict__ b2,
                            const float* __restrict__ w1, const float* __restrict__ b1) {
    extern __shared__ float sm[];
    float* sW = sm;                 // 36864
    float* sB = sW + 96 * HID;      // 384
    float* sH = sB + HID;           // 16*96
    int tid = threadIdx.x, warp = tid >> 5, lane = tid & 31;
    for (int i = tid; i < 96 * HID; i += 512) sW[i] = w1[i];
    for (int i = tid; i < HID; i += 512)      sB[i] = b1[i];
    __syncthreads();

    long t0 = (long)blockIdx.x * 64;
    float* h = sH + warp * 96;
    for (int it = 0; it < 4; it++) {
        long t = t0 + warp * 4 + it;
        const float* xr = g_x2 + t * 96;
        float v0 = xr[lane], v1 = xr[lane + 32], v2 = xr[lane + 64];
        float mean = warp_sum(v0 + v1 + v2) * (1.0f / 96.0f);
        float var  = warp_sum(v0 * v0 + v1 * v1 + v2 * v2) * (1.0f / 96.0f) - mean * mean;
        float inv  = rsqrtf(var + 1e-5f);
        h[lane]      = (v0 - mean) * inv * g2[lane]      + b2[lane];
        h[lane + 32] = (v1 - mean) * inv * g2[lane + 32] + b2[lane + 32];
        h[lane + 64] = (v2 - mean) * inv * g2[lane + 64] + b2[lane + 64];
        __syncwarp();

        float4 acc[3];
        acc[0] = acc[1] = acc[2] = make_float4(0.f, 0.f, 0.f, 0.f);
        const float4* h4p = (const float4*)h;
        #pragma unroll 4
        for (int c4 = 0; c4 < 24; c4++) {
            float4 h4 = h4p[c4];
            int cb = c4 * 4;
            #pragma unroll
            for (int g = 0; g < 3; g++) {
                int j4 = lane + 32 * g;
                float4 w0 = ((const float4*)(sW + (cb + 0) * HID))[j4];
                float4 w1v = ((const float4*)(sW + (cb + 1) * HID))[j4];
                float4 w2v = ((const float4*)(sW + (cb + 2) * HID))[j4];
                float4 w3v = ((const float4*)(sW + (cb + 3) * HID))[j4];
                acc[g].x += h4.x * w0.x + h4.y * w1v.x + h4.z * w2v.x + h4.w * w3v.x;
                acc[g].y += h4.x * w0.y + h4.y * w1v.y + h4.z * w2v.y + h4.w * w3v.y;
                acc[g].z += h4.x * w0.z + h4.y * w1v.z + h4.z * w2v.z + h4.w * w3v.z;
                acc[g].w += h4.x * w0.w + h4.y * w1v.w + h4.z * w2v.w + h4.w * w3v.w;
            }
        }
        float4* ga = (float4*)(g_act + t * HID);
        #pragma unroll
        for (int g = 0; g < 3; g++) {
            int j4 = lane + 32 * g;
            float4 bb = ((const float4*)sB)[j4];
            float4 r;
            r.x = gelu_tanh(acc[g].x + bb.x);
            r.y = gelu_tanh(acc[g].y + bb.y);
            r.z = gelu_tanh(acc[g].z + bb.z);
            r.w = gelu_tanh(acc[g].w + bb.w);
            ga[j4] = r;
        }
        __syncwarp();
    }
}

// ---------------- K5: fc2 + residual ----------------
// block = 512 (16 warps) x 4 tokens each. dyn smem: sW2[384*96] | sB2[96] | sA[16*384]
__global__ void mlp2_kernel(const float* __restrict__ w2, const float* __restrict__ b2) {
    extern __shared__ float sm[];
    float* sW = sm;                  // 36864
    float* sB = sW + HID * 96;       // 96
    float* sA = sB + 96;             // 16*384
    int tid = threadIdx.x, warp = tid >> 5, lane = tid & 31;
    for (int i = tid; i < HID * 96; i += 512) sW[i] = w2[i];
    if (tid < 96) sB[tid] = b2[tid];
    __syncthreads();

    long t0 = (long)blockIdx.x * 64;
    float4* a4 = (float4*)(sA + warp * HID);
    for (int it = 0; it < 4; it++) {
        long t = t0 + warp * 4 + it;
        const float4* ga4 = (const float4*)(g_act + t * HID);
        for (int i = lane; i < 96; i += 32) a4[i] = ga4[i];
        __syncwarp();
        if (lane < 24) {
            float4 acc = make_float4(0.f, 0.f, 0.f, 0.f);
            #pragma unroll 4
            for (int c4 = 0; c4 < 96; c4++) {
                float4 av = a4[c4];
                int cb = c4 * 4;
                float4 w0 = ((const float4*)(sW + (cb + 0) * 96))[lane];
                float4 w1v = ((const float4*)(sW + (cb + 1) * 96))[lane];
                float4 w2v = ((const float4*)(sW + (cb + 2) * 96))[lane];
                float4 w3v = ((const float4*)(sW + (cb + 3) * 96))[lane];
                acc.x += av.x * w0.x + av.y * w1v.x + av.z * w2v.x + av.w * w3v.x;
                acc.y += av.x * w0.y + av.y * w1v.y + av.z * w2v.y + av.w * w3v.y;
                acc.z += av.x * w0.z + av.y * w1v.z + av.z * w2v.z + av.w * w3v.z;
                acc.w += av.x * w0.w + av.y * w1v.w + av.z * w2v.w + av.w * w3v.w;
            }
            float4 bp = ((const float4*)sB)[lane];
            float4 xin = ((const float4*)(g_x2 + t * 96))[lane];
            float4 r;
            r.x = xin.x + acc.x + bp.x; r.y = xin.y + acc.y + bp.y;
            r.z = xin.z + acc.z + bp.z; r.w = xin.w + acc.w + bp.w;
            ((float4*)(g_x3 + t * 96))[lane] = r;
        }
        __syncwarp();
    }
}

// ---------------- K6: conv3d 3x3x3, 96 -> 3 ----------------
// block = 256 threads, 4 voxels/thread -> 1024 voxels/block, grid 150
__global__ void conv_kernel(const float* __restrict__ cw, const float* __restrict__ cbias,
                            float* __restrict__ out) {
    __shared__ __align__(16) float sWc[27 * 3 * 96];  // [k][o][c]
    __shared__ float sCB[3];
    int tid = threadIdx.x;
    for (int i = tid; i < 27 * 3 * 96; i += 256) {
        int k = i / 288, r = i % 288, o = r / 96, c = r % 96;
        sWc[i] = cw[((long)o * 96 + c) * 27 + k];
    }
    if (tid < 3) sCB[tid] = cbias[tid];
    __syncthreads();

    long base = (long)blockIdx.x * 1024;
    int bb[4], dd[4], hh2[4], ww2[4], ss[4];
    #pragma unroll
    for (int v = 0; v < 4; v++) {
        long t = base + tid + 256 * v;
        bb[v] = (int)(t / SPD);
        int s = (int)(t % SPD);
        ss[v] = s;
        dd[v] = s / (HH * WW_);
        hh2[v] = (s / WW_) % HH;
        ww2[v] = s % WW_;
    }
    float acc[4][3];
    #pragma unroll
    for (int v = 0; v < 4; v++) { acc[v][0] = acc[v][1] = acc[v][2] = 0.f; }

    for (int kd = -1; kd <= 1; kd++)
    for (int kh = -1; kh <= 1; kh++)
    for (int kw = -1; kw <= 1; kw++) {
        int k = (kd + 1) * 9 + (kh + 1) * 3 + (kw + 1);
        const float4* src[4];
        bool ok[4];
        #pragma unroll
        for (int v = 0; v < 4; v++) {
            int d2 = dd[v] + kd, h2 = hh2[v] + kh, w2 = ww2[v] + kw;
            ok[v] = ((unsigned)d2 < DD) && ((unsigned)h2 < HH) && ((unsigned)w2 < WW_);
            long nb = (long)bb[v] * SPD + ((long)d2 * HH + h2) * WW_ + w2;
            src[v] = (const float4*)(g_x3 + nb * 96);
        }
        const float* wk = sWc + k * 288;
        #pragma unroll 4
        for (int c4 = 0; c4 < 24; c4++) {
            float4 xv[4];
            #pragma unroll
            for (int v = 0; v < 4; v++)
                xv[v] = ok[v] ? src[v][c4] : make_float4(0.f, 0.f, 0.f, 0.f);
            #pragma unroll
            for (int o = 0; o < 3; o++) {
                float4 w4 = ((const float4*)(wk + o * 96))[c4];
                #pragma unroll
                for (int v = 0; v < 4; v++)
                    acc[v][o] += xv[v].x * w4.x + xv[v].y * w4.y +
                                 xv[v].z * w4.z + xv[v].w * w4.w;
            }
        }
    }
    #pragma unroll
    for (int v = 0; v < 4; v++)
        #pragma unroll
        for (int o = 0; o < 3; o++)
            out[((long)bb[v] * 3 + o) * SPD + ss[v]] = acc[v][o] + sCB[o];
}

// ---------------- launch ----------------
extern "C" void kernel_launch(void* const* d_in, const int* in_sizes, int n_in,
                              void* d_out, int out_size) {
    const float* I_m    = (const float*)d_in[0];
    const float* I_f    = (const float*)d_in[1];
    const float* ln1q_g = (const float*)d_in[2];
    const float* ln1q_b = (const float*)d_in[3];
    const float* ln1kv_g= (const float*)d_in[4];
    const float* ln1kv_b= (const float*)d_in[5];
    const float* wq     = (const float*)d_in[6];
    const float* bq     = (const float*)d_in[7];
    const float* wkv    = (const float*)d_in[8];
    const float* bkv    = (const float*)d_in[9];
    const float* wproj  = (const float*)d_in[10];
    const float* bproj  = (const float*)d_in[11];
    const float* relb   = (const float*)d_in[12];
    const float* ln2_g  = (const float*)d_in[13];
    const float* ln2_b  = (const float*)d_in[14];
    const float* w1     = (const float*)d_in[15];
    const float* b1     = (const float*)d_in[16];
    const float* w2     = (const float*)d_in[17];
    const float* b2     = (const float*)d_in[18];
    const float* cw     = (const float*)d_in[19];
    const float* cb     = (const float*)d_in[20];
    float* out = (float*)d_out;

    const int smem_q    = (96*33 + 96*96  + 96  + 8*4*96) * 4;   // 62208
    const int smem_kv   = (96*33 + 96*192 + 192 + 8*4*96) * 4;   // 99456
    const int smem_attn = (NT*96*2 + NT*NT) * 4;                 // 205200
    const int smem_m1   = (96*HID + HID + 16*96) * 4;            // 155136
    const int smem_m2   = (HID*96 + 96 + 16*HID) * 4;            // 172416

    cudaFuncSetAttribute(lnproj_kernel<96,  true >, cudaFuncAttributeMaxDynamicSharedMemorySize, smem_q);
    cudaFuncSetAttribute(lnproj_kernel<192, false>, cudaFuncAttributeMaxDynamicSharedMemorySize, smem_kv);
    cudaFuncSetAttribute(attn_kernel, cudaFuncAttributeMaxDynamicSharedMemorySize, smem_attn);
    cudaFuncSetAttribute(mlp1_kernel, cudaFuncAttributeMaxDynamicSharedMemorySize, smem_m1);
    cudaFuncSetAttribute(mlp2_kernel, cudaFuncAttributeMaxDynamicSharedMemorySize, smem_m2);

    bias_kernel<<<(NT*NT + 255) / 256, 256>>>(relb);
    lnproj_kernel<96,  true ><<<TOT / 32, 256, smem_q >>>(I_m, ln1q_g,  ln1q_b,  wq,  bq);
    lnproj_kernel<192, false><<<TOT / 32, 256, smem_kv>>>(I_f, ln1kv_g, ln1kv_b, wkv, bkv);
    attn_kernel<<<NWIN, 512, smem_attn>>>(wproj, bproj);
    mlp1_kernel<<<TOT / 64, 512, smem_m1>>>(ln2_g, ln2_b, w1, b1);
    mlp2_kernel<<<TOT / 64, 512, smem_m2>>>(w2, b2);
    conv_kernel<<<TOT / 1024, 256>>>(cw, cb, out);
}

// round 2
// speedup vs baseline: 2.0616x; 2.0616x over previous
#include <cuda_runtime.h>
#include <math.h>

#define CC 96
#define DD 40
#define HH 48
#define WW_ 40
#define BB 2
#define WIN_D 5
#define WIN_H 6
#define WIN_W 5
#define NT 150
#define NWD 8
#define NWH 8
#define NWW 8
#define NWIN 1024
#define SPD (DD*HH*WW_)   /* 76800 */
#define TOT (BB*SPD)      /* 153600 */
#define HID 384
#define PSTR 100          /* padded row stride (floats): 100 % 32 = 4 -> conflict-free */

// ---------------- scratch (device globals; no allocation) ----------------
__device__ __align__(128) float g_xt [TOT*CC];
__device__ __align__(128) float g_q  [NWIN*NT*CC];
__device__ __align__(128) float g_k  [NWIN*NT*CC];
__device__ __align__(128) float g_v  [NWIN*NT*CC];
__device__ __align__(128) float g_x2 [TOT*CC];
__device__ __align__(128) float g_x3 [TOT*CC];
__device__ __align__(128) float g_act[TOT*HID];
__device__ __align__(128) float g_bias[NT*NT];

__device__ __forceinline__ float warp_sum(float v) {
    #pragma unroll
    for (int o = 16; o > 0; o >>= 1) v += __shfl_xor_sync(0xffffffffu, v, o);
    return v;
}
__device__ __forceinline__ float warp_max(float v) {
    #pragma unroll
    for (int o = 16; o > 0; o >>= 1) v = fmaxf(v, __shfl_xor_sync(0xffffffffu, v, o));
    return v;
}
__device__ __forceinline__ float gelu_tanh(float x) {
    float x3 = x * x * x;
    return 0.5f * x * (1.0f + tanhf(0.79788456080286535588f * (x + 0.044715f * x3)));
}

// ---------------- K0: relative position bias table ----------------
__global__ void bias_kernel(const float* __restrict__ rel_bias) {
    int i = blockIdx.x * blockDim.x + threadIdx.x;
    if (i >= NT * NT) return;
    int n = i / NT, m = i % NT;
    int nd = n / 30, nh = (n / 5) % 6, nw = n % 5;
    int md = m / 30, mh = (m / 5) % 6, mw = m % 5;
    int idx = (nd - md + 4) * 99 + (nh - mh + 5) * 9 + (nw - mw + 4);
    g_bias[i] = rel_bias[idx];
}

// ---------------- K1/K2: transpose + LN + projection (window layout) ----------------
template<int COUT, bool ISQ>
__global__ void lnproj_kernel(const float* __restrict__ in,
                              const float* __restrict__ gamma,
                              const float* __restrict__ beta,
                              const float* __restrict__ wmat,
                              const float* __restrict__ bvec) {
    extern __shared__ float sm[];
    float* tile = sm;                 // 96*33
    float* sW   = tile + 96 * 33;     // 96*COUT
    float* sB   = sW + 96 * COUT;     // COUT
    float* sLN  = sB + COUT;          // 8*4*96

    int tid = threadIdx.x, warp = tid >> 5, lane = tid & 31;
    long t0 = (long)blockIdx.x * 32;
    int b  = (int)(t0 / SPD);
    int s0 = (int)(t0 % SPD);

    for (int i = tid; i < 96 * COUT; i += 256) sW[i] = wmat[i];
    for (int i = tid; i < COUT; i += 256)      sB[i] = bvec[i];
    const float* inb = in + (long)b * 96 * SPD + s0;
    for (int i = tid; i < 96 * 32; i += 256) {
        int c = i >> 5, j = i & 31;
        tile[c * 33 + j] = inb[(long)c * SPD + j];
    }
    __syncthreads();

    if (ISQ) {
        for (int i = tid; i < 96 * 32; i += 256) {
            int c = i % 96, j = i / 96;
            g_xt[(t0 + j) * 96 + c] = tile[c * 33 + j];
        }
    }

    float* myLN = sLN + warp * 4 * 96;
    #pragma unroll
    for (int tt = 0; tt < 4; tt++) {
        int j = warp * 4 + tt;
        float v0 = tile[lane * 33 + j];
        float v1 = tile[(lane + 32) * 33 + j];
        float v2 = tile[(lane + 64) * 33 + j];
        float mean = warp_sum(v0 + v1 + v2) * (1.0f / 96.0f);
        float var  = warp_sum(v0 * v0 + v1 * v1 + v2 * v2) * (1.0f / 96.0f) - mean * mean;
        float inv  = rsqrtf(var + 1e-5f);
        myLN[tt * 96 + lane]      = (v0 - mean) * inv * gamma[lane]      + beta[lane];
        myLN[tt * 96 + lane + 32] = (v1 - mean) * inv * gamma[lane + 32] + beta[lane + 32];
        myLN[tt * 96 + lane + 64] = (v2 - mean) * inv * gamma[lane + 64] + beta[lane + 64];
    }
    __syncwarp();

    long addr[4];
    #pragma unroll
    for (int tt = 0; tt < 4; tt++) {
        long t = t0 + warp * 4 + tt;
        int s = (int)(t % SPD);
        int d = s / (HH * WW_), h = (s / WW_) % HH, w = s % WW_;
        int wi = ((b * NWD + d / WIN_D) * NWH + h / WIN_H) * NWW + w / WIN_W;
        int n  = (d % WIN_D) * (WIN_H * WIN_W) + (h % WIN_H) * WIN_W + (w % WIN_W);
        addr[tt] = ((long)wi * NT + n) * 96;
    }

    const float4* L0 = (const float4*)(myLN);
    const float4* L1 = (const float4*)(myLN + 96);
    const float4* L2 = (const float4*)(myLN + 192);
    const float4* L3 = (const float4*)(myLN + 288);
    for (int jj = lane; jj < COUT; jj += 32) {
        float a0 = 0.f, a1 = 0.f, a2 = 0.f, a3 = 0.f;
        #pragma unroll 6
        for (int c4 = 0; c4 < 24; c4++) {
            float4 l0 = L0[c4], l1 = L1[c4], l2 = L2[c4], l3 = L3[c4];
            const float* wp = sW + c4 * 4 * COUT + jj;
            float w0 = wp[0], w1 = wp[COUT], w2 = wp[2 * COUT], w3 = wp[3 * COUT];
            a0 += l0.x * w0 + l0.y * w1 + l0.z * w2 + l0.w * w3;
            a1 += l1.x * w0 + l1.y * w1 + l1.z * w2 + l1.w * w3;
            a2 += l2.x * w0 + l2.y * w1 + l2.z * w2 + l2.w * w3;
            a3 += l3.x * w0 + l3.y * w1 + l3.z * w2 + l3.w * w3;
        }
        float bb = sB[jj];
        a0 += bb; a1 += bb; a2 += bb; a3 += bb;
        if (COUT == 96) {
            g_q[addr[0] + jj] = a0; g_q[addr[1] + jj] = a1;
            g_q[addr[2] + jj] = a2; g_q[addr[3] + jj] = a3;
        } else {
            float* dst = (jj < 96) ? g_k : g_v;
            int j2 = (jj < 96) ? jj : jj - 96;
            dst[addr[0] + j2] = a0; dst[addr[1] + j2] = a1;
            dst[addr[2] + j2] = a2; dst[addr[3] + j2] = a3;
        }
    }
}

// ---------------- K3: per-window attention + out-proj + residual ----------------
// block = 1024 threads (32 warps). dyn smem (padded rows, stride PSTR=100):
//   sQ[150*100] | sKV[150*100] | sS[150*150]  (wproj overlays sS in proj phase)
__global__ void __launch_bounds__(1024, 1)
attn_kernel(const float* __restrict__ wproj, const float* __restrict__ bproj) {
    extern __shared__ float sm[];
    float* sQ  = sm;
    float* sKV = sQ + NT * PSTR;
    float* sS  = sKV + NT * PSTR;
    int tid = threadIdx.x, warp = tid >> 5, lane = tid & 31;
    int wi = blockIdx.x;

    float4* sQ4  = (float4*)sQ;
    float4* sKV4 = (float4*)sKV;
    const float4* gq = (const float4*)(g_q + (long)wi * NT * 96);
    const float4* gk = (const float4*)(g_k + (long)wi * NT * 96);
    const float4* gv = (const float4*)(g_v + (long)wi * NT * 96);
    for (int i = tid; i < NT * 24; i += 1024) {
        int r = i / 24, c = i - r * 24;
        sQ4[r * 25 + c]  = gq[i];
        sKV4[r * 25 + c] = gk[i];
    }
    __syncthreads();

    const float scale = 0.102062072615965696f;  // 96^-0.5

    // ---- S = scale*Q.K^T + bias; softmax (2 rows / warp, conflict-free K reads) ----
    for (int n0 = warp * 2; n0 < NT; n0 += 64) {
        float acc0[5] = {0.f, 0.f, 0.f, 0.f, 0.f};
        float acc1[5] = {0.f, 0.f, 0.f, 0.f, 0.f};
        const float4* qa = (const float4*)(sQ + n0 * PSTR);
        const float4* qb = qa + 25;
        #pragma unroll 4
        for (int c4 = 0; c4 < 24; c4++) {
            float4 a4 = qa[c4], b4 = qb[c4];
            #pragma unroll
            for (int kk = 0; kk < 5; kk++) {
                int m = lane + 32 * kk;
                if (m < NT) {
                    float4 k4 = ((const float4*)(sKV + m * PSTR))[c4];
                    acc0[kk] += a4.x * k4.x + a4.y * k4.y + a4.z * k4.z + a4.w * k4.w;
                    acc1[kk] += b4.x * k4.x + b4.y * k4.y + b4.z * k4.z + b4.w * k4.w;
                }
            }
        }
        #pragma unroll
        for (int r = 0; r < 2; r++) {
            int n = n0 + r;
            float* acc = r ? acc1 : acc0;
            float sval[5];
            float mx = -1e30f;
            #pragma unroll
            for (int kk = 0; kk < 5; kk++) {
                int m = lane + 32 * kk;
                if (m < NT) {
                    sval[kk] = acc[kk] * scale + g_bias[n * NT + m];
                    mx = fmaxf(mx, sval[kk]);
                }
            }
            mx = warp_max(mx);
            float sum = 0.f;
            #pragma unroll
            for (int kk = 0; kk < 5; kk++) {
                int m = lane + 32 * kk;
                if (m < NT) { sval[kk] = __expf(sval[kk] - mx); sum += sval[kk]; }
            }
            sum = warp_sum(sum);
            float inv = 1.0f / sum;
            #pragma unroll
            for (int kk = 0; kk < 5; kk++) {
                int m = lane + 32 * kk;
                if (m < NT) sS[n * NT + m] = sval[kk] * inv;
            }
        }
    }
    __syncthreads();

    // V over K
    for (int i = tid; i < NT * 24; i += 1024) {
        int r = i / 24, c = i - r * 24;
        sKV4[r * 25 + c] = gv[i];
    }
    __syncthreads();

    // ---- O = P @ V into sQ (4 rows / warp: 4x reuse of v4) ----
    for (int n0 = warp * 4; n0 < NT; n0 += 128) {
        if (lane < 24) {
            float4 acc[4];
            #pragma unroll
            for (int r = 0; r < 4; r++) acc[r] = make_float4(0.f, 0.f, 0.f, 0.f);
            int nr[4];
            #pragma unroll
            for (int r = 0; r < 4; r++) nr[r] = (n0 + r < NT) ? (n0 + r) : (NT - 1);
            #pragma unroll 2
            for (int m = 0; m < NT; m++) {
                float4 v4 = ((const float4*)(sKV + m * PSTR))[lane];
                #pragma unroll
                for (int r = 0; r < 4; r++) {
                    float p = sS[nr[r] * NT + m];
                    acc[r].x += p * v4.x; acc[r].y += p * v4.y;
                    acc[r].z += p * v4.z; acc[r].w += p * v4.w;
                }
            }
            #pragma unroll
            for (int r = 0; r < 4; r++)
                if (n0 + r < NT) ((float4*)(sQ + (n0 + r) * PSTR))[lane] = acc[r];
        }
    }
    __syncthreads();

    // ---- out-proj + residual (2 rows / warp) ----
    float* sW  = sS;
    float* sBp = sS + 96 * 96;
    for (int i = tid; i < 96 * 96; i += 1024) sW[i] = wproj[i];
    if (tid < 96) sBp[tid] = bproj[tid];
    __syncthreads();

    int iww = wi & 7, iwh = (wi >> 3) & 7, iwd = (wi >> 6) & 7, b = wi >> 9;
    for (int n0 = warp * 2; n0 < NT; n0 += 64) {
        if (lane < 24) {
            float4 acc0 = make_float4(0.f, 0.f, 0.f, 0.f);
            float4 acc1 = make_float4(0.f, 0.f, 0.f, 0.f);
            const float4* oa = (const float4*)(sQ + n0 * PSTR);
            const float4* ob = oa + 25;
            #pragma unroll 4
            for (int c4 = 0; c4 < 24; c4++) {
                float4 a4 = oa[c4], b4v = ob[c4];
                int cb = c4 * 4;
                float4 w0 = ((const float4*)(sW + (cb + 0) * 96))[lane];
                float4 w1 = ((const float4*)(sW + (cb + 1) * 96))[lane];
                float4 w2 = ((const float4*)(sW + (cb + 2) * 96))[lane];
                float4 w3 = ((const float4*)(sW + (cb + 3) * 96))[lane];
                acc0.x += a4.x * w0.x + a4.y * w1.x + a4.z * w2.x + a4.w * w3.x;
                acc0.y += a4.x * w0.y + a4.y * w1.y + a4.z * w2.y + a4.w * w3.y;
                acc0.z += a4.x * w0.z + a4.y * w1.z + a4.z * w2.z + a4.w * w3.z;
                acc0.w += a4.x * w0.w + a4.y * w1.w + a4.z * w2.w + a4.w * w3.w;
                acc1.x += b4v.x * w0.x + b4v.y * w1.x + b4v.z * w2.x + b4v.w * w3.x;
                acc1.y += b4v.x * w0.y + b4v.y * w1.y + b4v.z * w2.y + b4v.w * w3.y;
                acc1.z += b4v.x * w0.z + b4v.y * w1.z + b4v.z * w2.z + b4v.w * w3.z;
                acc1.w += b4v.x * w0.w + b4v.y * w1.w + b4v.z * w2.w + b4v.w * w3.w;
            }
            float4 bp = ((const float4*)sBp)[lane];
            #pragma unroll
            for (int r = 0; r < 2; r++) {
                int n = n0 + r;
                float4 acc = r ? acc1 : acc0;
                int zd = n / 30, zh = (n / 5) % 6, zw = n % 5;
                int d = iwd * WIN_D + zd, h = iwh * WIN_H + zh, w = iww * WIN_W + zw;
                long t = (long)b * SPD + ((long)d * HH + h) * WW_ + w;
                float4 sc = ((const float4*)(g_xt + t * 96))[lane];
                float4 rres;
                rres.x = sc.x + acc.x + bp.x; rres.y = sc.y + acc.y + bp.y;
                rres.z = sc.z + acc.z + bp.z; rres.w = sc.w + acc.w + bp.w;
                ((float4*)(g_x2 + t * 96))[lane] = rres;
            }
        }
    }
}

// ---------------- K4: LN2 + fc1 + gelu (4 tokens / warp, 4x W reuse) ----------------
__global__ void __launch_bounds__(512)
mlp1_kernel(const float* __restrict__ g2, const float* __restrict__ b2,
            const float* __restrict__ w1, const float* __restrict__ b1) {
    extern __shared__ float sm[];
    float* sW = sm;                 // 96*384
    float* sB = sW + 96 * HID;      // 384
    float* sH = sB + HID;           // 16*4*96
    int tid = threadIdx.x, warp = tid >> 5, lane = tid & 31;
    for (int i = tid; i < 96 * HID; i += 512) sW[i] = w1[i];
    for (int i = tid; i < HID; i += 512)      sB[i] = b1[i];
    __syncthreads();

    long t0 = (long)blockIdx.x * 64 + warp * 4;
    float* h = sH + warp * 4 * 96;
    #pragma unroll
    for (int it = 0; it < 4; it++) {
        const float* xr = g_x2 + (t0 + it) * 96;
        float v0 = xr[lane], v1 = xr[lane + 32], v2 = xr[lane + 64];
        float mean = warp_sum(v0 + v1 + v2) * (1.0f / 96.0f);
        float var  = warp_sum(v0 * v0 + v1 * v1 + v2 * v2) * (1.0f / 96.0f) - mean * mean;
        float inv  = rsqrtf(var + 1e-5f);
        h[it * 96 + lane]      = (v0 - mean) * inv * g2[lane]      + b2[lane];
        h[it * 96 + lane + 32] = (v1 - mean) * inv * g2[lane + 32] + b2[lane + 32];
        h[it * 96 + lane + 64] = (v2 - mean) * inv * g2[lane + 64] + b2[lane + 64];
    }
    __syncwarp();

    for (int g = 0; g < 3; g++) {
        int j4 = lane + 32 * g;
        float4 acc[4];
        #pragma unroll
        for (int r = 0; r < 4; r++) acc[r] = make_float4(0.f, 0.f, 0.f, 0.f);
        #pragma unroll 4
        for (int c4 = 0; c4 < 24; c4++) {
            int cb = c4 * 4;
            float4 w0 = ((const float4*)(sW + (cb + 0) * HID))[j4];
            float4 w1v = ((const float4*)(sW + (cb + 1) * HID))[j4];
            float4 w2v = ((const float4*)(sW + (cb + 2) * HID))[j4];
            float4 w3v = ((const float4*)(sW + (cb + 3) * HID))[j4];
            #pragma unroll
            for (int r = 0; r < 4; r++) {
                float4 h4 = ((const float4*)(h + r * 96))[c4];
                acc[r].x += h4.x * w0.x + h4.y * w1v.x + h4.z * w2v.x + h4.w * w3v.x;
                acc[r].y += h4.x * w0.y + h4.y * w1v.y + h4.z * w2v.y + h4.w * w3v.y;
                acc[r].z += h4.x * w0.z + h4.y * w1v.z + h4.z * w2v.z + h4.w * w3v.z;
                acc[r].w += h4.x * w0.w + h4.y * w1v.w + h4.z * w2v.w + h4.w * w3v.w;
            }
        }
        float4 bb = ((const float4*)sB)[j4];
        #pragma unroll
        for (int r = 0; r < 4; r++) {
            float4 o;
            o.x = gelu_tanh(acc[r].x + bb.x);
            o.y = gelu_tanh(acc[r].y + bb.y);
            o.z = gelu_tanh(acc[r].z + bb.z);
            o.w = gelu_tanh(acc[r].w + bb.w);
            ((float4*)(g_act + (t0 + r) * HID))[j4] = o;
        }
    }
}

// ---------------- K5: fc2 + residual (4 tokens / warp, c-dim split in 2 halves) ----------------
__global__ void __launch_bounds__(512)
mlp2_kernel(const float* __restrict__ w2, const float* __restrict__ b2) {
    extern __shared__ float sm[];
    float* sW = sm;                  // 384*96
    float* sB = sW + HID * 96;       // 96
    float* sA = sB + 96;             // 16*4*192
    int tid = threadIdx.x, warp = tid >> 5, lane = tid & 31;
    for (int i = tid; i < HID * 96; i += 512) sW[i] = w2[i];
    if (tid < 96) sB[tid] = b2[tid];
    __syncthreads();

    long t0 = (long)blockIdx.x * 64 + warp * 4;
    float* aw = sA + warp * 4 * 192;
    float4 acc[4];
    #pragma unroll
    for (int r = 0; r < 4; r++) acc[r] = make_float4(0.f, 0.f, 0.f, 0.f);

    for (int half = 0; half < 2; half++) {
        __syncwarp();
        #pragma unroll
        for (int r = 0; r < 4; r++) {
            const float4* src = (const float4*)(g_act + (t0 + r) * HID + half * 192);
            float4* dst = (float4*)(aw + r * 192);
            for (int i = lane; i < 48; i += 32) dst[i] = src[i];
        }
        __syncwarp();
        if (lane < 24) {
            #pragma unroll 4
            for (int c4 = 0; c4 < 48; c4++) {
                int ch = half * 192 + c4 * 4;
                float4 w0 = ((const float4*)(sW + (ch + 0) * 96))[lane];
                float4 w1v = ((const float4*)(sW + (ch + 1) * 96))[lane];
                float4 w2v = ((const float4*)(sW + (ch + 2) * 96))[lane];
                float4 w3v = ((const float4*)(sW + (ch + 3) * 96))[lane];
                #pragma unroll
                for (int r = 0; r < 4; r++) {
                    float4 a4 = ((const float4*)(aw + r * 192))[c4];
                    acc[r].x += a4.x * w0.x + a4.y * w1v.x + a4.z * w2v.x + a4.w * w3v.x;
                    acc[r].y += a4.x * w0.y + a4.y * w1v.y + a4.z * w2v.y + a4.w * w3v.y;
                    acc[r].z += a4.x * w0.z + a4.y * w1v.z + a4.z * w2v.z + a4.w * w3v.z;
                    acc[r].w += a4.x * w0.w + a4.y * w1v.w + a4.z * w2v.w + a4.w * w3v.w;
                }
            }
        }
    }
    if (lane < 24) {
        float4 bb = ((const float4*)sB)[lane];
        #pragma unroll
        for (int r = 0; r < 4; r++) {
            float4 xin = ((const float4*)(g_x2 + (t0 + r) * 96))[lane];
            float4 o;
            o.x = xin.x + acc[r].x + bb.x; o.y = xin.y + acc[r].y + bb.y;
            o.z = xin.z + acc[r].z + bb.z; o.w = xin.w + acc[r].w + bb.w;
            ((float4*)(g_x3 + (t0 + r) * 96))[lane] = o;
        }
    }
}

// ---------------- K6: conv3d 3x3x3, 96 -> 3 ----------------
__global__ void conv_kernel(const float* __restrict__ cw, const float* __restrict__ cbias,
                            float* __restrict__ out) {
    __shared__ __align__(16) float sWc[27 * 3 * 96];
    __shared__ float sCB[3];
    int tid = threadIdx.x;
    for (int i = tid; i < 27 * 3 * 96; i += 256) {
        int k = i / 288, r = i % 288, o = r / 96, c = r % 96;
        sWc[i] = cw[((long)o * 96 + c) * 27 + k];
    }
    if (tid < 3) sCB[tid] = cbias[tid];
    __syncthreads();

    long base = (long)blockIdx.x * 1024;
    int bb[4], dd[4], hh2[4], ww2[4], ss[4];
    #pragma unroll
    for (int v = 0; v < 4; v++) {
        long t = base + tid + 256 * v;
        bb[v] = (int)(t / SPD);
        int s = (int)(t % SPD);
        ss[v] = s;
        dd[v] = s / (HH * WW_);
        hh2[v] = (s / WW_) % HH;
        ww2[v] = s % WW_;
    }
    float acc[4][3];
    #pragma unroll
    for (int v = 0; v < 4; v++) { acc[v][0] = acc[v][1] = acc[v][2] = 0.f; }

    for (int kd = -1; kd <= 1; kd++)
    for (int kh = -1; kh <= 1; kh++)
    for (int kw = -1; kw <= 1; kw++) {
        int k = (kd + 1) * 9 + (kh + 1) * 3 + (kw + 1);
        const float4* src[4];
        bool ok[4];
        #pragma unroll
        for (int v = 0; v < 4; v++) {
            int d2 = dd[v] + kd, h2 = hh2[v] + kh, w2 = ww2[v] + kw;
            ok[v] = ((unsigned)d2 < DD) && ((unsigned)h2 < HH) && ((unsigned)w2 < WW_);
            long nb = (long)bb[v] * SPD + ((long)d2 * HH + h2) * WW_ + w2;
            src[v] = (const float4*)(g_x3 + nb * 96);
        }
        const float* wk = sWc + k * 288;
        #pragma unroll 4
        for (int c4 = 0; c4 < 24; c4++) {
            float4 xv[4];
            #pragma unroll
            for (int v = 0; v < 4; v++)
                xv[v] = ok[v] ? src[v][c4] : make_float4(0.f, 0.f, 0.f, 0.f);
            #pragma unroll
            for (int o = 0; o < 3; o++) {
                float4 w4 = ((const float4*)(wk + o * 96))[c4];
                #pragma unroll
                for (int v = 0; v < 4; v++)
                    acc[v][o] += xv[v].x * w4.x + xv[v].y * w4.y +
                                 xv[v].z * w4.z + xv[v].w * w4.w;
            }
        }
    }
    #pragma unroll
    for (int v = 0; v < 4; v++)
        #pragma unroll
        for (int o = 0; o < 3; o++)
            out[((long)bb[v] * 3 + o) * SPD + ss[v]] = acc[v][o] + sCB[o];
}

// ---------------- launch ----------------
extern "C" void kernel_launch(void* const* d_in, const int* in_sizes, int n_in,
                              void* d_out, int out_size) {
    const float* I_m    = (const float*)d_in[0];
    const float* I_f    = (const float*)d_in[1];
    const float* ln1q_g = (const float*)d_in[2];
    const float* ln1q_b = (const float*)d_in[3];
    const float* ln1kv_g= (const float*)d_in[4];
    const float* ln1kv_b= (const float*)d_in[5];
    const float* wq     = (const float*)d_in[6];
    const float* bq     = (const float*)d_in[7];
    const float* wkv    = (const float*)d_in[8];
    const float* bkv    = (const float*)d_in[9];
    const float* wproj  = (const float*)d_in[10];
    const float* bproj  = (const float*)d_in[11];
    const float* relb   = (const float*)d_in[12];
    const float* ln2_g  = (const float*)d_in[13];
    const float* ln2_b  = (const float*)d_in[14];
    const float* w1     = (const float*)d_in[15];
    const float* b1     = (const float*)d_in[16];
    const float* w2     = (const float*)d_in[17];
    const float* b2     = (const float*)d_in[18];
    const float* cw     = (const float*)d_in[19];
    const float* cb     = (const float*)d_in[20];
    float* out = (float*)d_out;

    const int smem_q    = (96*33 + 96*96  + 96  + 8*4*96) * 4;        // 62208
    const int smem_kv   = (96*33 + 96*192 + 192 + 8*4*96) * 4;        // 99456
    const int smem_attn = (NT*PSTR*2 + NT*NT) * 4;                    // 210000
    const int smem_m1   = (96*HID + HID + 16*4*96) * 4;               // 173568
    const int smem_m2   = (HID*96 + 96 + 16*4*192) * 4;               // 196992

    cudaFuncSetAttribute(lnproj_kernel<96,  true >, cudaFuncAttributeMaxDynamicSharedMemorySize, smem_q);
    cudaFuncSetAttribute(lnproj_kernel<192, false>, cudaFuncAttributeMaxDynamicSharedMemorySize, smem_kv);
    cudaFuncSetAttribute(attn_kernel, cudaFuncAttributeMaxDynamicSharedMemorySize, smem_attn);
    cudaFuncSetAttribute(mlp1_kernel, cudaFuncAttributeMaxDynamicSharedMemorySize, smem_m1);
    cudaFuncSetAttribute(mlp2_kernel, cudaFuncAttributeMaxDynamicSharedMemorySize, smem_m2);

    bias_kernel<<<(NT*NT + 255) / 256, 256>>>(relb);
    lnproj_kernel<96,  true ><<<TOT / 32, 256, smem_q >>>(I_m, ln1q_g,  ln1q_b,  wq,  bq);
    lnproj_kernel<192, false><<<TOT / 32, 256, smem_kv>>>(I_f, ln1kv_g, ln1kv_b, wkv, bkv);
    attn_kernel<<<NWIN, 1024, smem_attn>>>(wproj, bproj);
    mlp1_kernel<<<TOT / 64, 512, smem_m1>>>(ln2_g, ln2_b, w1, b1);
    mlp2_kernel<<<TOT / 64, 512, smem_m2>>>(w2, b2);
    conv_kernel<<<TOT / 1024, 256>>>(cw, cb, out);
}

// round 5
// speedup vs baseline: 2.6957x; 1.3076x over previous
#include <cuda_runtime.h>
#include <cuda_bf16.h>
#include <math.h>
#include <stdint.h>

#define CC 96
#define DD 40
#define HH 48
#define WW_ 40
#define BB 2
#define WIN_D 5
#define WIN_H 6
#define WIN_W 5
#define NT 150
#define NWD 8
#define NWH 8
#define NWW 8
#define NWIN 1024
#define SPD (DD*HH*WW_)   /* 76800 */
#define TOT (BB*SPD)      /* 153600 */
#define HID 384
#define PSTR 100

// ---------------- scratch (device globals; no allocation) ----------------
__device__ __align__(128) float g_xt [TOT*CC];
__device__ __align__(128) float g_q  [NWIN*NT*CC];
__device__ __align__(128) float g_k  [NWIN*NT*CC];
__device__ __align__(128) float g_v  [NWIN*NT*CC];
__device__ __align__(128) float g_x2 [TOT*CC];
__device__ __align__(128) float g_x3 [TOT*CC];
__device__ __align__(128) float g_bias[NT*NT];

__device__ __forceinline__ float warp_sum(float v) {
    #pragma unroll
    for (int o = 16; o > 0; o >>= 1) v += __shfl_xor_sync(0xffffffffu, v, o);
    return v;
}
__device__ __forceinline__ float warp_max(float v) {
    #pragma unroll
    for (int o = 16; o > 0; o >>= 1) v = fmaxf(v, __shfl_xor_sync(0xffffffffu, v, o));
    return v;
}
__device__ __forceinline__ float gelu_fast(float x) {
    float z = 0.79788456080286535588f * (x + 0.044715f * x * x * x);
    float t = __expf(2.0f * z);
    return x * t / (t + 1.0f);   // x * (1+tanh(z))/2
}
// pack two fp32 -> bf16x2 (lo = first elem, as mma fragments require)
__device__ __forceinline__ uint32_t pack_bf16(float lo, float hi) {
    uint32_t r;
    asm("cvt.rn.bf16x2.f32 %0, %1, %2;" : "=r"(r) : "f"(hi), "f"(lo));
    return r;
}
__device__ __forceinline__ void mma16816(float c[4],
                                         uint32_t a0, uint32_t a1, uint32_t a2, uint32_t a3,
                                         uint32_t b0, uint32_t b1) {
    asm volatile(
        "mma.sync.aligned.m16n8k16.row.col.f32.bf16.bf16.f32 "
        "{%0,%1,%2,%3}, {%4,%5,%6,%7}, {%8,%9}, {%0,%1,%2,%3};"
        : "+f"(c[0]), "+f"(c[1]), "+f"(c[2]), "+f"(c[3])
        : "r"(a0), "r"(a1), "r"(a2), "r"(a3), "r"(b0), "r"(b1));
}

// ---------------- K0: relative position bias table ----------------
__global__ void bias_kernel(const float* __restrict__ rel_bias) {
    int i = blockIdx.x * blockDim.x + threadIdx.x;
    if (i >= NT * NT) return;
    int n = i / NT, m = i % NT;
    int nd = n / 30, nh = (n / 5) % 6, nw = n % 5;
    int md = m / 30, mh = (m / 5) % 6, mw = m % 5;
    int idx = (nd - md + 4) * 99 + (nh - mh + 5) * 9 + (nw - mw + 4);
    g_bias[i] = rel_bias[idx];
}

// ---------------- K1/K2: transpose + LN + projection (window layout) ----------------
template<int COUT, bool ISQ>
__global__ void lnproj_kernel(const float* __restrict__ in,
                              const float* __restrict__ gamma,
                              const float* __restrict__ beta,
                              const float* __restrict__ wmat,
                              const float* __restrict__ bvec) {
    extern __shared__ float sm[];
    float* tile = sm;
    float* sW   = tile + 96 * 33;
    float* sB   = sW + 96 * COUT;
    float* sLN  = sB + COUT;

    int tid = threadIdx.x, warp = tid >> 5, lane = tid & 31;
    long t0 = (long)blockIdx.x * 32;
    int b  = (int)(t0 / SPD);
    int s0 = (int)(t0 % SPD);

    for (int i = tid; i < 96 * COUT; i += 256) sW[i] = wmat[i];
    for (int i = tid; i < COUT; i += 256)      sB[i] = bvec[i];
    const float* inb = in + (long)b * 96 * SPD + s0;
    for (int i = tid; i < 96 * 32; i += 256) {
        int c = i >> 5, j = i & 31;
        tile[c * 33 + j] = inb[(long)c * SPD + j];
    }
    __syncthreads();

    if (ISQ) {
        for (int i = tid; i < 96 * 32; i += 256) {
            int c = i % 96, j = i / 96;
            g_xt[(t0 + j) * 96 + c] = tile[c * 33 + j];
        }
    }

    float* myLN = sLN + warp * 4 * 96;
    #pragma unroll
    for (int tt = 0; tt < 4; tt++) {
        int j = warp * 4 + tt;
        float v0 = tile[lane * 33 + j];
        float v1 = tile[(lane + 32) * 33 + j];
        float v2 = tile[(lane + 64) * 33 + j];
        float mean = warp_sum(v0 + v1 + v2) * (1.0f / 96.0f);
        float var  = warp_sum(v0 * v0 + v1 * v1 + v2 * v2) * (1.0f / 96.0f) - mean * mean;
        float inv  = rsqrtf(var + 1e-5f);
        myLN[tt * 96 + lane]      = (v0 - mean) * inv * gamma[lane]      + beta[lane];
        myLN[tt * 96 + lane + 32] = (v1 - mean) * inv * gamma[lane + 32] + beta[lane + 32];
        myLN[tt * 96 + lane + 64] = (v2 - mean) * inv * gamma[lane + 64] + beta[lane + 64];
    }
    __syncwarp();

    long addr[4];
    #pragma unroll
    for (int tt = 0; tt < 4; tt++) {
        long t = t0 + warp * 4 + tt;
        int s = (int)(t % SPD);
        int d = s / (HH * WW_), h = (s / WW_) % HH, w = s % WW_;
        int wi = ((b * NWD + d / WIN_D) * NWH + h / WIN_H) * NWW + w / WIN_W;
        int n  = (d % WIN_D) * (WIN_H * WIN_W) + (h % WIN_H) * WIN_W + (w % WIN_W);
        addr[tt] = ((long)wi * NT + n) * 96;
    }

    const float4* L0 = (const float4*)(myLN);
    const float4* L1 = (const float4*)(myLN + 96);
    const float4* L2 = (const float4*)(myLN + 192);
    const float4* L3 = (const float4*)(myLN + 288);
    for (int jj = lane; jj < COUT; jj += 32) {
        float a0 = 0.f, a1 = 0.f, a2 = 0.f, a3 = 0.f;
        #pragma unroll 6
        for (int c4 = 0; c4 < 24; c4++) {
            float4 l0 = L0[c4], l1 = L1[c4], l2 = L2[c4], l3 = L3[c4];
            const float* wp = sW + c4 * 4 * COUT + jj;
            float w0 = wp[0], w1 = wp[COUT], w2 = wp[2 * COUT], w3 = wp[3 * COUT];
            a0 += l0.x * w0 + l0.y * w1 + l0.z * w2 + l0.w * w3;
            a1 += l1.x * w0 + l1.y * w1 + l1.z * w2 + l1.w * w3;
            a2 += l2.x * w0 + l2.y * w1 + l2.z * w2 + l2.w * w3;
            a3 += l3.x * w0 + l3.y * w1 + l3.z * w2 + l3.w * w3;
        }
        float bb = sB[jj];
        a0 += bb; a1 += bb; a2 += bb; a3 += bb;
        if (COUT == 96) {
            g_q[addr[0] + jj] = a0; g_q[addr[1] + jj] = a1;
            g_q[addr[2] + jj] = a2; g_q[addr[3] + jj] = a3;
        } else {
            float* dst = (jj < 96) ? g_k : g_v;
            int j2 = (jj < 96) ? jj : jj - 96;
            dst[addr[0] + j2] = a0; dst[addr[1] + j2] = a1;
            dst[addr[2] + j2] = a2; dst[addr[3] + j2] = a3;
        }
    }
}

// ---------------- K3: per-window attention + out-proj + residual ----------------
__global__ void __launch_bounds__(1024, 1)
attn_kernel(const float* __restrict__ wproj, const float* __restrict__ bproj) {
    extern __shared__ float sm[];
    float* sQ  = sm;
    float* sKV = sQ + NT * PSTR;
    float* sS  = sKV + NT * PSTR;
    int tid = threadIdx.x, warp = tid >> 5, lane = tid & 31;
    int wi = blockIdx.x;

    float4* sQ4  = (float4*)sQ;
    float4* sKV4 = (float4*)sKV;
    const float4* gq = (const float4*)(g_q + (long)wi * NT * 96);
    const float4* gk = (const float4*)(g_k + (long)wi * NT * 96);
    const float4* gv = (const float4*)(g_v + (long)wi * NT * 96);
    for (int i = tid; i < NT * 24; i += 1024) {
        int r = i / 24, c = i - r * 24;
        sQ4[r * 25 + c]  = gq[i];
        sKV4[r * 25 + c] = gk[i];
    }
    __syncthreads();

    const float scale = 0.102062072615965696f;

    for (int n0 = warp * 2; n0 < NT; n0 += 64) {
        float acc0[5] = {0.f, 0.f, 0.f, 0.f, 0.f};
        float acc1[5] = {0.f, 0.f, 0.f, 0.f, 0.f};
        const float4* qa = (const float4*)(sQ + n0 * PSTR);
        const float4* qb = qa + 25;
        #pragma unroll 4
        for (int c4 = 0; c4 < 24; c4++) {
            float4 a4 = qa[c4], b4 = qb[c4];
            #pragma unroll
            for (int kk = 0; kk < 5; kk++) {
                int m = lane + 32 * kk;
                if (m < NT) {
                    float4 k4 = ((const float4*)(sKV + m * PSTR))[c4];
                    acc0[kk] += a4.x * k4.x + a4.y * k4.y + a4.z * k4.z + a4.w * k4.w;
                    acc1[kk] += b4.x * k4.x + b4.y * k4.y + b4.z * k4.z + b4.w * k4.w;
                }
            }
        }
        #pragma unroll
        for (int r = 0; r < 2; r++) {
            int n = n0 + r;
            float* acc = r ? acc1 : acc0;
            float sval[5];
            float mx = -1e30f;
            #pragma unroll
            for (int kk = 0; kk < 5; kk++) {
                int m = lane + 32 * kk;
                if (m < NT) {
                    sval[kk] = acc[kk] * scale + g_bias[n * NT + m];
                    mx = fmaxf(mx, sval[kk]);
                }
            }
            mx = warp_max(mx);
            float sum = 0.f;
            #pragma unroll
            for (int kk = 0; kk < 5; kk++) {
                int m = lane + 32 * kk;
                if (m < NT) { sval[kk] = __expf(sval[kk] - mx); sum += sval[kk]; }
            }
            sum = warp_sum(sum);
            float inv = 1.0f / sum;
            #pragma unroll
            for (int kk = 0; kk < 5; kk++) {
                int m = lane + 32 * kk;
                if (m < NT) sS[n * NT + m] = sval[kk] * inv;
            }
        }
    }
    __syncthreads();

    for (int i = tid; i < NT * 24; i += 1024) {
        int r = i / 24, c = i - r * 24;
        sKV4[r * 25 + c] = gv[i];
    }
    __syncthreads();

    for (int n0 = warp * 4; n0 < NT; n0 += 128) {
        if (lane < 24) {
            float4 acc[4];
            #pragma unroll
            for (int r = 0; r < 4; r++) acc[r] = make_float4(0.f, 0.f, 0.f, 0.f);
            int nr[4];
            #pragma unroll
            for (int r = 0; r < 4; r++) nr[r] = (n0 + r < NT) ? (n0 + r) : (NT - 1);
            #pragma unroll 2
            for (int m = 0; m < NT; m++) {
                float4 v4 = ((const float4*)(sKV + m * PSTR))[lane];
                #pragma unroll
                for (int r = 0; r < 4; r++) {
                    float p = sS[nr[r] * NT + m];
                    acc[r].x += p * v4.x; acc[r].y += p * v4.y;
                    acc[r].z += p * v4.z; acc[r].w += p * v4.w;
                }
            }
            #pragma unroll
            for (int r = 0; r < 4; r++)
                if (n0 + r < NT) ((float4*)(sQ + (n0 + r) * PSTR))[lane] = acc[r];
        }
    }
    __syncthreads();

    float* sW  = sS;
    float* sBp = sS + 96 * 96;
    for (int i = tid; i < 96 * 96; i += 1024) sW[i] = wproj[i];
    if (tid < 96) sBp[tid] = bproj[tid];
    __syncthreads();

    int iww = wi & 7, iwh = (wi >> 3) & 7, iwd = (wi >> 6) & 7, b = wi >> 9;
    for (int n0 = warp * 2; n0 < NT; n0 += 64) {
        if (lane < 24) {
            float4 acc0 = make_float4(0.f, 0.f, 0.f, 0.f);
            float4 acc1 = make_float4(0.f, 0.f, 0.f, 0.f);
            const float4* oa = (const float4*)(sQ + n0 * PSTR);
            const float4* ob = oa + 25;
            #pragma unroll 4
            for (int c4 = 0; c4 < 24; c4++) {
                float4 a4 = oa[c4], b4v = ob[c4];
                int cb = c4 * 4;
                float4 w0 = ((const float4*)(sW + (cb + 0) * 96))[lane];
                float4 w1 = ((const float4*)(sW + (cb + 1) * 96))[lane];
                float4 w2 = ((const float4*)(sW + (cb + 2) * 96))[lane];
                float4 w3 = ((const float4*)(sW + (cb + 3) * 96))[lane];
                acc0.x += a4.x * w0.x + a4.y * w1.x + a4.z * w2.x + a4.w * w3.x;
                acc0.y += a4.x * w0.y + a4.y * w1.y + a4.z * w2.y + a4.w * w3.y;
                acc0.z += a4.x * w0.z + a4.y * w1.z + a4.z * w2.z + a4.w * w3.z;
                acc0.w += a4.x * w0.w + a4.y * w1.w + a4.z * w2.w + a4.w * w3.w;
                acc1.x += b4v.x * w0.x + b4v.y * w1.x + b4v.z * w2.x + b4v.w * w3.x;
                acc1.y += b4v.x * w0.y + b4v.y * w1.y + b4v.z * w2.y + b4v.w * w3.y;
                acc1.z += b4v.x * w0.z + b4v.y * w1.z + b4v.z * w2.z + b4v.w * w3.z;
                acc1.w += b4v.x * w0.w + b4v.y * w1.w + b4v.z * w2.w + b4v.w * w3.w;
            }
            float4 bp = ((const float4*)sBp)[lane];
            #pragma unroll
            for (int r = 0; r < 2; r++) {
                int n = n0 + r;
                float4 acc = r ? acc1 : acc0;
                int zd = n / 30, zh = (n / 5) % 6, zw = n % 5;
                int d = iwd * WIN_D + zd, h = iwh * WIN_H + zh, w = iww * WIN_W + zw;
                long t = (long)b * SPD + ((long)d * HH + h) * WW_ + w;
                float4 sc = ((const float4*)(g_xt + t * 96))[lane];
                float4 rres;
                rres.x = sc.x + acc.x + bp.x; rres.y = sc.y + acc.y + bp.y;
                rres.z = sc.z + acc.z + bp.z; rres.w = sc.w + acc.w + bp.w;
                ((float4*)(g_x2 + t * 96))[lane] = rres;
            }
        }
    }
}

// ---------------- K4: fused LN2 + MLP via mma.sync (bf16 HMMA, fp32 accum) ----------------
// 128 tokens/CTA, 256 threads (8 warps), warp w owns rows [16w,16w+16).
// smem: sA bf16[128][104] | sT1 f32[96][132] | sT2 f32[128][100] | biases
#define ASTR 104
#define T1S  132
#define T2S  100
#define MA_OFF   0
#define MT1_OFF  26624
#define MT2_OFF  77312
#define MB1F_OFF 128512
#define MB2F_OFF 130048
#define MLG_OFF  130432
#define MLB_OFF  130816
#define MLP_SMEM 131200

__global__ void __launch_bounds__(256, 1)
mlp_mma_kernel(const float* __restrict__ g2, const float* __restrict__ b2ln,
               const float* __restrict__ w1, const float* __restrict__ b1,
               const float* __restrict__ w2, const float* __restrict__ b2) {
    extern __shared__ __align__(16) char smem[];
    __nv_bfloat16* sA = (__nv_bfloat16*)(smem + MA_OFF);
    float* sT1  = (float*)(smem + MT1_OFF);
    float* sT2  = (float*)(smem + MT2_OFF);
    float* sb1f = (float*)(smem + MB1F_OFF);
    float* sb2f = (float*)(smem + MB2F_OFF);
    float* slg  = (float*)(smem + MLG_OFF);
    float* slb  = (float*)(smem + MLB_OFF);

    int tid = threadIdx.x, wid = tid >> 5, lane = tid & 31;
    int g = lane >> 2, tig = lane & 3;
    long t0 = (long)blockIdx.x * 128;
    int r0 = wid * 16;

    for (int i = tid; i < HID; i += 256) sb1f[i] = b1[i];
    if (tid < 96) { sb2f[tid] = b2[tid]; slg[tid] = g2[tid]; slb[tid] = b2ln[tid]; }
    __syncthreads();

    // LN -> sA (bf16, row stride 104)
    #pragma unroll 1
    for (int it = 0; it < 16; it++) {
        int r = r0 + it;
        const float* xr = g_x2 + (t0 + r) * 96;
        float v0 = xr[lane], v1 = xr[lane + 32], v2 = xr[lane + 64];
        float mean = warp_sum(v0 + v1 + v2) * (1.0f / 96.0f);
        float var  = warp_sum(v0 * v0 + v1 * v1 + v2 * v2) * (1.0f / 96.0f) - mean * mean;
        float inv  = rsqrtf(var + 1e-5f);
        sA[r * ASTR + lane]      = __float2bfloat16_rn((v0 - mean) * inv * slg[lane]      + slb[lane]);
        sA[r * ASTR + lane + 32] = __float2bfloat16_rn((v1 - mean) * inv * slg[lane + 32] + slb[lane + 32]);
        sA[r * ASTR + lane + 64] = __float2bfloat16_rn((v2 - mean) * inv * slg[lane + 64] + slb[lane + 64]);
    }

    float c2[12][4];
    #pragma unroll
    for (int nt = 0; nt < 12; nt++)
        #pragma unroll
        for (int e = 0; e < 4; e++) c2[nt][e] = 0.f;

    uint32_t h[16][2];

    for (int j = 0; j < 3; j++) {
        __syncthreads();   // prior chunk reads done (and LN/A visible on j=0)
        // stage W1 chunk: sT1[k][n] = w1[k*HID + j*128 + n]  (96 x 128, f32, coalesced)
        for (int i = tid; i < 96 * 32; i += 256) {
            int k = i >> 5, n4 = (i & 31) << 2;
            float4 v = *(const float4*)(w1 + (long)k * HID + j * 128 + n4);
            *(float4*)(sT1 + k * T1S + n4) = v;
        }
        // stage W2 chunk: sT2[k][n] = w2[(j*128+k)*96 + n]   (128 x 96, f32)
        for (int i = tid; i < 128 * 24; i += 256) {
            int k = i / 24, n4 = (i % 24) << 2;
            float4 v = *(const float4*)(w2 + (long)(j * 128 + k) * 96 + n4);
            *(float4*)(sT2 + k * T2S + n4) = v;
        }
        __syncthreads();

        // GEMM1: C1(16x128) = A(16x96) @ W1c(96x128), split in two 64-col halves
        #pragma unroll
        for (int half = 0; half < 2; half++) {
            float c1[8][4];
            #pragma unroll
            for (int nt = 0; nt < 8; nt++)
                #pragma unroll
                for (int e = 0; e < 4; e++) c1[nt][e] = 0.f;
            #pragma unroll
            for (int kk = 0; kk < 6; kk++) {
                int kb = kk * 16 + tig * 2;
                uint32_t a0 = *(const uint32_t*)(sA + (r0 + g) * ASTR + kb);
                uint32_t a1 = *(const uint32_t*)(sA + (r0 + g + 8) * ASTR + kb);
                uint32_t a2 = *(const uint32_t*)(sA + (r0 + g) * ASTR + kb + 8);
                uint32_t a3 = *(const uint32_t*)(sA + (r0 + g + 8) * ASTR + kb + 8);
                #pragma unroll
                for (int nt = 0; nt < 8; nt++) {
                    int n = (half * 8 + nt) * 8 + g;
                    uint32_t b0 = pack_bf16(sT1[kb * T1S + n],       sT1[(kb + 1) * T1S + n]);
                    uint32_t b1v = pack_bf16(sT1[(kb + 8) * T1S + n], sT1[(kb + 9) * T1S + n]);
                    mma16816(c1[nt], a0, a1, a2, a3, b0, b1v);
                }
            }
            // gelu + bias -> bf16 H fragments (kept in registers; C1-frag == A-frag layout)
            #pragma unroll
            for (int nt = 0; nt < 8; nt++) {
                int nn = (half * 8 + nt) * 8 + tig * 2;
                float bb0 = sb1f[j * 128 + nn], bb1 = sb1f[j * 128 + nn + 1];
                h[half * 8 + nt][0] = pack_bf16(gelu_fast(c1[nt][0] + bb0), gelu_fast(c1[nt][1] + bb1));
                h[half * 8 + nt][1] = pack_bf16(gelu_fast(c1[nt][2] + bb0), gelu_fast(c1[nt][3] + bb1));
            }
        }

        // GEMM2: C2(16x96) += H(16x128) @ W2c(128x96)
        #pragma unroll
        for (int kk = 0; kk < 8; kk++) {
            uint32_t a0 = h[2 * kk][0], a1 = h[2 * kk][1];
            uint32_t a2 = h[2 * kk + 1][0], a3 = h[2 * kk + 1][1];
            int kb = kk * 16 + tig * 2;
            #pragma unroll
            for (int nt = 0; nt < 12; nt++) {
                int n = nt * 8 + g;
                uint32_t b0 = pack_bf16(sT2[kb * T2S + n],       sT2[(kb + 1) * T2S + n]);
                uint32_t b1v = pack_bf16(sT2[(kb + 8) * T2S + n], sT2[(kb + 9) * T2S + n]);
                mma16816(c2[nt], a0, a1, a2, a3, b0, b1v);
            }
        }
    }

    // epilogue: x3 = x2 + C2 + b2
    #pragma unroll
    for (int nt = 0; nt < 12; nt++) {
        int n = nt * 8 + tig * 2;
        long ra = t0 + r0 + g;
        float bb0 = sb2f[n], bb1 = sb2f[n + 1];
        float2 x0 = *(const float2*)(g_x2 + ra * 96 + n);
        float2 x1 = *(const float2*)(g_x2 + (ra + 8) * 96 + n);
        float2 o0 = make_float2(x0.x + c2[nt][0] + bb0, x0.y + c2[nt][1] + bb1);
        float2 o1 = make_float2(x1.x + c2[nt][2] + bb0, x1.y + c2[nt][3] + bb1);
        *(float2*)(g_x3 + ra * 96 + n) = o0;
        *(float2*)(g_x3 + (ra + 8) * 96 + n) = o1;
    }
}

// ---------------- K6: conv3d 3x3x3, 96 -> 3 ----------------
__global__ void conv_kernel(const float* __restrict__ cw, const float* __restrict__ cbias,
                            float* __restrict__ out) {
    __shared__ __align__(16) float sWc[27 * 3 * 96];
    __shared__ float sCB[3];
    int tid = threadIdx.x;
    for (int i = tid; i < 27 * 3 * 96; i += 256) {
        int k = i / 288, r = i % 288, o = r / 96, c = r % 96;
        sWc[i] = cw[((long)o * 96 + c) * 27 + k];
    }
    if (tid < 3) sCB[tid] = cbias[tid];
    __syncthreads();

    long base = (long)blockIdx.x * 1024;
    int bb[4], dd[4], hh2[4], ww2[4], ss[4];
    #pragma unroll
    for (int v = 0; v < 4; v++) {
        long t = base + tid + 256 * v;
        bb[v] = (int)(t / SPD);
        int s = (int)(t % SPD);
        ss[v] = s;
        dd[v] = s / (HH * WW_);
        hh2[v] = (s / WW_) % HH;
        ww2[v] = s % WW_;
    }
    float acc[4][3];
    #pragma unroll
    for (int v = 0; v < 4; v++) { acc[v][0] = acc[v][1] = acc[v][2] = 0.f; }

    for (int kd = -1; kd <= 1; kd++)
    for (int kh = -1; kh <= 1; kh++)
    for (int kw = -1; kw <= 1; kw++) {
        int k = (kd + 1) * 9 + (kh + 1) * 3 + (kw + 1);
        const float4* src[4];
        bool ok[4];
        #pragma unroll
        for (int v = 0; v < 4; v++) {
            int d2 = dd[v] + kd, h2 = hh2[v] + kh, w2 = ww2[v] + kw;
            ok[v] = ((unsigned)d2 < DD) && ((unsigned)h2 < HH) && ((unsigned)w2 < WW_);
            long nb = (long)bb[v] * SPD + ((long)d2 * HH + h2) * WW_ + w2;
            src[v] = (const float4*)(g_x3 + nb * 96);
        }
        const float* wk = sWc + k * 288;
        #pragma unroll 4
        for (int c4 = 0; c4 < 24; c4++) {
            float4 xv[4];
            #pragma unroll
            for (int v = 0; v < 4; v++)
                xv[v] = ok[v] ? src[v][c4] : make_float4(0.f, 0.f, 0.f, 0.f);
            #pragma unroll
            for (int o = 0; o < 3; o++) {
                float4 w4 = ((const float4*)(wk + o * 96))[c4];
                #pragma unroll
                for (int v = 0; v < 4; v++)
                    acc[v][o] += xv[v].x * w4.x + xv[v].y * w4.y +
                                 xv[v].z * w4.z + xv[v].w * w4.w;
            }
        }
    }
    #pragma unroll
    for (int v = 0; v < 4; v++)
        #pragma unroll
        for (int o = 0; o < 3; o++)
            out[((long)bb[v] * 3 + o) * SPD + ss[v]] = acc[v][o] + sCB[o];
}

// ---------------- launch ----------------
extern "C" void kernel_launch(void* const* d_in, const int* in_sizes, int n_in,
                              void* d_out, int out_size) {
    const float* I_m    = (const float*)d_in[0];
    const float* I_f    = (const float*)d_in[1];
    const float* ln1q_g = (const float*)d_in[2];
    const float* ln1q_b = (const float*)d_in[3];
    const float* ln1kv_g= (const float*)d_in[4];
    const float* ln1kv_b= (const float*)d_in[5];
    const float* wq     = (const float*)d_in[6];
    const float* bq     = (const float*)d_in[7];
    const float* wkv    = (const float*)d_in[8];
    const float* bkv    = (const float*)d_in[9];
    const float* wproj  = (const float*)d_in[10];
    const float* bproj  = (const float*)d_in[11];
    const float* relb   = (const float*)d_in[12];
    const float* ln2_g  = (const float*)d_in[13];
    const float* ln2_b  = (const float*)d_in[14];
    const float* w1     = (const float*)d_in[15];
    const float* b1     = (const float*)d_in[16];
    const float* w2     = (const float*)d_in[17];
    const float* b2     = (const float*)d_in[18];
    const float* cw     = (const float*)d_in[19];
    const float* cb     = (const float*)d_in[20];
    float* out = (float*)d_out;

    const int smem_q    = (96*33 + 96*96  + 96  + 8*4*96) * 4;
    const int smem_kv   = (96*33 + 96*192 + 192 + 8*4*96) * 4;
    const int smem_attn = (NT*PSTR*2 + NT*NT) * 4;

    cudaFuncSetAttribute(lnproj_kernel<96,  true >, cudaFuncAttributeMaxDynamicSharedMemorySize, smem_q);
    cudaFuncSetAttribute(lnproj_kernel<192, false>, cudaFuncAttributeMaxDynamicSharedMemorySize, smem_kv);
    cudaFuncSetAttribute(attn_kernel, cudaFuncAttributeMaxDynamicSharedMemorySize, smem_attn);
    cudaFuncSetAttribute(mlp_mma_kernel, cudaFuncAttributeMaxDynamicSharedMemorySize, MLP_SMEM);

    bias_kernel<<<(NT*NT + 255) / 256, 256>>>(relb);
    lnproj_kernel<96,  true ><<<TOT / 32, 256, smem_q >>>(I_m, ln1q_g,  ln1q_b,  wq,  bq);
    lnproj_kernel<192, false><<<TOT / 32, 256, smem_kv>>>(I_f, ln1kv_g, ln1kv_b, wkv, bkv);
    attn_kernel<<<NWIN, 1024, smem_attn>>>(wproj, bproj);
    mlp_mma_kernel<<<TOT / 128, 256, MLP_SMEM>>>(ln2_g, ln2_b, w1, b1, w2, b2);
    conv_kernel<<<TOT / 1024, 256>>>(cw, cb, out);
}

// round 6
// speedup vs baseline: 3.1225x; 1.1583x over previous
#include <cuda_runtime.h>
#include <cuda_bf16.h>
#include <math.h>
#include <stdint.h>

#define CC 96
#define DD 40
#define HH 48
#define WW_ 40
#define BB 2
#define WIN_D 5
#define WIN_H 6
#define WIN_W 5
#define NT 150
#define NWD 8
#define NWH 8
#define NWW 8
#define NWIN 1024
#define SPD (DD*HH*WW_)   /* 76800 */
#define TOT (BB*SPD)      /* 153600 */
#define HID 384

// ---------------- scratch (device globals; no allocation) ----------------
__device__ __align__(128) float g_xt [TOT*CC];
__device__ __align__(128) float g_q  [NWIN*NT*CC];
__device__ __align__(128) float g_k  [NWIN*NT*CC];
__device__ __align__(128) float g_v  [NWIN*NT*CC];
__device__ __align__(128) float g_x2 [TOT*CC];
__device__ __align__(128) float g_x3 [TOT*CC];
__device__ __align__(128) float g_bias[NT*NT];

__device__ __forceinline__ float warp_sum(float v) {
    #pragma unroll
    for (int o = 16; o > 0; o >>= 1) v += __shfl_xor_sync(0xffffffffu, v, o);
    return v;
}
__device__ __forceinline__ float gelu_fast(float x) {
    float z = 0.79788456080286535588f * (x + 0.044715f * x * x * x);
    float t = __expf(2.0f * z);
    return x * t / (t + 1.0f);
}
// pack two fp32 -> bf16x2 (lo in low half)
__device__ __forceinline__ uint32_t pack_bf16(float lo, float hi) {
    uint32_t r;
    asm("cvt.rn.bf16x2.f32 %0, %1, %2;" : "=r"(r) : "f"(hi), "f"(lo));
    return r;
}
__device__ __forceinline__ void mma16816(float c[4],
                                         uint32_t a0, uint32_t a1, uint32_t a2, uint32_t a3,
                                         uint32_t b0, uint32_t b1) {
    asm volatile(
        "mma.sync.aligned.m16n8k16.row.col.f32.bf16.bf16.f32 "
        "{%0,%1,%2,%3}, {%4,%5,%6,%7}, {%8,%9}, {%0,%1,%2,%3};"
        : "+f"(c[0]), "+f"(c[1]), "+f"(c[2]), "+f"(c[3])
        : "r"(a0), "r"(a1), "r"(a2), "r"(a3), "r"(b0), "r"(b1));
}

// ---------------- K0: relative position bias table ----------------
__global__ void bias_kernel(const float* __restrict__ rel_bias) {
    int i = blockIdx.x * blockDim.x + threadIdx.x;
    if (i >= NT * NT) return;
    int n = i / NT, m = i % NT;
    int nd = n / 30, nh = (n / 5) % 6, nw = n % 5;
    int md = m / 30, mh = (m / 5) % 6, mw = m % 5;
    int idx = (nd - md + 4) * 99 + (nh - mh + 5) * 9 + (nw - mw + 4);
    g_bias[i] = rel_bias[idx];
}

// ---------------- K1/K2: transpose + LN + projection (window layout) ----------------
template<int COUT, bool ISQ>
__global__ void lnproj_kernel(const float* __restrict__ in,
                              const float* __restrict__ gamma,
                              const float* __restrict__ beta,
                              const float* __restrict__ wmat,
                              const float* __restrict__ bvec) {
    extern __shared__ float sm[];
    float* tile = sm;
    float* sW   = tile + 96 * 33;
    float* sB   = sW + 96 * COUT;
    float* sLN  = sB + COUT;

    int tid = threadIdx.x, warp = tid >> 5, lane = tid & 31;
    long t0 = (long)blockIdx.x * 32;
    int b  = (int)(t0 / SPD);
    int s0 = (int)(t0 % SPD);

    for (int i = tid; i < 96 * COUT; i += 256) sW[i] = wmat[i];
    for (int i = tid; i < COUT; i += 256)      sB[i] = bvec[i];
    const float* inb = in + (long)b * 96 * SPD + s0;
    for (int i = tid; i < 96 * 32; i += 256) {
        int c = i >> 5, j = i & 31;
        tile[c * 33 + j] = inb[(long)c * SPD + j];
    }
    __syncthreads();

    if (ISQ) {
        for (int i = tid; i < 96 * 32; i += 256) {
            int c = i % 96, j = i / 96;
            g_xt[(t0 + j) * 96 + c] = tile[c * 33 + j];
        }
    }

    float* myLN = sLN + warp * 4 * 96;
    #pragma unroll
    for (int tt = 0; tt < 4; tt++) {
        int j = warp * 4 + tt;
        float v0 = tile[lane * 33 + j];
        float v1 = tile[(lane + 32) * 33 + j];
        float v2 = tile[(lane + 64) * 33 + j];
        float mean = warp_sum(v0 + v1 + v2) * (1.0f / 96.0f);
        float var  = warp_sum(v0 * v0 + v1 * v1 + v2 * v2) * (1.0f / 96.0f) - mean * mean;
        float inv  = rsqrtf(var + 1e-5f);
        myLN[tt * 96 + lane]      = (v0 - mean) * inv * gamma[lane]      + beta[lane];
        myLN[tt * 96 + lane + 32] = (v1 - mean) * inv * gamma[lane + 32] + beta[lane + 32];
        myLN[tt * 96 + lane + 64] = (v2 - mean) * inv * gamma[lane + 64] + beta[lane + 64];
    }
    __syncwarp();

    long addr[4];
    #pragma unroll
    for (int tt = 0; tt < 4; tt++) {
        long t = t0 + warp * 4 + tt;
        int s = (int)(t % SPD);
        int d = s / (HH * WW_), h = (s / WW_) % HH, w = s % WW_;
        int wi = ((b * NWD + d / WIN_D) * NWH + h / WIN_H) * NWW + w / WIN_W;
        int n  = (d % WIN_D) * (WIN_H * WIN_W) + (h % WIN_H) * WIN_W + (w % WIN_W);
        addr[tt] = ((long)wi * NT + n) * 96;
    }

    const float4* L0 = (const float4*)(myLN);
    const float4* L1 = (const float4*)(myLN + 96);
    const float4* L2 = (const float4*)(myLN + 192);
    const float4* L3 = (const float4*)(myLN + 288);
    for (int jj = lane; jj < COUT; jj += 32) {
        float a0 = 0.f, a1 = 0.f, a2 = 0.f, a3 = 0.f;
        #pragma unroll 6
        for (int c4 = 0; c4 < 24; c4++) {
            float4 l0 = L0[c4], l1 = L1[c4], l2 = L2[c4], l3 = L3[c4];
            const float* wp = sW + c4 * 4 * COUT + jj;
            float w0 = wp[0], w1 = wp[COUT], w2 = wp[2 * COUT], w3 = wp[3 * COUT];
            a0 += l0.x * w0 + l0.y * w1 + l0.z * w2 + l0.w * w3;
            a1 += l1.x * w0 + l1.y * w1 + l1.z * w2 + l1.w * w3;
            a2 += l2.x * w0 + l2.y * w1 + l2.z * w2 + l2.w * w3;
            a3 += l3.x * w0 + l3.y * w1 + l3.z * w2 + l3.w * w3;
        }
        float bb = sB[jj];
        a0 += bb; a1 += bb; a2 += bb; a3 += bb;
        if (COUT == 96) {
            g_q[addr[0] + jj] = a0; g_q[addr[1] + jj] = a1;
            g_q[addr[2] + jj] = a2; g_q[addr[3] + jj] = a3;
        } else {
            float* dst = (jj < 96) ? g_k : g_v;
            int j2 = (jj < 96) ? jj : jj - 96;
            dst[addr[0] + j2] = a0; dst[addr[1] + j2] = a1;
            dst[addr[2] + j2] = a2; dst[addr[3] + j2] = a3;
        }
    }
}

// ---------------- K3: per-window attention via mma.sync (bf16) ----------------
// 320 threads = 10 warps; warp w owns rows [16w, 16w+16) of 160 (150 real + 10 pad).
// smem: sQ bf16[160][104] | sK bf16[152][104] (wproj^T overlays) | sVT bf16[96][168] | bproj
#define AQS 104
#define VTS 168
#define WPS 104
#define ASQ_OFF 0
#define ASK_OFF 33280
#define ASVT_OFF 64896
#define ASBP_OFF 97152
#define ATT_SMEM 97536

__global__ void __launch_bounds__(320, 1)
attn_mma_kernel(const float* __restrict__ wproj, const float* __restrict__ bproj) {
    extern __shared__ __align__(16) char smem[];
    __nv_bfloat16* sQ  = (__nv_bfloat16*)(smem + ASQ_OFF);
    __nv_bfloat16* sK  = (__nv_bfloat16*)(smem + ASK_OFF);
    __nv_bfloat16* sWp = sK;   // overlays K after GEMM1
    __nv_bfloat16* sVT = (__nv_bfloat16*)(smem + ASVT_OFF);
    float* sBp = (float*)(smem + ASBP_OFF);

    int tid = threadIdx.x, wid = tid >> 5, lane = tid & 31;
    int g = lane >> 2, tig = lane & 3;
    int wi = blockIdx.x;
    int r0 = wid * 16;
    const float scale = 0.102062072615965696f;  // 96^-0.5

    const float* gq = g_q + (long)wi * NT * 96;
    const float* gk = g_k + (long)wi * NT * 96;
    const float* gv = g_v + (long)wi * NT * 96;

    // stage Q (160 rows, pad 0), K (152 rows, pad 0) as bf16x2
    for (int i = tid; i < 160 * 48; i += 320) {
        int r = i / 48, c2 = (i % 48) * 2;
        float2 v = (r < NT) ? *(const float2*)(gq + r * 96 + c2) : make_float2(0.f, 0.f);
        *(uint32_t*)(sQ + r * AQS + c2) = pack_bf16(v.x, v.y);
    }
    for (int i = tid; i < 152 * 48; i += 320) {
        int r = i / 48, c2 = (i % 48) * 2;
        float2 v = (r < NT) ? *(const float2*)(gk + r * 96 + c2) : make_float2(0.f, 0.f);
        *(uint32_t*)(sK + r * AQS + c2) = pack_bf16(v.x, v.y);
    }
    // stage V transposed: sVT[c][m], m pad 0 to 160
    for (int i = tid; i < 160 * 96; i += 320) {
        int m = i / 96, c = i % 96;
        float v = (m < NT) ? gv[(long)m * 96 + c] : 0.f;
        sVT[c * VTS + m] = __float2bfloat16_rn(v);
    }
    if (tid < 96) sBp[tid] = bproj[tid];
    __syncthreads();

    // ---- GEMM1: S stripe (16 x 152) in registers ----
    float cs[19][4];
    #pragma unroll
    for (int nt = 0; nt < 19; nt++) { cs[nt][0]=0.f; cs[nt][1]=0.f; cs[nt][2]=0.f; cs[nt][3]=0.f; }
    #pragma unroll
    for (int kk = 0; kk < 6; kk++) {
        int kb = kk * 16 + tig * 2;
        uint32_t a0 = *(const uint32_t*)(sQ + (r0 + g)     * AQS + kb);
        uint32_t a1 = *(const uint32_t*)(sQ + (r0 + g + 8) * AQS + kb);
        uint32_t a2 = *(const uint32_t*)(sQ + (r0 + g)     * AQS + kb + 8);
        uint32_t a3 = *(const uint32_t*)(sQ + (r0 + g + 8) * AQS + kb + 8);
        #pragma unroll
        for (int nt = 0; nt < 19; nt++) {
            int m = nt * 8 + g;
            uint32_t b0 = *(const uint32_t*)(sK + m * AQS + kb);
            uint32_t b1 = *(const uint32_t*)(sK + m * AQS + kb + 8);
            mma16816(cs[nt], a0, a1, a2, a3, b0, b1);
        }
    }

    // ---- softmax in registers (rows n0r, n1r) ----
    int n0r = r0 + g, n1r = r0 + g + 8;
    float mx0 = -1e30f, mx1 = -1e30f;
    #pragma unroll
    for (int nt = 0; nt < 19; nt++) {
        int m = nt * 8 + tig * 2;
        if (m < NT) {
            if (n0r < NT) {
                float2 bv = *(const float2*)(g_bias + n0r * NT + m);
                cs[nt][0] = cs[nt][0] * scale + bv.x;
                cs[nt][1] = cs[nt][1] * scale + bv.y;
            } else { cs[nt][0] = 0.f; cs[nt][1] = 0.f; }
            if (n1r < NT) {
                float2 bv = *(const float2*)(g_bias + n1r * NT + m);
                cs[nt][2] = cs[nt][2] * scale + bv.x;
                cs[nt][3] = cs[nt][3] * scale + bv.y;
            } else { cs[nt][2] = 0.f; cs[nt][3] = 0.f; }
            mx0 = fmaxf(mx0, fmaxf(cs[nt][0], cs[nt][1]));
            mx1 = fmaxf(mx1, fmaxf(cs[nt][2], cs[nt][3]));
        } else {
            cs[nt][0] = -1e30f; cs[nt][1] = -1e30f;
            cs[nt][2] = -1e30f; cs[nt][3] = -1e30f;
        }
    }
    mx0 = fmaxf(mx0, __shfl_xor_sync(0xffffffffu, mx0, 1));
    mx0 = fmaxf(mx0, __shfl_xor_sync(0xffffffffu, mx0, 2));
    mx1 = fmaxf(mx1, __shfl_xor_sync(0xffffffffu, mx1, 1));
    mx1 = fmaxf(mx1, __shfl_xor_sync(0xffffffffu, mx1, 2));
    float s0 = 0.f, s1 = 0.f;
    #pragma unroll
    for (int nt = 0; nt < 19; nt++) {
        cs[nt][0] = __expf(cs[nt][0] - mx0);
        cs[nt][1] = __expf(cs[nt][1] - mx0);
        cs[nt][2] = __expf(cs[nt][2] - mx1);
        cs[nt][3] = __expf(cs[nt][3] - mx1);
        s0 += cs[nt][0] + cs[nt][1];
        s1 += cs[nt][2] + cs[nt][3];
    }
    s0 += __shfl_xor_sync(0xffffffffu, s0, 1);
    s0 += __shfl_xor_sync(0xffffffffu, s0, 2);
    s1 += __shfl_xor_sync(0xffffffffu, s1, 1);
    s1 += __shfl_xor_sync(0xffffffffu, s1, 2);
    float inv0 = 1.0f / s0, inv1 = 1.0f / s1;

    // ---- pack P -> A-fragments (C-frag(2kt,2kt+1) == A-frag(kt)) ----
    uint32_t pa[10][4];
    #pragma unroll
    for (int kt = 0; kt < 10; kt++) {
        int e = 2 * kt, o = 2 * kt + 1;
        pa[kt][0] = pack_bf16(cs[e][0] * inv0, cs[e][1] * inv0);
        pa[kt][1] = pack_bf16(cs[e][2] * inv1, cs[e][3] * inv1);
        if (o < 19) {
            pa[kt][2] = pack_bf16(cs[o][0] * inv0, cs[o][1] * inv0);
            pa[kt][3] = pack_bf16(cs[o][2] * inv1, cs[o][3] * inv1);
        } else { pa[kt][2] = 0u; pa[kt][3] = 0u; }
    }

    // all warps done with sK -> overlay wproj^T
    __syncthreads();
    for (int i = tid; i < 96 * 96; i += 320) {
        int r = i / 96, cp = i % 96;     // wproj[r][cp]
        sWp[cp * WPS + r] = __float2bfloat16_rn(wproj[i]);
    }
    __syncthreads();

    // ---- GEMM2: O stripe (16 x 96) = P @ V ----
    float co[12][4];
    #pragma unroll
    for (int nt = 0; nt < 12; nt++) { co[nt][0]=0.f; co[nt][1]=0.f; co[nt][2]=0.f; co[nt][3]=0.f; }
    #pragma unroll
    for (int kt = 0; kt < 10; kt++) {
        int kb = kt * 16 + tig * 2;
        #pragma unroll
        for (int nt = 0; nt < 12; nt++) {
            int c = nt * 8 + g;
            uint32_t b0 = *(const uint32_t*)(sVT + c * VTS + kb);
            uint32_t b1 = *(const uint32_t*)(sVT + c * VTS + kb + 8);
            mma16816(co[nt], pa[kt][0], pa[kt][1], pa[kt][2], pa[kt][3], b0, b1);
        }
    }

    // ---- pack O -> A-frags; GEMM3: O2 = O @ Wp ----
    uint32_t oa[6][4];
    #pragma unroll
    for (int kt = 0; kt < 6; kt++) {
        oa[kt][0] = pack_bf16(co[2*kt][0],   co[2*kt][1]);
        oa[kt][1] = pack_bf16(co[2*kt][2],   co[2*kt][3]);
        oa[kt][2] = pack_bf16(co[2*kt+1][0], co[2*kt+1][1]);
        oa[kt][3] = pack_bf16(co[2*kt+1][2], co[2*kt+1][3]);
    }
    float c2r[12][4];
    #pragma unroll
    for (int nt = 0; nt < 12; nt++) { c2r[nt][0]=0.f; c2r[nt][1]=0.f; c2r[nt][2]=0.f; c2r[nt][3]=0.f; }
    #pragma unroll
    for (int kt = 0; kt < 6; kt++) {
        int kb = kt * 16 + tig * 2;
        #pragma unroll
        for (int nt = 0; nt < 12; nt++) {
            int cp = nt * 8 + g;
            uint32_t b0 = *(const uint32_t*)(sWp + cp * WPS + kb);
            uint32_t b1 = *(const uint32_t*)(sWp + cp * WPS + kb + 8);
            mma16816(c2r[nt], oa[kt][0], oa[kt][1], oa[kt][2], oa[kt][3], b0, b1);
        }
    }

    // ---- epilogue: x2 = shortcut + O2 + bproj ----
    int iww = wi & 7, iwh = (wi >> 3) & 7, iwd = (wi >> 6) & 7, b = wi >> 9;
    long t0r = -1, t1r = -1;
    if (n0r < NT) {
        int zd = n0r / 30, zh = (n0r / 5) % 6, zw = n0r % 5;
        int d = iwd * WIN_D + zd, h = iwh * WIN_H + zh, w = iww * WIN_W + zw;
        t0r = (long)b * SPD + ((long)d * HH + h) * WW_ + w;
    }
    if (n1r < NT) {
        int zd = n1r / 30, zh = (n1r / 5) % 6, zw = n1r % 5;
        int d = iwd * WIN_D + zd, h = iwh * WIN_H + zh, w = iww * WIN_W + zw;
        t1r = (long)b * SPD + ((long)d * HH + h) * WW_ + w;
    }
    #pragma unroll
    for (int nt = 0; nt < 12; nt++) {
        int cp = nt * 8 + tig * 2;
        float b0v = sBp[cp], b1v = sBp[cp + 1];
        if (t0r >= 0) {
            float2 x = *(const float2*)(g_xt + t0r * 96 + cp);
            float2 o = make_float2(x.x + c2r[nt][0] + b0v, x.y + c2r[nt][1] + b1v);
            *(float2*)(g_x2 + t0r * 96 + cp) = o;
        }
        if (t1r >= 0) {
            float2 x = *(const float2*)(g_xt + t1r * 96 + cp);
            float2 o = make_float2(x.x + c2r[nt][2] + b0v, x.y + c2r[nt][3] + b1v);
            *(float2*)(g_x2 + t1r * 96 + cp) = o;
        }
    }
}

// ---------------- K4: fused LN2 + MLP via mma.sync (bf16 HMMA, fp32 accum) ----------------
#define ASTR 104
#define T1S  132
#define T2S  100
#define MA_OFF   0
#define MT1_OFF  26624
#define MT2_OFF  77312
#define MB1F_OFF 128512
#define MB2F_OFF 130048
#define MLG_OFF  130432
#define MLB_OFF  130816
#define MLP_SMEM 131200

__global__ void __launch_bounds__(256, 1)
mlp_mma_kernel(const float* __restrict__ g2, const float* __restrict__ b2ln,
               const float* __restrict__ w1, const float* __restrict__ b1,
               const float* __restrict__ w2, const float* __restrict__ b2) {
    extern __shared__ __align__(16) char smem[];
    __nv_bfloat16* sA = (__nv_bfloat16*)(smem + MA_OFF);
    float* sT1  = (float*)(smem + MT1_OFF);
    float* sT2  = (float*)(smem + MT2_OFF);
    float* sb1f = (float*)(smem + MB1F_OFF);
    float* sb2f = (float*)(smem + MB2F_OFF);
    float* slg  = (float*)(smem + MLG_OFF);
    float* slb  = (float*)(smem + MLB_OFF);

    int tid = threadIdx.x, wid = tid >> 5, lane = tid & 31;
    int g = lane >> 2, tig = lane & 3;
    long t0 = (long)blockIdx.x * 128;
    int r0 = wid * 16;

    for (int i = tid; i < HID; i += 256) sb1f[i] = b1[i];
    if (tid < 96) { sb2f[tid] = b2[tid]; slg[tid] = g2[tid]; slb[tid] = b2ln[tid]; }
    __syncthreads();

    #pragma unroll 1
    for (int it = 0; it < 16; it++) {
        int r = r0 + it;
        const float* xr = g_x2 + (t0 + r) * 96;
        float v0 = xr[lane], v1 = xr[lane + 32], v2 = xr[lane + 64];
        float mean = warp_sum(v0 + v1 + v2) * (1.0f / 96.0f);
        float var  = warp_sum(v0 * v0 + v1 * v1 + v2 * v2) * (1.0f / 96.0f) - mean * mean;
        float inv  = rsqrtf(var + 1e-5f);
        sA[r * ASTR + lane]      = __float2bfloat16_rn((v0 - mean) * inv * slg[lane]      + slb[lane]);
        sA[r * ASTR + lane + 32] = __float2bfloat16_rn((v1 - mean) * inv * slg[lane + 32] + slb[lane + 32]);
        sA[r * ASTR + lane + 64] = __float2bfloat16_rn((v2 - mean) * inv * slg[lane + 64] + slb[lane + 64]);
    }

    float c2[12][4];
    #pragma unroll
    for (int nt = 0; nt < 12; nt++)
        #pragma unroll
        for (int e = 0; e < 4; e++) c2[nt][e] = 0.f;

    uint32_t h[16][2];

    for (int j = 0; j < 3; j++) {
        __syncthreads();
        for (int i = tid; i < 96 * 32; i += 256) {
            int k = i >> 5, n4 = (i & 31) << 2;
            float4 v = *(const float4*)(w1 + (long)k * HID + j * 128 + n4);
            *(float4*)(sT1 + k * T1S + n4) = v;
        }
        for (int i = tid; i < 128 * 24; i += 256) {
            int k = i / 24, n4 = (i % 24) << 2;
            float4 v = *(const float4*)(w2 + (long)(j * 128 + k) * 96 + n4);
            *(float4*)(sT2 + k * T2S + n4) = v;
        }
        __syncthreads();

        #pragma unroll
        for (int half = 0; half < 2; half++) {
            float c1[8][4];
            #pragma unroll
            for (int nt = 0; nt < 8; nt++)
                #pragma unroll
                for (int e = 0; e < 4; e++) c1[nt][e] = 0.f;
            #pragma unroll
            for (int kk = 0; kk < 6; kk++) {
                int kb = kk * 16 + tig * 2;
                uint32_t a0 = *(const uint32_t*)(sA + (r0 + g) * ASTR + kb);
                uint32_t a1 = *(const uint32_t*)(sA + (r0 + g + 8) * ASTR + kb);
                uint32_t a2 = *(const uint32_t*)(sA + (r0 + g) * ASTR + kb + 8);
                uint32_t a3 = *(const uint32_t*)(sA + (r0 + g + 8) * ASTR + kb + 8);
                #pragma unroll
                for (int nt = 0; nt < 8; nt++) {
                    int n = (half * 8 + nt) * 8 + g;
                    uint32_t b0 = pack_bf16(sT1[kb * T1S + n],       sT1[(kb + 1) * T1S + n]);
                    uint32_t b1v = pack_bf16(sT1[(kb + 8) * T1S + n], sT1[(kb + 9) * T1S + n]);
                    mma16816(c1[nt], a0, a1, a2, a3, b0, b1v);
                }
            }
            #pragma unroll
            for (int nt = 0; nt < 8; nt++) {
                int nn = (half * 8 + nt) * 8 + tig * 2;
                float bb0 = sb1f[j * 128 + nn], bb1 = sb1f[j * 128 + nn + 1];
                h[half * 8 + nt][0] = pack_bf16(gelu_fast(c1[nt][0] + bb0), gelu_fast(c1[nt][1] + bb1));
                h[half * 8 + nt][1] = pack_bf16(gelu_fast(c1[nt][2] + bb0), gelu_fast(c1[nt][3] + bb1));
            }
        }

        #pragma unroll
        for (int kk = 0; kk < 8; kk++) {
            uint32_t a0 = h[2 * kk][0], a1 = h[2 * kk][1];
            uint32_t a2 = h[2 * kk + 1][0], a3 = h[2 * kk + 1][1];
            int kb = kk * 16 + tig * 2;
            #pragma unroll
            for (int nt = 0; nt < 12; nt++) {
                int n = nt * 8 + g;
                uint32_t b0 = pack_bf16(sT2[kb * T2S + n],       sT2[(kb + 1) * T2S + n]);
                uint32_t b1v = pack_bf16(sT2[(kb + 8) * T2S + n], sT2[(kb + 9) * T2S + n]);
                mma16816(c2[nt], a0, a1, a2, a3, b0, b1v);
            }
        }
    }

    #pragma unroll
    for (int nt = 0; nt < 12; nt++) {
        int n = nt * 8 + tig * 2;
        long ra = t0 + r0 + g;
        float bb0 = sb2f[n], bb1 = sb2f[n + 1];
        float2 x0 = *(const float2*)(g_x2 + ra * 96 + n);
        float2 x1 = *(const float2*)(g_x2 + (ra + 8) * 96 + n);
        float2 o0 = make_float2(x0.x + c2[nt][0] + bb0, x0.y + c2[nt][1] + bb1);
        float2 o1 = make_float2(x1.x + c2[nt][2] + bb0, x1.y + c2[nt][3] + bb1);
        *(float2*)(g_x3 + ra * 96 + n) = o0;
        *(float2*)(g_x3 + (ra + 8) * 96 + n) = o1;
    }
}

// ---------------- K6: conv3d 3x3x3, 96 -> 3 ----------------
__global__ void conv_kernel(const float* __restrict__ cw, const float* __restrict__ cbias,
                            float* __restrict__ out) {
    __shared__ __align__(16) float sWc[27 * 3 * 96];
    __shared__ float sCB[3];
    int tid = threadIdx.x;
    for (int i = tid; i < 27 * 3 * 96; i += 256) {
        int k = i / 288, r = i % 288, o = r / 96, c = r % 96;
        sWc[i] = cw[((long)o * 96 + c) * 27 + k];
    }
    if (tid < 3) sCB[tid] = cbias[tid];
    __syncthreads();

    long base = (long)blockIdx.x * 1024;
    int bb[4], dd[4], hh2[4], ww2[4], ss[4];
    #pragma unroll
    for (int v = 0; v < 4; v++) {
        long t = base + tid + 256 * v;
        bb[v] = (int)(t / SPD);
        int s = (int)(t % SPD);
        ss[v] = s;
        dd[v] = s / (HH * WW_);
        hh2[v] = (s / WW_) % HH;
        ww2[v] = s % WW_;
    }
    float acc[4][3];
    #pragma unroll
    for (int v = 0; v < 4; v++) { acc[v][0] = acc[v][1] = acc[v][2] = 0.f; }

    for (int kd = -1; kd <= 1; kd++)
    for (int kh = -1; kh <= 1; kh++)
    for (int kw = -1; kw <= 1; kw++) {
        int k = (kd + 1) * 9 + (kh + 1) * 3 + (kw + 1);
        const float4* src[4];
        bool ok[4];
        #pragma unroll
        for (int v = 0; v < 4; v++) {
            int d2 = dd[v] + kd, h2 = hh2[v] + kh, w2 = ww2[v] + kw;
            ok[v] = ((unsigned)d2 < DD) && ((unsigned)h2 < HH) && ((unsigned)w2 < WW_);
            long nb = (long)bb[v] * SPD + ((long)d2 * HH + h2) * WW_ + w2;
            src[v] = (const float4*)(g_x3 + nb * 96);
        }
        const float* wk = sWc + k * 288;
        #pragma unroll 4
        for (int c4 = 0; c4 < 24; c4++) {
            float4 xv[4];
            #pragma unroll
            for (int v = 0; v < 4; v++)
                xv[v] = ok[v] ? src[v][c4] : make_float4(0.f, 0.f, 0.f, 0.f);
            #pragma unroll
            for (int o = 0; o < 3; o++) {
                float4 w4 = ((const float4*)(wk + o * 96))[c4];
                #pragma unroll
                for (int v = 0; v < 4; v++)
                    acc[v][o] += xv[v].x * w4.x + xv[v].y * w4.y +
                                 xv[v].z * w4.z + xv[v].w * w4.w;
            }
        }
    }
    #pragma unroll
    for (int v = 0; v < 4; v++)
        #pragma unroll
        for (int o = 0; o < 3; o++)
            out[((long)bb[v] * 3 + o) * SPD + ss[v]] = acc[v][o] + sCB[o];
}

// ---------------- launch ----------------
extern "C" void kernel_launch(void* const* d_in, const int* in_sizes, int n_in,
                              void* d_out, int out_size) {
    const float* I_m    = (const float*)d_in[0];
    const float* I_f    = (const float*)d_in[1];
    const float* ln1q_g = (const float*)d_in[2];
    const float* ln1q_b = (const float*)d_in[3];
    const float* ln1kv_g= (const float*)d_in[4];
    const float* ln1kv_b= (const float*)d_in[5];
    const float* wq     = (const float*)d_in[6];
    const float* bq     = (const float*)d_in[7];
    const float* wkv    = (const float*)d_in[8];
    const float* bkv    = (const float*)d_in[9];
    const float* wproj  = (const float*)d_in[10];
    const float* bproj  = (const float*)d_in[11];
    const float* relb   = (const float*)d_in[12];
    const float* ln2_g  = (const float*)d_in[13];
    const float* ln2_b  = (const float*)d_in[14];
    const float* w1     = (const float*)d_in[15];
    const float* b1     = (const float*)d_in[16];
    const float* w2     = (const float*)d_in[17];
    const float* b2     = (const float*)d_in[18];
    const float* cw     = (const float*)d_in[19];
    const float* cb     = (const float*)d_in[20];
    float* out = (float*)d_out;

    const int smem_q    = (96*33 + 96*96  + 96  + 8*4*96) * 4;
    const int smem_kv   = (96*33 + 96*192 + 192 + 8*4*96) * 4;

    cudaFuncSetAttribute(lnproj_kernel<96,  true >, cudaFuncAttributeMaxDynamicSharedMemorySize, smem_q);
    cudaFuncSetAttribute(lnproj_kernel<192, false>, cudaFuncAttributeMaxDynamicSharedMemorySize, smem_kv);
    cudaFuncSetAttribute(attn_mma_kernel, cudaFuncAttributeMaxDynamicSharedMemorySize, ATT_SMEM);
    cudaFuncSetAttribute(mlp_mma_kernel, cudaFuncAttributeMaxDynamicSharedMemorySize, MLP_SMEM);

    bias_kernel<<<(NT*NT + 255) / 256, 256>>>(relb);
    lnproj_kernel<96,  true ><<<TOT / 32, 256, smem_q >>>(I_m, ln1q_g,  ln1q_b,  wq,  bq);
    lnproj_kernel<192, false><<<TOT / 32, 256, smem_kv>>>(I_f, ln1kv_g, ln1kv_b, wkv, bkv);
    attn_mma_kernel<<<NWIN, 320, ATT_SMEM>>>(wproj, bproj);
    mlp_mma_kernel<<<TOT / 128, 256, MLP_SMEM>>>(ln2_g, ln2_b, w1, b1, w2, b2);
    conv_kernel<<<TOT / 1024, 256>>>(cw, cb, out);
}

// round 7
// speedup vs baseline: 4.2839x; 1.3719x over previous
#include <cuda_runtime.h>
#include <cuda_bf16.h>
#include <math.h>
#include <stdint.h>

#define CC 96
#define DD 40
#define HH 48
#define WW_ 40
#define BB 2
#define WIN_D 5
#define WIN_H 6
#define WIN_W 5
#define NT 150
#define NWD 8
#define NWH 8
#define NWW 8
#define NWIN 1024
#define SPD (DD*HH*WW_)   /* 76800 */
#define TOT (BB*SPD)      /* 153600 */
#define HID 384

// ---------------- scratch (device globals; no allocation) ----------------
__device__ __align__(128) float          g_xt [TOT*CC];
__device__ __align__(128) __nv_bfloat16  g_q  [NWIN*NT*CC];
__device__ __align__(128) __nv_bfloat16  g_k  [NWIN*NT*CC];
__device__ __align__(128) __nv_bfloat16  g_v  [NWIN*NT*CC];
__device__ __align__(128) float          g_x2 [TOT*CC];
__device__ __align__(128) float          g_x3 [TOT*CC];
__device__ __align__(128) float          g_bias[NT*NT];

__device__ __forceinline__ float warp_sum(float v) {
    #pragma unroll
    for (int o = 16; o > 0; o >>= 1) v += __shfl_xor_sync(0xffffffffu, v, o);
    return v;
}
__device__ __forceinline__ float gelu_fast(float x) {
    float z = 0.79788456080286535588f * (x + 0.044715f * x * x * x);
    float t = __expf(2.0f * z);
    return x * t / (t + 1.0f);
}
__device__ __forceinline__ uint32_t pack_bf16(float lo, float hi) {
    uint32_t r;
    asm("cvt.rn.bf16x2.f32 %0, %1, %2;" : "=r"(r) : "f"(hi), "f"(lo));
    return r;
}
__device__ __forceinline__ void mma16816(float c[4],
                                         uint32_t a0, uint32_t a1, uint32_t a2, uint32_t a3,
                                         uint32_t b0, uint32_t b1) {
    asm volatile(
        "mma.sync.aligned.m16n8k16.row.col.f32.bf16.bf16.f32 "
        "{%0,%1,%2,%3}, {%4,%5,%6,%7}, {%8,%9}, {%0,%1,%2,%3};"
        : "+f"(c[0]), "+f"(c[1]), "+f"(c[2]), "+f"(c[3])
        : "r"(a0), "r"(a1), "r"(a2), "r"(a3), "r"(b0), "r"(b1));
}

// ---------------- K0: relative position bias table ----------------
__global__ void bias_kernel(const float* __restrict__ rel_bias) {
    int i = blockIdx.x * blockDim.x + threadIdx.x;
    if (i >= NT * NT) return;
    int n = i / NT, m = i % NT;
    int nd = n / 30, nh = (n / 5) % 6, nw = n % 5;
    int md = m / 30, mh = (m / 5) % 6, mw = m % 5;
    int idx = (nd - md + 4) * 99 + (nh - mh + 5) * 9 + (nw - mw + 4);
    g_bias[i] = rel_bias[idx];
}

// ---------------- K1/K2: transpose + LN + projection via mma.sync ----------------
// 256 threads, 128 tokens/CTA. tile f32[96][129] | sA bf16[128][104] | sWT bf16[COUT][104]
#define LTS 129
#define LASTR 104
template<int COUT, bool ISQ>
__global__ void __launch_bounds__(256)
lnproj_mma_kernel(const float* __restrict__ in,
                  const float* __restrict__ gamma,
                  const float* __restrict__ beta,
                  const float* __restrict__ wmat,   // (96, COUT)
                  const float* __restrict__ bvec) {
    extern __shared__ __align__(16) char smem[];
    float* tile = (float*)smem;                                    // 49536 B
    __nv_bfloat16* sA  = (__nv_bfloat16*)(smem + 49536);           // 26624 B
    __nv_bfloat16* sWT = (__nv_bfloat16*)(smem + 76160);           // COUT*208 B
    float* sB  = (float*)(smem + 76160 + COUT * 208);
    float* sG  = sB + COUT;
    float* sBt = sG + 96;

    int tid = threadIdx.x, wid = tid >> 5, lane = tid & 31;
    int g = lane >> 2, tig = lane & 3;
    long t0 = (long)blockIdx.x * 128;
    int b  = (int)(t0 / SPD);
    int s0 = (int)(t0 % SPD);
    int r0 = wid * 16;

    // stage input tile (channel-major, coalesced)
    const float* inb = in + (long)b * 96 * SPD + s0;
    for (int i = tid; i < 96 * 128; i += 256) {
        int c = i >> 7, t = i & 127;
        tile[c * LTS + t] = inb[(long)c * SPD + t];
    }
    // stage W transposed bf16
    for (int i = tid; i < 96 * COUT; i += 256) {
        int k = i / COUT, n = i - k * COUT;
        sWT[n * LASTR + k] = __float2bfloat16_rn(wmat[i]);
    }
    for (int i = tid; i < COUT; i += 256) sB[i] = bvec[i];
    if (tid < 96) { sG[tid] = gamma[tid]; sBt[tid] = beta[tid]; }
    __syncthreads();

    if (ISQ) {  // shortcut transpose to global (fp32)
        for (int i = tid; i < 96 * 128; i += 256) {
            int c = i % 96, t = i / 96;
            g_xt[(t0 + t) * 96 + c] = tile[c * LTS + t];
        }
    }

    // LN -> sA bf16
    #pragma unroll 1
    for (int it = 0; it < 16; it++) {
        int t = r0 + it;
        float v0 = tile[lane * LTS + t];
        float v1 = tile[(lane + 32) * LTS + t];
        float v2 = tile[(lane + 64) * LTS + t];
        float mean = warp_sum(v0 + v1 + v2) * (1.0f / 96.0f);
        float var  = warp_sum(v0 * v0 + v1 * v1 + v2 * v2) * (1.0f / 96.0f) - mean * mean;
        float inv  = rsqrtf(var + 1e-5f);
        sA[t * LASTR + lane]      = __float2bfloat16_rn((v0 - mean) * inv * sG[lane]      + sBt[lane]);
        sA[t * LASTR + lane + 32] = __float2bfloat16_rn((v1 - mean) * inv * sG[lane + 32] + sBt[lane + 32]);
        sA[t * LASTR + lane + 64] = __float2bfloat16_rn((v2 - mean) * inv * sG[lane + 64] + sBt[lane + 64]);
    }
    __syncthreads();

    // window addresses for this thread's two rows
    long base0, base1;
    {
        int rows[2] = { r0 + g, r0 + g + 8 };
        long bases[2];
        #pragma unroll
        for (int rr = 0; rr < 2; rr++) {
            long t = t0 + rows[rr];
            int s = (int)(t % SPD);
            int d = s / (HH * WW_), h = (s / WW_) % HH, w = s % WW_;
            int wi = ((b * NWD + d / WIN_D) * NWH + h / WIN_H) * NWW + w / WIN_W;
            int n  = (d % WIN_D) * 30 + (h % WIN_H) * 5 + (w % WIN_W);
            bases[rr] = ((long)wi * NT + n) * 96;
        }
        base0 = bases[0]; base1 = bases[1];
    }

    const int NHALF = COUT / 96;
    #pragma unroll
    for (int half = 0; half < NHALF; half++) {
        float c[12][4];
        #pragma unroll
        for (int nt = 0; nt < 12; nt++) { c[nt][0]=0.f; c[nt][1]=0.f; c[nt][2]=0.f; c[nt][3]=0.f; }
        #pragma unroll
        for (int kk = 0; kk < 6; kk++) {
            int kb = kk * 16 + tig * 2;
            uint32_t a0 = *(const uint32_t*)(sA + (r0 + g)     * LASTR + kb);
            uint32_t a1 = *(const uint32_t*)(sA + (r0 + g + 8) * LASTR + kb);
            uint32_t a2 = *(const uint32_t*)(sA + (r0 + g)     * LASTR + kb + 8);
            uint32_t a3 = *(const uint32_t*)(sA + (r0 + g + 8) * LASTR + kb + 8);
            #pragma unroll
            for (int nt = 0; nt < 12; nt++) {
                int n = half * 96 + nt * 8 + g;
                uint32_t b0 = *(const uint32_t*)(sWT + n * LASTR + kb);
                uint32_t b1 = *(const uint32_t*)(sWT + n * LASTR + kb + 8);
                mma16816(c[nt], a0, a1, a2, a3, b0, b1);
            }
        }
        __nv_bfloat16* dst = ISQ ? g_q : (half == 0 ? g_k : g_v);
        #pragma unroll
        for (int nt = 0; nt < 12; nt++) {
            int col = nt * 8 + tig * 2;
            float b0v = sB[half * 96 + col], b1v = sB[half * 96 + col + 1];
            *(uint32_t*)(dst + base0 + col) = pack_bf16(c[nt][0] + b0v, c[nt][1] + b1v);
            *(uint32_t*)(dst + base1 + col) = pack_bf16(c[nt][2] + b0v, c[nt][3] + b1v);
        }
    }
}

// ---------------- K3: per-window attention via mma.sync (bf16) ----------------
#define AQS 104
#define VTS 168
#define WPS 104
#define ASQ_OFF 0
#define ASK_OFF 33280
#define ASVT_OFF 64896
#define ASBP_OFF 97152
#define ATT_SMEM 97536

__global__ void __launch_bounds__(320, 1)
attn_mma_kernel(const float* __restrict__ wproj, const float* __restrict__ bproj) {
    extern __shared__ __align__(16) char smem[];
    __nv_bfloat16* sQ  = (__nv_bfloat16*)(smem + ASQ_OFF);
    __nv_bfloat16* sK  = (__nv_bfloat16*)(smem + ASK_OFF);
    __nv_bfloat16* sWp = sK;   // overlays K after GEMM1
    __nv_bfloat16* sVT = (__nv_bfloat16*)(smem + ASVT_OFF);
    float* sBp = (float*)(smem + ASBP_OFF);

    int tid = threadIdx.x, wid = tid >> 5, lane = tid & 31;
    int g = lane >> 2, tig = lane & 3;
    int wi = blockIdx.x;
    int r0 = wid * 16;
    const float scale = 0.102062072615965696f;

    const __nv_bfloat16* gq = g_q + (long)wi * NT * 96;
    const __nv_bfloat16* gk = g_k + (long)wi * NT * 96;
    const __nv_bfloat16* gv = g_v + (long)wi * NT * 96;

    for (int i = tid; i < 160 * 48; i += 320) {
        int r = i / 48, c2 = (i % 48) * 2;
        uint32_t v = (r < NT) ? *(const uint32_t*)(gq + r * 96 + c2) : 0u;
        *(uint32_t*)(sQ + r * AQS + c2) = v;
    }
    for (int i = tid; i < 152 * 48; i += 320) {
        int r = i / 48, c2 = (i % 48) * 2;
        uint32_t v = (r < NT) ? *(const uint32_t*)(gk + r * 96 + c2) : 0u;
        *(uint32_t*)(sK + r * AQS + c2) = v;
    }
    for (int i = tid; i < 160 * 96; i += 320) {
        int m = i / 96, c = i % 96;
        sVT[c * VTS + m] = (m < NT) ? gv[(long)m * 96 + c] : __nv_bfloat16(0.f);
    }
    if (tid < 96) sBp[tid] = bproj[tid];
    __syncthreads();

    // ---- GEMM1: S stripe (16 x 152) in registers ----
    float cs[19][4];
    #pragma unroll
    for (int nt = 0; nt < 19; nt++) { cs[nt][0]=0.f; cs[nt][1]=0.f; cs[nt][2]=0.f; cs[nt][3]=0.f; }
    #pragma unroll
    for (int kk = 0; kk < 6; kk++) {
        int kb = kk * 16 + tig * 2;
        uint32_t a0 = *(const uint32_t*)(sQ + (r0 + g)     * AQS + kb);
        uint32_t a1 = *(const uint32_t*)(sQ + (r0 + g + 8) * AQS + kb);
        uint32_t a2 = *(const uint32_t*)(sQ + (r0 + g)     * AQS + kb + 8);
        uint32_t a3 = *(const uint32_t*)(sQ + (r0 + g + 8) * AQS + kb + 8);
        #pragma unroll
        for (int nt = 0; nt < 19; nt++) {
            int m = nt * 8 + g;
            uint32_t b0 = *(const uint32_t*)(sK + m * AQS + kb);
            uint32_t b1 = *(const uint32_t*)(sK + m * AQS + kb + 8);
            mma16816(cs[nt], a0, a1, a2, a3, b0, b1);
        }
    }

    // ---- softmax in registers ----
    int n0r = r0 + g, n1r = r0 + g + 8;
    float mx0 = -1e30f, mx1 = -1e30f;
    #pragma unroll
    for (int nt = 0; nt < 19; nt++) {
        int m = nt * 8 + tig * 2;
        if (m < NT) {
            if (n0r < NT) {
                float2 bv = *(const float2*)(g_bias + n0r * NT + m);
                cs[nt][0] = cs[nt][0] * scale + bv.x;
                cs[nt][1] = cs[nt][1] * scale + bv.y;
            } else { cs[nt][0] = 0.f; cs[nt][1] = 0.f; }
            if (n1r < NT) {
                float2 bv = *(const float2*)(g_bias + n1r * NT + m);
                cs[nt][2] = cs[nt][2] * scale + bv.x;
                cs[nt][3] = cs[nt][3] * scale + bv.y;
            } else { cs[nt][2] = 0.f; cs[nt][3] = 0.f; }
            mx0 = fmaxf(mx0, fmaxf(cs[nt][0], cs[nt][1]));
            mx1 = fmaxf(mx1, fmaxf(cs[nt][2], cs[nt][3]));
        } else {
            cs[nt][0] = -1e30f; cs[nt][1] = -1e30f;
            cs[nt][2] = -1e30f; cs[nt][3] = -1e30f;
        }
    }
    mx0 = fmaxf(mx0, __shfl_xor_sync(0xffffffffu, mx0, 1));
    mx0 = fmaxf(mx0, __shfl_xor_sync(0xffffffffu, mx0, 2));
    mx1 = fmaxf(mx1, __shfl_xor_sync(0xffffffffu, mx1, 1));
    mx1 = fmaxf(mx1, __shfl_xor_sync(0xffffffffu, mx1, 2));
    float s0 = 0.f, s1 = 0.f;
    #pragma unroll
    for (int nt = 0; nt < 19; nt++) {
        cs[nt][0] = __expf(cs[nt][0] - mx0);
        cs[nt][1] = __expf(cs[nt][1] - mx0);
        cs[nt][2] = __expf(cs[nt][2] - mx1);
        cs[nt][3] = __expf(cs[nt][3] - mx1);
        s0 += cs[nt][0] + cs[nt][1];
        s1 += cs[nt][2] + cs[nt][3];
    }
    s0 += __shfl_xor_sync(0xffffffffu, s0, 1);
    s0 += __shfl_xor_sync(0xffffffffu, s0, 2);
    s1 += __shfl_xor_sync(0xffffffffu, s1, 1);
    s1 += __shfl_xor_sync(0xffffffffu, s1, 2);
    float inv0 = 1.0f / s0, inv1 = 1.0f / s1;

    uint32_t pa[10][4];
    #pragma unroll
    for (int kt = 0; kt < 10; kt++) {
        int e = 2 * kt, o = 2 * kt + 1;
        pa[kt][0] = pack_bf16(cs[e][0] * inv0, cs[e][1] * inv0);
        pa[kt][1] = pack_bf16(cs[e][2] * inv1, cs[e][3] * inv1);
        if (o < 19) {
            pa[kt][2] = pack_bf16(cs[o][0] * inv0, cs[o][1] * inv0);
            pa[kt][3] = pack_bf16(cs[o][2] * inv1, cs[o][3] * inv1);
        } else { pa[kt][2] = 0u; pa[kt][3] = 0u; }
    }

    __syncthreads();
    for (int i = tid; i < 96 * 96; i += 320) {
        int r = i / 96, cp = i % 96;
        sWp[cp * WPS + r] = __float2bfloat16_rn(wproj[i]);
    }
    __syncthreads();

    // ---- GEMM2: O = P @ V ----
    float co[12][4];
    #pragma unroll
    for (int nt = 0; nt < 12; nt++) { co[nt][0]=0.f; co[nt][1]=0.f; co[nt][2]=0.f; co[nt][3]=0.f; }
    #pragma unroll
    for (int kt = 0; kt < 10; kt++) {
        int kb = kt * 16 + tig * 2;
        #pragma unroll
        for (int nt = 0; nt < 12; nt++) {
            int c = nt * 8 + g;
            uint32_t b0 = *(const uint32_t*)(sVT + c * VTS + kb);
            uint32_t b1 = *(const uint32_t*)(sVT + c * VTS + kb + 8);
            mma16816(co[nt], pa[kt][0], pa[kt][1], pa[kt][2], pa[kt][3], b0, b1);
        }
    }

    uint32_t oa[6][4];
    #pragma unroll
    for (int kt = 0; kt < 6; kt++) {
        oa[kt][0] = pack_bf16(co[2*kt][0],   co[2*kt][1]);
        oa[kt][1] = pack_bf16(co[2*kt][2],   co[2*kt][3]);
        oa[kt][2] = pack_bf16(co[2*kt+1][0], co[2*kt+1][1]);
        oa[kt][3] = pack_bf16(co[2*kt+1][2], co[2*kt+1][3]);
    }
    float c2r[12][4];
    #pragma unroll
    for (int nt = 0; nt < 12; nt++) { c2r[nt][0]=0.f; c2r[nt][1]=0.f; c2r[nt][2]=0.f; c2r[nt][3]=0.f; }
    #pragma unroll
    for (int kt = 0; kt < 6; kt++) {
        int kb = kt * 16 + tig * 2;
        #pragma unroll
        for (int nt = 0; nt < 12; nt++) {
            int cp = nt * 8 + g;
            uint32_t b0 = *(const uint32_t*)(sWp + cp * WPS + kb);
            uint32_t b1 = *(const uint32_t*)(sWp + cp * WPS + kb + 8);
            mma16816(c2r[nt], oa[kt][0], oa[kt][1], oa[kt][2], oa[kt][3], b0, b1);
        }
    }

    int iww = wi & 7, iwh = (wi >> 3) & 7, iwd = (wi >> 6) & 7, b = wi >> 9;
    long t0r = -1, t1r = -1;
    if (n0r < NT) {
        int zd = n0r / 30, zh = (n0r / 5) % 6, zw = n0r % 5;
        int d = iwd * WIN_D + zd, h = iwh * WIN_H + zh, w = iww * WIN_W + zw;
        t0r = (long)b * SPD + ((long)d * HH + h) * WW_ + w;
    }
    if (n1r < NT) {
        int zd = n1r / 30, zh = (n1r / 5) % 6, zw = n1r % 5;
        int d = iwd * WIN_D + zd, h = iwh * WIN_H + zh, w = iww * WIN_W + zw;
        t1r = (long)b * SPD + ((long)d * HH + h) * WW_ + w;
    }
    #pragma unroll
    for (int nt = 0; nt < 12; nt++) {
        int cp = nt * 8 + tig * 2;
        float b0v = sBp[cp], b1v = sBp[cp + 1];
        if (t0r >= 0) {
            float2 x = *(const float2*)(g_xt + t0r * 96 + cp);
            float2 o = make_float2(x.x + c2r[nt][0] + b0v, x.y + c2r[nt][1] + b1v);
            *(float2*)(g_x2 + t0r * 96 + cp) = o;
        }
        if (t1r >= 0) {
            float2 x = *(const float2*)(g_xt + t1r * 96 + cp);
            float2 o = make_float2(x.x + c2r[nt][2] + b0v, x.y + c2r[nt][3] + b1v);
            *(float2*)(g_x2 + t1r * 96 + cp) = o;
        }
    }
}

// ---------------- K4: fused LN2 + MLP via mma.sync (transposed bf16 weights) ----------------
#define ASTR 104
#define W1S  104
#define W2S  136
#define MA_OFF    0
#define MW1_OFF   26624
#define MW2_OFF   53248
#define MB1F_OFF  79360
#define MB2F_OFF  80896
#define MLG_OFF   81280
#define MLB_OFF   81664
#define MLP_SMEM  82048

__global__ void __launch_bounds__(256)
mlp_mma_kernel(const float* __restrict__ g2, const float* __restrict__ b2ln,
               const float* __restrict__ w1, const float* __restrict__ b1,
               const float* __restrict__ w2, const float* __restrict__ b2) {
    extern __shared__ __align__(16) char smem[];
    __nv_bfloat16* sA   = (__nv_bfloat16*)(smem + MA_OFF);
    __nv_bfloat16* sW1T = (__nv_bfloat16*)(smem + MW1_OFF);
    __nv_bfloat16* sW2T = (__nv_bfloat16*)(smem + MW2_OFF);
    float* sb1f = (float*)(smem + MB1F_OFF);
    float* sb2f = (float*)(smem + MB2F_OFF);
    float* slg  = (float*)(smem + MLG_OFF);
    float* slb  = (float*)(smem + MLB_OFF);

    int tid = threadIdx.x, wid = tid >> 5, lane = tid & 31;
    int g = lane >> 2, tig = lane & 3;
    long t0 = (long)blockIdx.x * 128;
    int r0 = wid * 16;

    for (int i = tid; i < HID; i += 256) sb1f[i] = b1[i];
    if (tid < 96) { sb2f[tid] = b2[tid]; slg[tid] = g2[tid]; slb[tid] = b2ln[tid]; }
    __syncthreads();

    #pragma unroll 1
    for (int it = 0; it < 16; it++) {
        int r = r0 + it;
        const float* xr = g_x2 + (t0 + r) * 96;
        float v0 = xr[lane], v1 = xr[lane + 32], v2 = xr[lane + 64];
        float mean = warp_sum(v0 + v1 + v2) * (1.0f / 96.0f);
        float var  = warp_sum(v0 * v0 + v1 * v1 + v2 * v2) * (1.0f / 96.0f) - mean * mean;
        float inv  = rsqrtf(var + 1e-5f);
        sA[r * ASTR + lane]      = __float2bfloat16_rn((v0 - mean) * inv * slg[lane]      + slb[lane]);
        sA[r * ASTR + lane + 32] = __float2bfloat16_rn((v1 - mean) * inv * slg[lane + 32] + slb[lane + 32]);
        sA[r * ASTR + lane + 64] = __float2bfloat16_rn((v2 - mean) * inv * slg[lane + 64] + slb[lane + 64]);
    }

    float c2[12][4];
    #pragma unroll
    for (int nt = 0; nt < 12; nt++) { c2[nt][0]=0.f; c2[nt][1]=0.f; c2[nt][2]=0.f; c2[nt][3]=0.f; }

    uint32_t h[16][2];

    for (int j = 0; j < 3; j++) {
        __syncthreads();
        // stage W1 chunk transposed bf16: sW1T[n][k], n<128, k<96
        for (int i = tid; i < 96 * 128; i += 256) {
            int k = i >> 7, n = i & 127;
            sW1T[n * W1S + k] = __float2bfloat16_rn(w1[(long)k * HID + j * 128 + n]);
        }
        // stage W2 chunk transposed bf16: sW2T[n][k], n<96, k<128
        for (int i = tid; i < 128 * 96; i += 256) {
            int k = i / 96, n = i - k * 96;
            sW2T[n * W2S + k] = __float2bfloat16_rn(w2[(long)(j * 128 + k) * 96 + n]);
        }
        __syncthreads();

        #pragma unroll
        for (int half = 0; half < 2; half++) {
            float c1[8][4];
            #pragma unroll
            for (int nt = 0; nt < 8; nt++) { c1[nt][0]=0.f; c1[nt][1]=0.f; c1[nt][2]=0.f; c1[nt][3]=0.f; }
            #pragma unroll
            for (int kk = 0; kk < 6; kk++) {
                int kb = kk * 16 + tig * 2;
                uint32_t a0 = *(const uint32_t*)(sA + (r0 + g) * ASTR + kb);
                uint32_t a1 = *(const uint32_t*)(sA + (r0 + g + 8) * ASTR + kb);
                uint32_t a2 = *(const uint32_t*)(sA + (r0 + g) * ASTR + kb + 8);
                uint32_t a3 = *(const uint32_t*)(sA + (r0 + g + 8) * ASTR + kb + 8);
                #pragma unroll
                for (int nt = 0; nt < 8; nt++) {
                    int n = (half * 8 + nt) * 8 + g;
                    uint32_t b0 = *(const uint32_t*)(sW1T + n * W1S + kb);
                    uint32_t b1v = *(const uint32_t*)(sW1T + n * W1S + kb + 8);
                    mma16816(c1[nt], a0, a1, a2, a3, b0, b1v);
                }
            }
            #pragma unroll
            for (int nt = 0; nt < 8; nt++) {
                int nn = (half * 8 + nt) * 8 + tig * 2;
                float bb0 = sb1f[j * 128 + nn], bb1 = sb1f[j * 128 + nn + 1];
                h[half * 8 + nt][0] = pack_bf16(gelu_fast(c1[nt][0] + bb0), gelu_fast(c1[nt][1] + bb1));
                h[half * 8 + nt][1] = pack_bf16(gelu_fast(c1[nt][2] + bb0), gelu_fast(c1[nt][3] + bb1));
            }
        }

        #pragma unroll
        for (int kk = 0; kk < 8; kk++) {
            uint32_t a0 = h[2 * kk][0], a1 = h[2 * kk][1];
            uint32_t a2 = h[2 * kk + 1][0], a3 = h[2 * kk + 1][1];
            int kb = kk * 16 + tig * 2;
            #pragma unroll
            for (int nt = 0; nt < 12; nt++) {
                int n = nt * 8 + g;
                uint32_t b0 = *(const uint32_t*)(sW2T + n * W2S + kb);
                uint32_t b1v = *(const uint32_t*)(sW2T + n * W2S + kb + 8);
                mma16816(c2[nt], a0, a1, a2, a3, b0, b1v);
            }
        }
    }

    #pragma unroll
    for (int nt = 0; nt < 12; nt++) {
        int n = nt * 8 + tig * 2;
        long ra = t0 + r0 + g;
        float bb0 = sb2f[n], bb1 = sb2f[n + 1];
        float2 x0 = *(const float2*)(g_x2 + ra * 96 + n);
        float2 x1 = *(const float2*)(g_x2 + (ra + 8) * 96 + n);
        float2 o0 = make_float2(x0.x + c2[nt][0] + bb0, x0.y + c2[nt][1] + bb1);
        float2 o1 = make_float2(x1.x + c2[nt][2] + bb0, x1.y + c2[nt][3] + bb1);
        *(float2*)(g_x3 + ra * 96 + n) = o0;
        *(float2*)(g_x3 + (ra + 8) * 96 + n) = o1;
    }
}

// ---------------- K6: conv3d 3x3x3, 96 -> 3 ----------------
__global__ void conv_kernel(const float* __restrict__ cw, const float* __restrict__ cbias,
                            float* __restrict__ out) {
    __shared__ __align__(16) float sWc[27 * 3 * 96];
    __shared__ float sCB[3];
    int tid = threadIdx.x;
    for (int i = tid; i < 27 * 3 * 96; i += 256) {
        int k = i / 288, r = i % 288, o = r / 96, c = r % 96;
        sWc[i] = cw[((long)o * 96 + c) * 27 + k];
    }
    if (tid < 3) sCB[tid] = cbias[tid];
    __syncthreads();

    long base = (long)blockIdx.x * 1024;
    int bb[4], dd[4], hh2[4], ww2[4], ss[4];
    #pragma unroll
    for (int v = 0; v < 4; v++) {
        long t = base + tid + 256 * v;
        bb[v] = (int)(t / SPD);
        int s = (int)(t % SPD);
        ss[v] = s;
        dd[v] = s / (HH * WW_);
        hh2[v] = (s / WW_) % HH;
        ww2[v] = s % WW_;
    }
    float acc[4][3];
    #pragma unroll
    for (int v = 0; v < 4; v++) { acc[v][0] = acc[v][1] = acc[v][2] = 0.f; }

    for (int kd = -1; kd <= 1; kd++)
    for (int kh = -1; kh <= 1; kh++)
    for (int kw = -1; kw <= 1; kw++) {
        int k = (kd + 1) * 9 + (kh + 1) * 3 + (kw + 1);
        const float4* src[4];
        bool ok[4];
        #pragma unroll
        for (int v = 0; v < 4; v++) {
            int d2 = dd[v] + kd, h2 = hh2[v] + kh, w2 = ww2[v] + kw;
            ok[v] = ((unsigned)d2 < DD) && ((unsigned)h2 < HH) && ((unsigned)w2 < WW_);
            long nb = (long)bb[v] * SPD + ((long)d2 * HH + h2) * WW_ + w2;
            src[v] = (const float4*)(g_x3 + nb * 96);
        }
        const float* wk = sWc + k * 288;
        #pragma unroll 4
        for (int c4 = 0; c4 < 24; c4++) {
            float4 xv[4];
            #pragma unroll
            for (int v = 0; v < 4; v++)
                xv[v] = ok[v] ? src[v][c4] : make_float4(0.f, 0.f, 0.f, 0.f);
            #pragma unroll
            for (int o = 0; o < 3; o++) {
                float4 w4 = ((const float4*)(wk + o * 96))[c4];
                #pragma unroll
                for (int v = 0; v < 4; v++)
                    acc[v][o] += xv[v].x * w4.x + xv[v].y * w4.y +
                                 xv[v].z * w4.z + xv[v].w * w4.w;
            }
        }
    }
    #pragma unroll
    for (int v = 0; v < 4; v++)
        #pragma unroll
        for (int o = 0; o < 3; o++)
            out[((long)bb[v] * 3 + o) * SPD + ss[v]] = acc[v][o] + sCB[o];
}

// ---------------- launch ----------------
extern "C" void kernel_launch(void* const* d_in, const int* in_sizes, int n_in,
                              void* d_out, int out_size) {
    const float* I_m    = (const float*)d_in[0];
    const float* I_f    = (const float*)d_in[1];
    const float* ln1q_g = (const float*)d_in[2];
    const float* ln1q_b = (const float*)d_in[3];
    const float* ln1kv_g= (const float*)d_in[4];
    const float* ln1kv_b= (const float*)d_in[5];
    const float* wq     = (const float*)d_in[6];
    const float* bq     = (const float*)d_in[7];
    const float* wkv    = (const float*)d_in[8];
    const float* bkv    = (const float*)d_in[9];
    const float* wproj  = (const float*)d_in[10];
    const float* bproj  = (const float*)d_in[11];
    const float* relb   = (const float*)d_in[12];
    const float* ln2_g  = (const float*)d_in[13];
    const float* ln2_b  = (const float*)d_in[14];
    const float* w1     = (const float*)d_in[15];
    const float* b1     = (const float*)d_in[16];
    const float* w2     = (const float*)d_in[17];
    const float* b2     = (const float*)d_in[18];
    const float* cw     = (const float*)d_in[19];
    const float* cb     = (const float*)d_in[20];
    float* out = (float*)d_out;

    const int smem_q  = 76160 + 96 * 208 + (96 + 96 + 96) * 4;    // 97,280
    const int smem_kv = 76160 + 192 * 208 + (192 + 96 + 96) * 4;  // 117,632

    cudaFuncSetAttribute(lnproj_mma_kernel<96,  true >, cudaFuncAttributeMaxDynamicSharedMemorySize, smem_q);
    cudaFuncSetAttribute(lnproj_mma_kernel<192, false>, cudaFuncAttributeMaxDynamicSharedMemorySize, smem_kv);
    cudaFuncSetAttribute(attn_mma_kernel, cudaFuncAttributeMaxDynamicSharedMemorySize, ATT_SMEM);
    cudaFuncSetAttribute(mlp_mma_kernel, cudaFuncAttributeMaxDynamicSharedMemorySize, MLP_SMEM);

    bias_kernel<<<(NT*NT + 255) / 256, 256>>>(relb);
    lnproj_mma_kernel<96,  true ><<<TOT / 128, 256, smem_q >>>(I_m, ln1q_g,  ln1q_b,  wq,  bq);
    lnproj_mma_kernel<192, false><<<TOT / 128, 256, smem_kv>>>(I_f, ln1kv_g, ln1kv_b, wkv, bkv);
    attn_mma_kernel<<<NWIN, 320, ATT_SMEM>>>(wproj, bproj);
    mlp_mma_kernel<<<TOT / 128, 256, MLP_SMEM>>>(ln2_g, ln2_b, w1, b1, w2, b2);
    conv_kernel<<<TOT / 1024, 256>>>(cw, cb, out);
}

// round 8
// speedup vs baseline: 5.5427x; 1.2938x over previous
#include <cuda_runtime.h>
#include <cuda_bf16.h>
#include <math.h>
#include <stdint.h>

#define CC 96
#define DD 40
#define HH 48
#define WW_ 40
#define BB 2
#define WIN_D 5
#define WIN_H 6
#define WIN_W 5
#define NT 150
#define NWD 8
#define NWH 8
#define NWW 8
#define NWIN 1024
#define SPD (DD*HH*WW_)   /* 76800 */
#define TOT (BB*SPD)      /* 153600 */
#define HID 384

// ---------------- scratch (device globals; no allocation) ----------------
__device__ __align__(128) float          g_xt [TOT*CC];
__device__ __align__(128) __nv_bfloat16  g_q  [NWIN*NT*CC];
__device__ __align__(128) __nv_bfloat16  g_k  [NWIN*NT*CC];
__device__ __align__(128) __nv_bfloat16  g_v  [NWIN*NT*CC];
__device__ __align__(128) float          g_x2 [TOT*CC];
__device__ __align__(128) float          g_x3 [TOT*CC];
__device__ __align__(128) float          g_bias[NT*NT];

__device__ __forceinline__ float warp_sum(float v) {
    #pragma unroll
    for (int o = 16; o > 0; o >>= 1) v += __shfl_xor_sync(0xffffffffu, v, o);
    return v;
}
__device__ __forceinline__ float gelu_fast(float x) {
    float z = 0.79788456080286535588f * (x + 0.044715f * x * x * x);
    float t = __expf(2.0f * z);
    return x * t / (t + 1.0f);
}
__device__ __forceinline__ uint32_t pack_bf16(float lo, float hi) {
    uint32_t r;
    asm("cvt.rn.bf16x2.f32 %0, %1, %2;" : "=r"(r) : "f"(hi), "f"(lo));
    return r;
}
__device__ __forceinline__ void mma16816(float c[4],
                                         uint32_t a0, uint32_t a1, uint32_t a2, uint32_t a3,
                                         uint32_t b0, uint32_t b1) {
    asm volatile(
        "mma.sync.aligned.m16n8k16.row.col.f32.bf16.bf16.f32 "
        "{%0,%1,%2,%3}, {%4,%5,%6,%7}, {%8,%9}, {%0,%1,%2,%3};"
        : "+f"(c[0]), "+f"(c[1]), "+f"(c[2]), "+f"(c[3])
        : "r"(a0), "r"(a1), "r"(a2), "r"(a3), "r"(b0), "r"(b1));
}
__device__ __forceinline__ uint32_t smem_u32(const void* p) {
    uint32_t a;
    asm("{ .reg .u64 t; cvta.to.shared.u64 t, %1; cvt.u32.u64 %0, t; }" : "=r"(a) : "l"(p));
    return a;
}
__device__ __forceinline__ void cp16(uint32_t dst, const void* src) {
    asm volatile("cp.async.cg.shared.global [%0], [%1], 16;" :: "r"(dst), "l"(src));
}

// ---------------- K0: relative position bias table ----------------
__global__ void bias_kernel(const float* __restrict__ rel_bias) {
    int i = blockIdx.x * blockDim.x + threadIdx.x;
    if (i >= NT * NT) return;
    int n = i / NT, m = i % NT;
    int nd = n / 30, nh = (n / 5) % 6, nw = n % 5;
    int md = m / 30, mh = (m / 5) % 6, mw = m % 5;
    int idx = (nd - md + 4) * 99 + (nh - mh + 5) * 9 + (nw - mw + 4);
    g_bias[i] = rel_bias[idx];
}

// ---------------- K1/K2: transpose + LN + projection via mma.sync ----------------
// 256 threads, 128 tokens/CTA. W staged per 96-col half -> smem < 98KB -> 2 CTAs/SM.
#define LTS 129
#define LASTR 104
#define LTILE_OFF 0
#define LA_OFF    49536
#define LWT_OFF   76160
#define LB_OFF    96128
template<int COUT, bool ISQ>
__global__ void __launch_bounds__(256, 2)
lnproj_mma_kernel(const float* __restrict__ in,
                  const float* __restrict__ gamma,
                  const float* __restrict__ beta,
                  const float* __restrict__ wmat,   // (96, COUT)
                  const float* __restrict__ bvec) {
    extern __shared__ __align__(16) char smem[];
    float* tile = (float*)(smem + LTILE_OFF);
    __nv_bfloat16* sA  = (__nv_bfloat16*)(smem + LA_OFF);
    __nv_bfloat16* sWT = (__nv_bfloat16*)(smem + LWT_OFF);   // 96 x 104 bf16 (one half)
    float* sB  = (float*)(smem + LB_OFF);
    float* sG  = sB + COUT;
    float* sBt = sG + 96;

    int tid = threadIdx.x, wid = tid >> 5, lane = tid & 31;
    int g = lane >> 2, tig = lane & 3;
    long t0 = (long)blockIdx.x * 128;
    int b  = (int)(t0 / SPD);
    int s0 = (int)(t0 % SPD);
    int r0 = wid * 16;

    // stage input tile (channel-major, coalesced)
    const float* inb = in + (long)b * 96 * SPD + s0;
    for (int i = tid; i < 96 * 128; i += 256) {
        int c = i >> 7, t = i & 127;
        tile[c * LTS + t] = inb[(long)c * SPD + t];
    }
    for (int i = tid; i < COUT; i += 256) sB[i] = bvec[i];
    if (tid < 96) { sG[tid] = gamma[tid]; sBt[tid] = beta[tid]; }
    __syncthreads();

    if (ISQ) {  // shortcut transpose to global (fp32)
        for (int i = tid; i < 96 * 128; i += 256) {
            int c = i % 96, t = i / 96;
            g_xt[(t0 + t) * 96 + c] = tile[c * LTS + t];
        }
    }

    // LN -> sA bf16 (own-warp rows; no block sync needed for A reads)
    #pragma unroll 1
    for (int it = 0; it < 16; it++) {
        int t = r0 + it;
        float v0 = tile[lane * LTS + t];
        float v1 = tile[(lane + 32) * LTS + t];
        float v2 = tile[(lane + 64) * LTS + t];
        float mean = warp_sum(v0 + v1 + v2) * (1.0f / 96.0f);
        float var  = warp_sum(v0 * v0 + v1 * v1 + v2 * v2) * (1.0f / 96.0f) - mean * mean;
        float inv  = rsqrtf(var + 1e-5f);
        sA[t * LASTR + lane]      = __float2bfloat16_rn((v0 - mean) * inv * sG[lane]      + sBt[lane]);
        sA[t * LASTR + lane + 32] = __float2bfloat16_rn((v1 - mean) * inv * sG[lane + 32] + sBt[lane + 32]);
        sA[t * LASTR + lane + 64] = __float2bfloat16_rn((v2 - mean) * inv * sG[lane + 64] + sBt[lane + 64]);
    }

    // window addresses for this thread's two rows
    long base0, base1;
    {
        long bases[2];
        int rows[2] = { r0 + g, r0 + g + 8 };
        #pragma unroll
        for (int rr = 0; rr < 2; rr++) {
            long t = t0 + rows[rr];
            int s = (int)(t % SPD);
            int d = s / (HH * WW_), h = (s / WW_) % HH, w = s % WW_;
            int wi = ((b * NWD + d / WIN_D) * NWH + h / WIN_H) * NWW + w / WIN_W;
            int n  = (d % WIN_D) * 30 + (h % WIN_H) * 5 + (w % WIN_W);
            bases[rr] = ((long)wi * NT + n) * 96;
        }
        base0 = bases[0]; base1 = bases[1];
    }

    const int NHALF = COUT / 96;
    #pragma unroll
    for (int half = 0; half < NHALF; half++) {
        __syncthreads();   // prior-half sWT reads done (and tile/LN ordering on half 0)
        for (int i = tid; i < 96 * 96; i += 256) {
            int k = i / 96, n = i - k * 96;
            sWT[n * LASTR + k] = __float2bfloat16_rn(wmat[(long)k * COUT + half * 96 + n]);
        }
        __syncthreads();

        float c[12][4];
        #pragma unroll
        for (int nt = 0; nt < 12; nt++) { c[nt][0]=0.f; c[nt][1]=0.f; c[nt][2]=0.f; c[nt][3]=0.f; }
        #pragma unroll
        for (int kk = 0; kk < 6; kk++) {
            int kb = kk * 16 + tig * 2;
            uint32_t a0 = *(const uint32_t*)(sA + (r0 + g)     * LASTR + kb);
            uint32_t a1 = *(const uint32_t*)(sA + (r0 + g + 8) * LASTR + kb);
            uint32_t a2 = *(const uint32_t*)(sA + (r0 + g)     * LASTR + kb + 8);
            uint32_t a3 = *(const uint32_t*)(sA + (r0 + g + 8) * LASTR + kb + 8);
            #pragma unroll
            for (int nt = 0; nt < 12; nt++) {
                int n = nt * 8 + g;
                uint32_t b0 = *(const uint32_t*)(sWT + n * LASTR + kb);
                uint32_t b1 = *(const uint32_t*)(sWT + n * LASTR + kb + 8);
                mma16816(c[nt], a0, a1, a2, a3, b0, b1);
            }
        }
        __nv_bfloat16* dst = ISQ ? g_q : (half == 0 ? g_k : g_v);
        #pragma unroll
        for (int nt = 0; nt < 12; nt++) {
            int col = nt * 8 + tig * 2;
            float b0v = sB[half * 96 + col], b1v = sB[half * 96 + col + 1];
            *(uint32_t*)(dst + base0 + col) = pack_bf16(c[nt][0] + b0v, c[nt][1] + b1v);
            *(uint32_t*)(dst + base1 + col) = pack_bf16(c[nt][2] + b0v, c[nt][3] + b1v);
        }
    }
}

// ---------------- K3: per-window attention via mma.sync (bf16) ----------------
// 320 threads. cp.async staging, V row-major, wproj staged upfront: ONE __syncthreads total.
#define AQS 104
#define ASQ_OFF 0
#define ASK_OFF 33280
#define ASV_OFF 64896
#define ASW_OFF 98176
#define ASBP_OFF 118144
#define ATT_SMEM 118528

__global__ void __launch_bounds__(320, 1)
attn_mma_kernel(const float* __restrict__ wproj, const float* __restrict__ bproj) {
    extern __shared__ __align__(16) char smem[];
    __nv_bfloat16* sQ  = (__nv_bfloat16*)(smem + ASQ_OFF);   // 160 x 104
    __nv_bfloat16* sK  = (__nv_bfloat16*)(smem + ASK_OFF);   // 152 x 104
    __nv_bfloat16* sV  = (__nv_bfloat16*)(smem + ASV_OFF);   // 160 x 104 (row-major)
    __nv_bfloat16* sWp = (__nv_bfloat16*)(smem + ASW_OFF);   // 96 x 104 (wproj^T)
    float* sBp = (float*)(smem + ASBP_OFF);

    int tid = threadIdx.x, wid = tid >> 5, lane = tid & 31;
    int g = lane >> 2, tig = lane & 3;
    int wi = blockIdx.x;
    int r0 = wid * 16;
    const float scale = 0.102062072615965696f;

    const char* gq = (const char*)(g_q + (long)wi * NT * 96);
    const char* gk = (const char*)(g_k + (long)wi * NT * 96);
    const char* gv = (const char*)(g_v + (long)wi * NT * 96);

    uint32_t sb = smem_u32(smem);
    // cp.async staging: 150 rows x 12 x 16B each for Q, K, V
    for (int i = tid; i < 150 * 12; i += 320) {
        int r = i / 12, c = i % 12;
        cp16(sb + ASQ_OFF + r * 208 + c * 16, gq + r * 192 + c * 16);
        cp16(sb + ASK_OFF + r * 208 + c * 16, gk + r * 192 + c * 16);
        cp16(sb + ASV_OFF + r * 208 + c * 16, gv + r * 192 + c * 16);
    }
    asm volatile("cp.async.commit_group;");

    // wproj^T + bias (regular path, overlaps the async copies)
    for (int i = tid; i < 96 * 96; i += 320) {
        int r = i / 96, cp = i - r * 96;
        sWp[cp * AQS + r] = __float2bfloat16_rn(wproj[i]);
    }
    if (tid < 96) sBp[tid] = bproj[tid];
    // zero pad rows (Q 150-159, K 150-151, V 150-159), u32 granularity
    {
        uint32_t* zq = (uint32_t*)(sQ + 150 * AQS);
        uint32_t* zk = (uint32_t*)(sK + 150 * AQS);
        uint32_t* zv = (uint32_t*)(sV + 150 * AQS);
        for (int i = tid; i < 520; i += 320) { zq[i] = 0u; zv[i] = 0u; }
        for (int i = tid; i < 104; i += 320) zk[i] = 0u;
    }
    asm volatile("cp.async.wait_group 0;");
    __syncthreads();   // the only block sync

    // ---- GEMM1: S stripe (16 x 152) in registers ----
    float cs[19][4];
    #pragma unroll
    for (int nt = 0; nt < 19; nt++) { cs[nt][0]=0.f; cs[nt][1]=0.f; cs[nt][2]=0.f; cs[nt][3]=0.f; }
    #pragma unroll
    for (int kk = 0; kk < 6; kk++) {
        int kb = kk * 16 + tig * 2;
        uint32_t a0 = *(const uint32_t*)(sQ + (r0 + g)     * AQS + kb);
        uint32_t a1 = *(const uint32_t*)(sQ + (r0 + g + 8) * AQS + kb);
        uint32_t a2 = *(const uint32_t*)(sQ + (r0 + g)     * AQS + kb + 8);
        uint32_t a3 = *(const uint32_t*)(sQ + (r0 + g + 8) * AQS + kb + 8);
        #pragma unroll
        for (int nt = 0; nt < 19; nt++) {
            int m = nt * 8 + g;
            uint32_t b0 = *(const uint32_t*)(sK + m * AQS + kb);
            uint32_t b1 = *(const uint32_t*)(sK + m * AQS + kb + 8);
            mma16816(cs[nt], a0, a1, a2, a3, b0, b1);
        }
    }

    // ---- softmax in registers ----
    int n0r = r0 + g, n1r = r0 + g + 8;
    float mx0 = -1e30f, mx1 = -1e30f;
    #pragma unroll
    for (int nt = 0; nt < 19; nt++) {
        int m = nt * 8 + tig * 2;
        if (m < NT) {
            if (n0r < NT) {
                float2 bv = *(const float2*)(g_bias + n0r * NT + m);
                cs[nt][0] = cs[nt][0] * scale + bv.x;
                cs[nt][1] = cs[nt][1] * scale + bv.y;
            } else { cs[nt][0] = 0.f; cs[nt][1] = 0.f; }
            if (n1r < NT) {
                float2 bv = *(const float2*)(g_bias + n1r * NT + m);
                cs[nt][2] = cs[nt][2] * scale + bv.x;
                cs[nt][3] = cs[nt][3] * scale + bv.y;
            } else { cs[nt][2] = 0.f; cs[nt][3] = 0.f; }
            mx0 = fmaxf(mx0, fmaxf(cs[nt][0], cs[nt][1]));
            mx1 = fmaxf(mx1, fmaxf(cs[nt][2], cs[nt][3]));
        } else {
            cs[nt][0] = -1e30f; cs[nt][1] = -1e30f;
            cs[nt][2] = -1e30f; cs[nt][3] = -1e30f;
        }
    }
    mx0 = fmaxf(mx0, __shfl_xor_sync(0xffffffffu, mx0, 1));
    mx0 = fmaxf(mx0, __shfl_xor_sync(0xffffffffu, mx0, 2));
    mx1 = fmaxf(mx1, __shfl_xor_sync(0xffffffffu, mx1, 1));
    mx1 = fmaxf(mx1, __shfl_xor_sync(0xffffffffu, mx1, 2));
    float s0 = 0.f, s1 = 0.f;
    #pragma unroll
    for (int nt = 0; nt < 19; nt++) {
        cs[nt][0] = __expf(cs[nt][0] - mx0);
        cs[nt][1] = __expf(cs[nt][1] - mx0);
        cs[nt][2] = __expf(cs[nt][2] - mx1);
        cs[nt][3] = __expf(cs[nt][3] - mx1);
        s0 += cs[nt][0] + cs[nt][1];
        s1 += cs[nt][2] + cs[nt][3];
    }
    s0 += __shfl_xor_sync(0xffffffffu, s0, 1);
    s0 += __shfl_xor_sync(0xffffffffu, s0, 2);
    s1 += __shfl_xor_sync(0xffffffffu, s1, 1);
    s1 += __shfl_xor_sync(0xffffffffu, s1, 2);
    float inv0 = 1.0f / s0, inv1 = 1.0f / s1;

    uint32_t pa[10][4];
    #pragma unroll
    for (int kt = 0; kt < 10; kt++) {
        int e = 2 * kt, o = 2 * kt + 1;
        pa[kt][0] = pack_bf16(cs[e][0] * inv0, cs[e][1] * inv0);
        pa[kt][1] = pack_bf16(cs[e][2] * inv1, cs[e][3] * inv1);
        if (o < 19) {
            pa[kt][2] = pack_bf16(cs[o][0] * inv0, cs[o][1] * inv0);
            pa[kt][3] = pack_bf16(cs[o][2] * inv1, cs[o][3] * inv1);
        } else { pa[kt][2] = 0u; pa[kt][3] = 0u; }
    }

    // ---- GEMM2: O = P @ V (V row-major; B-frag = 2x LDS.16 + pack) ----
    float co[12][4];
    #pragma unroll
    for (int nt = 0; nt < 12; nt++) { co[nt][0]=0.f; co[nt][1]=0.f; co[nt][2]=0.f; co[nt][3]=0.f; }
    #pragma unroll
    for (int kt = 0; kt < 10; kt++) {
        int kb = kt * 16 + tig * 2;
        const uint16_t* v0p = (const uint16_t*)(sV + (kb + 0) * AQS);
        const uint16_t* v1p = (const uint16_t*)(sV + (kb + 1) * AQS);
        const uint16_t* v8p = (const uint16_t*)(sV + (kb + 8) * AQS);
        const uint16_t* v9p = (const uint16_t*)(sV + (kb + 9) * AQS);
        #pragma unroll
        for (int nt = 0; nt < 12; nt++) {
            int n = nt * 8 + g;
            uint32_t b0 = (uint32_t)v0p[n] | ((uint32_t)v1p[n] << 16);
            uint32_t b1 = (uint32_t)v8p[n] | ((uint32_t)v9p[n] << 16);
            mma16816(co[nt], pa[kt][0], pa[kt][1], pa[kt][2], pa[kt][3], b0, b1);
        }
    }

    uint32_t oa[6][4];
    #pragma unroll
    for (int kt = 0; kt < 6; kt++) {
        oa[kt][0] = pack_bf16(co[2*kt][0],   co[2*kt][1]);
        oa[kt][1] = pack_bf16(co[2*kt][2],   co[2*kt][3]);
        oa[kt][2] = pack_bf16(co[2*kt+1][0], co[2*kt+1][1]);
        oa[kt][3] = pack_bf16(co[2*kt+1][2], co[2*kt+1][3]);
    }
    float c2r[12][4];
    #pragma unroll
    for (int nt = 0; nt < 12; nt++) { c2r[nt][0]=0.f; c2r[nt][1]=0.f; c2r[nt][2]=0.f; c2r[nt][3]=0.f; }
    #pragma unroll
    for (int kt = 0; kt < 6; kt++) {
        int kb = kt * 16 + tig * 2;
        #pragma unroll
        for (int nt = 0; nt < 12; nt++) {
            int cp = nt * 8 + g;
            uint32_t b0 = *(const uint32_t*)(sWp + cp * AQS + kb);
            uint32_t b1 = *(const uint32_t*)(sWp + cp * AQS + kb + 8);
            mma16816(c2r[nt], oa[kt][0], oa[kt][1], oa[kt][2], oa[kt][3], b0, b1);
        }
    }

    int iww = wi & 7, iwh = (wi >> 3) & 7, iwd = (wi >> 6) & 7, b = wi >> 9;
    long t0r = -1, t1r = -1;
    if (n0r < NT) {
        int zd = n0r / 30, zh = (n0r / 5) % 6, zw = n0r % 5;
        int d = iwd * WIN_D + zd, h = iwh * WIN_H + zh, w = iww * WIN_W + zw;
        t0r = (long)b * SPD + ((long)d * HH + h) * WW_ + w;
    }
    if (n1r < NT) {
        int zd = n1r / 30, zh = (n1r / 5) % 6, zw = n1r % 5;
        int d = iwd * WIN_D + zd, h = iwh * WIN_H + zh, w = iww * WIN_W + zw;
        t1r = (long)b * SPD + ((long)d * HH + h) * WW_ + w;
    }
    #pragma unroll
    for (int nt = 0; nt < 12; nt++) {
        int cp = nt * 8 + tig * 2;
        float b0v = sBp[cp], b1v = sBp[cp + 1];
        if (t0r >= 0) {
            float2 x = *(const float2*)(g_xt + t0r * 96 + cp);
            float2 o = make_float2(x.x + c2r[nt][0] + b0v, x.y + c2r[nt][1] + b1v);
            *(float2*)(g_x2 + t0r * 96 + cp) = o;
        }
        if (t1r >= 0) {
            float2 x = *(const float2*)(g_xt + t1r * 96 + cp);
            float2 o = make_float2(x.x + c2r[nt][2] + b0v, x.y + c2r[nt][3] + b1v);
            *(float2*)(g_x2 + t1r * 96 + cp) = o;
        }
    }
}

// ---------------- K4: fused LN2 + MLP via mma.sync (transposed bf16 weights) ----------------
#define ASTR 104
#define W1S  104
#define W2S  136
#define MA_OFF    0
#define MW1_OFF   26624
#define MW2_OFF   53248
#define MB1F_OFF  79360
#define MB2F_OFF  80896
#define MLG_OFF   81280
#define MLB_OFF   81664
#define MLP_SMEM  82048

__global__ void __launch_bounds__(256, 2)
mlp_mma_kernel(const float* __restrict__ g2, const float* __restrict__ b2ln,
               const float* __restrict__ w1, const float* __restrict__ b1,
               const float* __restrict__ w2, const float* __restrict__ b2) {
    extern __shared__ __align__(16) char smem[];
    __nv_bfloat16* sA   = (__nv_bfloat16*)(smem + MA_OFF);
    __nv_bfloat16* sW1T = (__nv_bfloat16*)(smem + MW1_OFF);
    __nv_bfloat16* sW2T = (__nv_bfloat16*)(smem + MW2_OFF);
    float* sb1f = (float*)(smem + MB1F_OFF);
    float* sb2f = (float*)(smem + MB2F_OFF);
    float* slg  = (float*)(smem + MLG_OFF);
    float* slb  = (float*)(smem + MLB_OFF);

    int tid = threadIdx.x, wid = tid >> 5, lane = tid & 31;
    int g = lane >> 2, tig = lane & 3;
    long t0 = (long)blockIdx.x * 128;
    int r0 = wid * 16;

    for (int i = tid; i < HID; i += 256) sb1f[i] = b1[i];
    if (tid < 96) { sb2f[tid] = b2[tid]; slg[tid] = g2[tid]; slb[tid] = b2ln[tid]; }
    __syncthreads();

    #pragma unroll 1
    for (int it = 0; it < 16; it++) {
        int r = r0 + it;
        const float* xr = g_x2 + (t0 + r) * 96;
        float v0 = xr[lane], v1 = xr[lane + 32], v2 = xr[lane + 64];
        float mean = warp_sum(v0 + v1 + v2) * (1.0f / 96.0f);
        float var  = warp_sum(v0 * v0 + v1 * v1 + v2 * v2) * (1.0f / 96.0f) - mean * mean;
        float inv  = rsqrtf(var + 1e-5f);
        sA[r * ASTR + lane]      = __float2bfloat16_rn((v0 - mean) * inv * slg[lane]      + slb[lane]);
        sA[r * ASTR + lane + 32] = __float2bfloat16_rn((v1 - mean) * inv * slg[lane + 32] + slb[lane + 32]);
        sA[r * ASTR + lane + 64] = __float2bfloat16_rn((v2 - mean) * inv * slg[lane + 64] + slb[lane + 64]);
    }

    float c2[12][4];
    #pragma unroll
    for (int nt = 0; nt < 12; nt++) { c2[nt][0]=0.f; c2[nt][1]=0.f; c2[nt][2]=0.f; c2[nt][3]=0.f; }

    uint32_t h[16][2];

    for (int j = 0; j < 3; j++) {
        __syncthreads();
        for (int i = tid; i < 96 * 128; i += 256) {
            int k = i >> 7, n = i & 127;
            sW1T[n * W1S + k] = __float2bfloat16_rn(w1[(long)k * HID + j * 128 + n]);
        }
        for (int i = tid; i < 128 * 96; i += 256) {
            int k = i / 96, n = i - k * 96;
            sW2T[n * W2S + k] = __float2bfloat16_rn(w2[(long)(j * 128 + k) * 96 + n]);
        }
        __syncthreads();

        #pragma unroll
        for (int half = 0; half < 2; half++) {
            float c1[8][4];
            #pragma unroll
            for (int nt = 0; nt < 8; nt++) { c1[nt][0]=0.f; c1[nt][1]=0.f; c1[nt][2]=0.f; c1[nt][3]=0.f; }
            #pragma unroll
            for (int kk = 0; kk < 6; kk++) {
                int kb = kk * 16 + tig * 2;
                uint32_t a0 = *(const uint32_t*)(sA + (r0 + g) * ASTR + kb);
                uint32_t a1 = *(const uint32_t*)(sA + (r0 + g + 8) * ASTR + kb);
                uint32_t a2 = *(const uint32_t*)(sA + (r0 + g) * ASTR + kb + 8);
                uint32_t a3 = *(const uint32_t*)(sA + (r0 + g + 8) * ASTR + kb + 8);
                #pragma unroll
                for (int nt = 0; nt < 8; nt++) {
                    int n = (half * 8 + nt) * 8 + g;
                    uint32_t b0 = *(const uint32_t*)(sW1T + n * W1S + kb);
                    uint32_t b1v = *(const uint32_t*)(sW1T + n * W1S + kb + 8);
                    mma16816(c1[nt], a0, a1, a2, a3, b0, b1v);
                }
            }
            #pragma unroll
            for (int nt = 0; nt < 8; nt++) {
                int nn = (half * 8 + nt) * 8 + tig * 2;
                float bb0 = sb1f[j * 128 + nn], bb1 = sb1f[j * 128 + nn + 1];
                h[half * 8 + nt][0] = pack_bf16(gelu_fast(c1[nt][0] + bb0), gelu_fast(c1[nt][1] + bb1));
                h[half * 8 + nt][1] = pack_bf16(gelu_fast(c1[nt][2] + bb0), gelu_fast(c1[nt][3] + bb1));
            }
        }

        #pragma unroll
        for (int kk = 0; kk < 8; kk++) {
            uint32_t a0 = h[2 * kk][0], a1 = h[2 * kk][1];
            uint32_t a2 = h[2 * kk + 1][0], a3 = h[2 * kk + 1][1];
            int kb = kk * 16 + tig * 2;
            #pragma unroll
            for (int nt = 0; nt < 12; nt++) {
                int n = nt * 8 + g;
                uint32_t b0 = *(const uint32_t*)(sW2T + n * W2S + kb);
                uint32_t b1v = *(const uint32_t*)(sW2T + n * W2S + kb + 8);
                mma16816(c2[nt], a0, a1, a2, a3, b0, b1v);
            }
        }
    }

    #pragma unroll
    for (int nt = 0; nt < 12; nt++) {
        int n = nt * 8 + tig * 2;
        long ra = t0 + r0 + g;
        float bb0 = sb2f[n], bb1 = sb2f[n + 1];
        float2 x0 = *(const float2*)(g_x2 + ra * 96 + n);
        float2 x1 = *(const float2*)(g_x2 + (ra + 8) * 96 + n);
        float2 o0 = make_float2(x0.x + c2[nt][0] + bb0, x0.y + c2[nt][1] + bb1);
        float2 o1 = make_float2(x1.x + c2[nt][2] + bb0, x1.y + c2[nt][3] + bb1);
        *(float2*)(g_x3 + ra * 96 + n) = o0;
        *(float2*)(g_x3 + (ra + 8) * 96 + n) = o1;
    }
}

// ---------------- K6: conv3d 3x3x3, 96 -> 3 (2 voxels/thread, grid 300) ----------------
__global__ void conv_kernel(const float* __restrict__ cw, const float* __restrict__ cbias,
                            float* __restrict__ out) {
    __shared__ __align__(16) float sWc[27 * 3 * 96];
    __shared__ float sCB[3];
    int tid = threadIdx.x;
    for (int i = tid; i < 27 * 3 * 96; i += 256) {
        int k = i / 288, r = i % 288, o = r / 96, c = r % 96;
        sWc[i] = cw[((long)o * 96 + c) * 27 + k];
    }
    if (tid < 3) sCB[tid] = cbias[tid];
    __syncthreads();

    long base = (long)blockIdx.x * 512;
    int bb[2], dd[2], hh2[2], ww2[2], ss[2];
    #pragma unroll
    for (int v = 0; v < 2; v++) {
        long t = base + tid + 256 * v;
        bb[v] = (int)(t / SPD);
        int s = (int)(t % SPD);
        ss[v] = s;
        dd[v] = s / (HH * WW_);
        hh2[v] = (s / WW_) % HH;
        ww2[v] = s % WW_;
    }
    float acc[2][3];
    #pragma unroll
    for (int v = 0; v < 2; v++) { acc[v][0] = acc[v][1] = acc[v][2] = 0.f; }

    for (int kd = -1; kd <= 1; kd++)
    for (int kh = -1; kh <= 1; kh++)
    for (int kw = -1; kw <= 1; kw++) {
        int k = (kd + 1) * 9 + (kh + 1) * 3 + (kw + 1);
        const float4* src[2];
        bool ok[2];
        #pragma unroll
        for (int v = 0; v < 2; v++) {
            int d2 = dd[v] + kd, h2 = hh2[v] + kh, w2 = ww2[v] + kw;
            ok[v] = ((unsigned)d2 < DD) && ((unsigned)h2 < HH) && ((unsigned)w2 < WW_);
            long nb = (long)bb[v] * SPD + ((long)d2 * HH + h2) * WW_ + w2;
            src[v] = (const float4*)(g_x3 + nb * 96);
        }
        const float* wk = sWc + k * 288;
        #pragma unroll 4
        for (int c4 = 0; c4 < 24; c4++) {
            float4 xv[2];
            #pragma unroll
            for (int v = 0; v < 2; v++)
                xv[v] = ok[v] ? src[v][c4] : make_float4(0.f, 0.f, 0.f, 0.f);
            #pragma unroll
            for (int o = 0; o < 3; o++) {
                float4 w4 = ((const float4*)(wk + o * 96))[c4];
                #pragma unroll
                for (int v = 0; v < 2; v++)
                    acc[v][o] += xv[v].x * w4.x + xv[v].y * w4.y +
                                 xv[v].z * w4.z + xv[v].w * w4.w;
            }
        }
    }
    #pragma unroll
    for (int v = 0; v < 2; v++)
        #pragma unroll
        for (int o = 0; o < 3; o++)
            out[((long)bb[v] * 3 + o) * SPD + ss[v]] = acc[v][o] + sCB[o];
}

// ---------------- launch ----------------
extern "C" void kernel_launch(void* const* d_in, const int* in_sizes, int n_in,
                              void* d_out, int out_size) {
    const float* I_m    = (const float*)d_in[0];
    const float* I_f    = (const float*)d_in[1];
    const float* ln1q_g = (const float*)d_in[2];
    const float* ln1q_b = (const float*)d_in[3];
    const float* ln1kv_g= (const float*)d_in[4];
    const float* ln1kv_b= (const float*)d_in[5];
    const float* wq     = (const float*)d_in[6];
    const float* bq     = (const float*)d_in[7];
    const float* wkv    = (const float*)d_in[8];
    const float* bkv    = (const float*)d_in[9];
    const float* wproj  = (const float*)d_in[10];
    const float* bproj  = (const float*)d_in[11];
    const float* relb   = (const float*)d_in[12];
    const float* ln2_g  = (const float*)d_in[13];
    const float* ln2_b  = (const float*)d_in[14];
    const float* w1     = (const float*)d_in[15];
    const float* b1     = (const float*)d_in[16];
    const float* w2     = (const float*)d_in[17];
    const float* b2     = (const float*)d_in[18];
    const float* cw     = (const float*)d_in[19];
    const float* cb     = (const float*)d_in[20];
    float* out = (float*)d_out;

    const int smem_q  = LB_OFF + 96 * 4 + 768;    // 97,280
    const int smem_kv = LB_OFF + 192 * 4 + 768;   // 97,664

    cudaFuncSetAttribute(lnproj_mma_kernel<96,  true >, cudaFuncAttributeMaxDynamicSharedMemorySize, smem_q);
    cudaFuncSetAttribute(lnproj_mma_kernel<192, false>, cudaFuncAttributeMaxDynamicSharedMemorySize, smem_kv);
    cudaFuncSetAttribute(attn_mma_kernel, cudaFuncAttributeMaxDynamicSharedMemorySize, ATT_SMEM);
    cudaFuncSetAttribute(mlp_mma_kernel, cudaFuncAttributeMaxDynamicSharedMemorySize, MLP_SMEM);

    bias_kernel<<<(NT*NT + 255) / 256, 256>>>(relb);
    lnproj_mma_kernel<96,  true ><<<TOT / 128, 256, smem_q >>>(I_m, ln1q_g,  ln1q_b,  wq,  bq);
    lnproj_mma_kernel<192, false><<<TOT / 128, 256, smem_kv>>>(I_f, ln1kv_g, ln1kv_b, wkv, bkv);
    attn_mma_kernel<<<NWIN, 320, ATT_SMEM>>>(wproj, bproj);
    mlp_mma_kernel<<<TOT / 128, 256, MLP_SMEM>>>(ln2_g, ln2_b, w1, b1, w2, b2);
    conv_kernel<<<TOT / 512, 256>>>(cw, cb, out);
}

// round 9
// speedup vs baseline: 6.1451x; 1.1087x over previous
#include <cuda_runtime.h>
#include <cuda_bf16.h>
#include <math.h>
#include <stdint.h>

#define CC 96
#define DD 40
#define HH 48
#define WW_ 40
#define BB 2
#define WIN_D 5
#define WIN_H 6
#define WIN_W 5
#define NT 150
#define NWD 8
#define NWH 8
#define NWW 8
#define NWIN 1024
#define SPD (DD*HH*WW_)   /* 76800 */
#define TOT (BB*SPD)      /* 153600 */
#define HID 384

// ---------------- scratch (device globals; no allocation) ----------------
__device__ __align__(128) float          g_xt [TOT*CC];
__device__ __align__(128) __nv_bfloat16  g_q  [NWIN*NT*CC];
__device__ __align__(128) __nv_bfloat16  g_k  [NWIN*NT*CC];
__device__ __align__(128) __nv_bfloat16  g_v  [NWIN*NT*CC];
__device__ __align__(128) float          g_x2 [TOT*CC];
__device__ __align__(128) float          g_x3 [TOT*CC];
__device__ __align__(128) float          g_bias[NT*NT];
// pre-converted transposed bf16 weights
__device__ __align__(128) __nv_bfloat16  g_wqT[96*96];
__device__ __align__(128) __nv_bfloat16  g_wkT[96*96];
__device__ __align__(128) __nv_bfloat16  g_wvT[96*96];
__device__ __align__(128) __nv_bfloat16  g_wpT[96*96];
__device__ __align__(128) __nv_bfloat16  g_w1T[HID*96];   // [n<384][k<96]
__device__ __align__(128) __nv_bfloat16  g_w2T[96*HID];   // [n<96][k<384]

__device__ __forceinline__ float warp_sum(float v) {
    #pragma unroll
    for (int o = 16; o > 0; o >>= 1) v += __shfl_xor_sync(0xffffffffu, v, o);
    return v;
}
__device__ __forceinline__ float gelu_fast(float x) {
    float z = 0.79788456080286535588f * (x + 0.044715f * x * x * x);
    float t = __expf(2.0f * z);
    return x * t / (t + 1.0f);
}
__device__ __forceinline__ uint32_t pack_bf16(float lo, float hi) {
    uint32_t r;
    asm("cvt.rn.bf16x2.f32 %0, %1, %2;" : "=r"(r) : "f"(hi), "f"(lo));
    return r;
}
__device__ __forceinline__ void mma16816(float c[4],
                                         uint32_t a0, uint32_t a1, uint32_t a2, uint32_t a3,
                                         uint32_t b0, uint32_t b1) {
    asm volatile(
        "mma.sync.aligned.m16n8k16.row.col.f32.bf16.bf16.f32 "
        "{%0,%1,%2,%3}, {%4,%5,%6,%7}, {%8,%9}, {%0,%1,%2,%3};"
        : "+f"(c[0]), "+f"(c[1]), "+f"(c[2]), "+f"(c[3])
        : "r"(a0), "r"(a1), "r"(a2), "r"(a3), "r"(b0), "r"(b1));
}
__device__ __forceinline__ uint32_t smem_u32(const void* p) {
    uint32_t a;
    asm("{ .reg .u64 t; cvta.to.shared.u64 t, %1; cvt.u32.u64 %0, t; }" : "=r"(a) : "l"(p));
    return a;
}
__device__ __forceinline__ void cp16(uint32_t dst, const void* src) {
    asm volatile("cp.async.cg.shared.global [%0], [%1], 16;" :: "r"(dst), "l"(src));
}
#define CP_COMMIT() asm volatile("cp.async.commit_group;")
#define CP_WAIT0()  asm volatile("cp.async.wait_group 0;")

// ---------------- K0a: relative position bias table ----------------
__global__ void bias_kernel(const float* __restrict__ rel_bias) {
    int i = blockIdx.x * blockDim.x + threadIdx.x;
    if (i >= NT * NT) return;
    int n = i / NT, m = i % NT;
    int nd = n / 30, nh = (n / 5) % 6, nw = n % 5;
    int md = m / 30, mh = (m / 5) % 6, mw = m % 5;
    int idx = (nd - md + 4) * 99 + (nh - mh + 5) * 9 + (nw - mw + 4);
    g_bias[i] = rel_bias[idx];
}

// ---------------- K0b: pre-convert weights to transposed bf16 ----------------
__global__ void prep_w_kernel(const float* __restrict__ wq, const float* __restrict__ wkv,
                              const float* __restrict__ wproj,
                              const float* __restrict__ w1, const float* __restrict__ w2) {
    int i = blockIdx.x * 256 + threadIdx.x;
    if (i < 9216) {
        int n = i / 96, k = i % 96;
        g_wqT[i] = __float2bfloat16_rn(wq[k * 96 + n]);
        g_wpT[i] = __float2bfloat16_rn(wproj[k * 96 + n]);
        g_wkT[i] = __float2bfloat16_rn(wkv[k * 192 + n]);
        g_wvT[i] = __float2bfloat16_rn(wkv[k * 192 + 96 + n]);
    }
    if (i < 36864) {
        int n = i / 96, k = i % 96;      // w1T: [n<384][k<96]
        g_w1T[i] = __float2bfloat16_rn(w1[(long)k * HID + n]);
        int n2 = i / 384, k2 = i % 384;  // w2T: [n<96][k<384]
        g_w2T[i] = __float2bfloat16_rn(w2[(long)k2 * 96 + n2]);
    }
}

// ---------------- K1/K2: transpose + LN + projection via mma.sync ----------------
#define LTS 129
#define LASTR 104
#define LTILE_OFF 0
#define LA_OFF    49536
#define LWT_OFF   76160
#define LB_OFF    96128
template<int COUT, bool ISQ>
__global__ void __launch_bounds__(256, 2)
lnproj_mma_kernel(const float* __restrict__ in,
                  const float* __restrict__ gamma,
                  const float* __restrict__ beta,
                  const float* __restrict__ bvec) {
    extern __shared__ __align__(16) char smem[];
    float* tile = (float*)(smem + LTILE_OFF);
    __nv_bfloat16* sA  = (__nv_bfloat16*)(smem + LA_OFF);
    __nv_bfloat16* sWT = (__nv_bfloat16*)(smem + LWT_OFF);   // 96 x 104 bf16 (one half)
    float* sB  = (float*)(smem + LB_OFF);
    float* sG  = sB + COUT;
    float* sBt = sG + 96;

    int tid = threadIdx.x, wid = tid >> 5, lane = tid & 31;
    int g = lane >> 2, tig = lane & 3;
    long t0 = (long)blockIdx.x * 128;
    int b  = (int)(t0 / SPD);
    int s0 = (int)(t0 % SPD);
    int r0 = wid * 16;
    uint32_t sb = smem_u32(smem);

    const float* inb = in + (long)b * 96 * SPD + s0;
    for (int i = tid; i < 96 * 128; i += 256) {
        int c = i >> 7, t = i & 127;
        tile[c * LTS + t] = inb[(long)c * SPD + t];
    }
    for (int i = tid; i < COUT; i += 256) sB[i] = bvec[i];
    if (tid < 96) { sG[tid] = gamma[tid]; sBt[tid] = beta[tid]; }
    __syncthreads();

    if (ISQ) {
        for (int i = tid; i < 96 * 128; i += 256) {
            int c = i % 96, t = i / 96;
            g_xt[(t0 + t) * 96 + c] = tile[c * LTS + t];
        }
    }

    // LN -> sA bf16 (own-warp rows)
    #pragma unroll 1
    for (int it = 0; it < 16; it++) {
        int t = r0 + it;
        float v0 = tile[lane * LTS + t];
        float v1 = tile[(lane + 32) * LTS + t];
        float v2 = tile[(lane + 64) * LTS + t];
        float mean = warp_sum(v0 + v1 + v2) * (1.0f / 96.0f);
        float var  = warp_sum(v0 * v0 + v1 * v1 + v2 * v2) * (1.0f / 96.0f) - mean * mean;
        float inv  = rsqrtf(var + 1e-5f);
        sA[t * LASTR + lane]      = __float2bfloat16_rn((v0 - mean) * inv * sG[lane]      + sBt[lane]);
        sA[t * LASTR + lane + 32] = __float2bfloat16_rn((v1 - mean) * inv * sG[lane + 32] + sBt[lane + 32]);
        sA[t * LASTR + lane + 64] = __float2bfloat16_rn((v2 - mean) * inv * sG[lane + 64] + sBt[lane + 64]);
    }

    long base0, base1;
    {
        long bases[2];
        int rows[2] = { r0 + g, r0 + g + 8 };
        #pragma unroll
        for (int rr = 0; rr < 2; rr++) {
            long t = t0 + rows[rr];
            int s = (int)(t % SPD);
            int d = s / (HH * WW_), h = (s / WW_) % HH, w = s % WW_;
            int wi = ((b * NWD + d / WIN_D) * NWH + h / WIN_H) * NWW + w / WIN_W;
            int n  = (d % WIN_D) * 30 + (h % WIN_H) * 5 + (w % WIN_W);
            bases[rr] = ((long)wi * NT + n) * 96;
        }
        base0 = bases[0]; base1 = bases[1];
    }

    const int NHALF = COUT / 96;
    #pragma unroll
    for (int half = 0; half < NHALF; half++) {
        __syncthreads();   // prior-half sWT reads done
        const __nv_bfloat16* wsrc = ISQ ? g_wqT : (half == 0 ? g_wkT : g_wvT);
        for (int i = tid; i < 96 * 12; i += 256) {
            int n = i / 12, c = i % 12;
            cp16(sb + LWT_OFF + n * 208 + c * 16, (const char*)(wsrc + n * 96) + c * 16);
        }
        CP_COMMIT(); CP_WAIT0();
        __syncthreads();

        float c[12][4];
        #pragma unroll
        for (int nt = 0; nt < 12; nt++) { c[nt][0]=0.f; c[nt][1]=0.f; c[nt][2]=0.f; c[nt][3]=0.f; }
        #pragma unroll
        for (int kk = 0; kk < 6; kk++) {
            int kb = kk * 16 + tig * 2;
            uint32_t a0 = *(const uint32_t*)(sA + (r0 + g)     * LASTR + kb);
            uint32_t a1 = *(const uint32_t*)(sA + (r0 + g + 8) * LASTR + kb);
            uint32_t a2 = *(const uint32_t*)(sA + (r0 + g)     * LASTR + kb + 8);
            uint32_t a3 = *(const uint32_t*)(sA + (r0 + g + 8) * LASTR + kb + 8);
            #pragma unroll
            for (int nt = 0; nt < 12; nt++) {
                int n = nt * 8 + g;
                uint32_t b0 = *(const uint32_t*)(sWT + n * LASTR + kb);
                uint32_t b1 = *(const uint32_t*)(sWT + n * LASTR + kb + 8);
                mma16816(c[nt], a0, a1, a2, a3, b0, b1);
            }
        }
        __nv_bfloat16* dst = ISQ ? g_q : (half == 0 ? g_k : g_v);
        #pragma unroll
        for (int nt = 0; nt < 12; nt++) {
            int col = nt * 8 + tig * 2;
            float b0v = sB[half * 96 + col], b1v = sB[half * 96 + col + 1];
            *(uint32_t*)(dst + base0 + col) = pack_bf16(c[nt][0] + b0v, c[nt][1] + b1v);
            *(uint32_t*)(dst + base1 + col) = pack_bf16(c[nt][2] + b0v, c[nt][3] + b1v);
        }
    }
}

// ---------------- K3: attention, 2 CTAs per window (80 rows each) ----------------
#define AQS 104
#define ASQ_OFF 0          /* 80 x 208B  = 16640 */
#define ASK_OFF 16640      /* 152 x 208B = 31616 */
#define ASV_OFF 48256      /* 160 x 208B = 33280 */
#define ASW_OFF 81536      /* 96 x 208B  = 19968 */
#define ASBP_OFF 101504
#define ATT_SMEM 101888

__global__ void __launch_bounds__(160, 2)
attn_mma_kernel(const float* __restrict__ bproj) {
    extern __shared__ __align__(16) char smem[];
    __nv_bfloat16* sQ  = (__nv_bfloat16*)(smem + ASQ_OFF);
    __nv_bfloat16* sK  = (__nv_bfloat16*)(smem + ASK_OFF);
    __nv_bfloat16* sV  = (__nv_bfloat16*)(smem + ASV_OFF);
    __nv_bfloat16* sWp = (__nv_bfloat16*)(smem + ASW_OFF);
    float* sBp = (float*)(smem + ASBP_OFF);

    int tid = threadIdx.x, wid = tid >> 5, lane = tid & 31;
    int g = lane >> 2, tig = lane & 3;
    int wi   = blockIdx.x >> 1;
    int half = blockIdx.x & 1;
    int r0 = wid * 16;                 // local row base (0..64)
    int rowoff = half * 80;            // global row offset
    const float scale = 0.102062072615965696f;

    const char* gq = (const char*)(g_q + (long)wi * NT * 96);
    const char* gk = (const char*)(g_k + (long)wi * NT * 96);
    const char* gv = (const char*)(g_v + (long)wi * NT * 96);

    uint32_t sb = smem_u32(smem);
    int qrows = half ? 70 : 80;       // real Q rows staged
    for (int i = tid; i < qrows * 12; i += 160) {
        int r = i / 12, c = i % 12;
        cp16(sb + ASQ_OFF + r * 208 + c * 16, gq + (rowoff + r) * 192 + c * 16);
    }
    for (int i = tid; i < 150 * 12; i += 160) {
        int r = i / 12, c = i % 12;
        cp16(sb + ASK_OFF + r * 208 + c * 16, gk + r * 192 + c * 16);
        cp16(sb + ASV_OFF + r * 208 + c * 16, gv + r * 192 + c * 16);
    }
    for (int i = tid; i < 96 * 12; i += 160) {
        int n = i / 12, c = i % 12;
        cp16(sb + ASW_OFF + n * 208 + c * 16, (const char*)(g_wpT + n * 96) + c * 16);
    }
    if (tid < 96) sBp[tid] = bproj[tid];
    // zero pad rows
    {
        uint32_t* zk = (uint32_t*)(sK + 150 * AQS);
        uint32_t* zv = (uint32_t*)(sV + 150 * AQS);
        for (int i = tid; i < 520; i += 160) zv[i] = 0u;
        for (int i = tid; i < 104; i += 160) zk[i] = 0u;
        if (half) {
            uint32_t* zq = (uint32_t*)(sQ + 70 * AQS);
            for (int i = tid; i < 520; i += 160) zq[i] = 0u;
        }
    }
    CP_COMMIT(); CP_WAIT0();
    __syncthreads();

    // ---- GEMM1: S stripe (16 x 152) ----
    float cs[19][4];
    #pragma unroll
    for (int nt = 0; nt < 19; nt++) { cs[nt][0]=0.f; cs[nt][1]=0.f; cs[nt][2]=0.f; cs[nt][3]=0.f; }
    #pragma unroll
    for (int kk = 0; kk < 6; kk++) {
        int kb = kk * 16 + tig * 2;
        uint32_t a0 = *(const uint32_t*)(sQ + (r0 + g)     * AQS + kb);
        uint32_t a1 = *(const uint32_t*)(sQ + (r0 + g + 8) * AQS + kb);
        uint32_t a2 = *(const uint32_t*)(sQ + (r0 + g)     * AQS + kb + 8);
        uint32_t a3 = *(const uint32_t*)(sQ + (r0 + g + 8) * AQS + kb + 8);
        #pragma unroll
        for (int nt = 0; nt < 19; nt++) {
            int m = nt * 8 + g;
            uint32_t b0 = *(const uint32_t*)(sK + m * AQS + kb);
            uint32_t b1 = *(const uint32_t*)(sK + m * AQS + kb + 8);
            mma16816(cs[nt], a0, a1, a2, a3, b0, b1);
        }
    }

    // ---- softmax (global rows) ----
    int n0r = rowoff + r0 + g, n1r = rowoff + r0 + g + 8;
    float mx0 = -1e30f, mx1 = -1e30f;
    #pragma unroll
    for (int nt = 0; nt < 19; nt++) {
        int m = nt * 8 + tig * 2;
        if (m < NT) {
            if (n0r < NT) {
                float2 bv = *(const float2*)(g_bias + n0r * NT + m);
                cs[nt][0] = cs[nt][0] * scale + bv.x;
                cs[nt][1] = cs[nt][1] * scale + bv.y;
            } else { cs[nt][0] = 0.f; cs[nt][1] = 0.f; }
            if (n1r < NT) {
                float2 bv = *(const float2*)(g_bias + n1r * NT + m);
                cs[nt][2] = cs[nt][2] * scale + bv.x;
                cs[nt][3] = cs[nt][3] * scale + bv.y;
            } else { cs[nt][2] = 0.f; cs[nt][3] = 0.f; }
            mx0 = fmaxf(mx0, fmaxf(cs[nt][0], cs[nt][1]));
            mx1 = fmaxf(mx1, fmaxf(cs[nt][2], cs[nt][3]));
        } else {
            cs[nt][0] = -1e30f; cs[nt][1] = -1e30f;
            cs[nt][2] = -1e30f; cs[nt][3] = -1e30f;
        }
    }
    mx0 = fmaxf(mx0, __shfl_xor_sync(0xffffffffu, mx0, 1));
    mx0 = fmaxf(mx0, __shfl_xor_sync(0xffffffffu, mx0, 2));
    mx1 = fmaxf(mx1, __shfl_xor_sync(0xffffffffu, mx1, 1));
    mx1 = fmaxf(mx1, __shfl_xor_sync(0xffffffffu, mx1, 2));
    float s0 = 0.f, s1 = 0.f;
    #pragma unroll
    for (int nt = 0; nt < 19; nt++) {
        cs[nt][0] = __expf(cs[nt][0] - mx0);
        cs[nt][1] = __expf(cs[nt][1] - mx0);
        cs[nt][2] = __expf(cs[nt][2] - mx1);
        cs[nt][3] = __expf(cs[nt][3] - mx1);
        s0 += cs[nt][0] + cs[nt][1];
        s1 += cs[nt][2] + cs[nt][3];
    }
    s0 += __shfl_xor_sync(0xffffffffu, s0, 1);
    s0 += __shfl_xor_sync(0xffffffffu, s0, 2);
    s1 += __shfl_xor_sync(0xffffffffu, s1, 1);
    s1 += __shfl_xor_sync(0xffffffffu, s1, 2);
    float inv0 = 1.0f / s0, inv1 = 1.0f / s1;

    uint32_t pa[10][4];
    #pragma unroll
    for (int kt = 0; kt < 10; kt++) {
        int e = 2 * kt, o = 2 * kt + 1;
        pa[kt][0] = pack_bf16(cs[e][0] * inv0, cs[e][1] * inv0);
        pa[kt][1] = pack_bf16(cs[e][2] * inv1, cs[e][3] * inv1);
        if (o < 19) {
            pa[kt][2] = pack_bf16(cs[o][0] * inv0, cs[o][1] * inv0);
            pa[kt][3] = pack_bf16(cs[o][2] * inv1, cs[o][3] * inv1);
        } else { pa[kt][2] = 0u; pa[kt][3] = 0u; }
    }

    // ---- GEMM2: O = P @ V (V row-major) ----
    float co[12][4];
    #pragma unroll
    for (int nt = 0; nt < 12; nt++) { co[nt][0]=0.f; co[nt][1]=0.f; co[nt][2]=0.f; co[nt][3]=0.f; }
    #pragma unroll
    for (int kt = 0; kt < 10; kt++) {
        int kb = kt * 16 + tig * 2;
        const uint16_t* v0p = (const uint16_t*)(sV + (kb + 0) * AQS);
        const uint16_t* v1p = (const uint16_t*)(sV + (kb + 1) * AQS);
        const uint16_t* v8p = (const uint16_t*)(sV + (kb + 8) * AQS);
        const uint16_t* v9p = (const uint16_t*)(sV + (kb + 9) * AQS);
        #pragma unroll
        for (int nt = 0; nt < 12; nt++) {
            int n = nt * 8 + g;
            uint32_t b0 = (uint32_t)v0p[n] | ((uint32_t)v1p[n] << 16);
            uint32_t b1 = (uint32_t)v8p[n] | ((uint32_t)v9p[n] << 16);
            mma16816(co[nt], pa[kt][0], pa[kt][1], pa[kt][2], pa[kt][3], b0, b1);
        }
    }

    uint32_t oa[6][4];
    #pragma unroll
    for (int kt = 0; kt < 6; kt++) {
        oa[kt][0] = pack_bf16(co[2*kt][0],   co[2*kt][1]);
        oa[kt][1] = pack_bf16(co[2*kt][2],   co[2*kt][3]);
        oa[kt][2] = pack_bf16(co[2*kt+1][0], co[2*kt+1][1]);
        oa[kt][3] = pack_bf16(co[2*kt+1][2], co[2*kt+1][3]);
    }
    float c2r[12][4];
    #pragma unroll
    for (int nt = 0; nt < 12; nt++) { c2r[nt][0]=0.f; c2r[nt][1]=0.f; c2r[nt][2]=0.f; c2r[nt][3]=0.f; }
    #pragma unroll
    for (int kt = 0; kt < 6; kt++) {
        int kb = kt * 16 + tig * 2;
        #pragma unroll
        for (int nt = 0; nt < 12; nt++) {
            int cp = nt * 8 + g;
            uint32_t b0 = *(const uint32_t*)(sWp + cp * AQS + kb);
            uint32_t b1 = *(const uint32_t*)(sWp + cp * AQS + kb + 8);
            mma16816(c2r[nt], oa[kt][0], oa[kt][1], oa[kt][2], oa[kt][3], b0, b1);
        }
    }

    int iww = wi & 7, iwh = (wi >> 3) & 7, iwd = (wi >> 6) & 7, b = wi >> 9;
    long t0r = -1, t1r = -1;
    if (n0r < NT) {
        int zd = n0r / 30, zh = (n0r / 5) % 6, zw = n0r % 5;
        int d = iwd * WIN_D + zd, h = iwh * WIN_H + zh, w = iww * WIN_W + zw;
        t0r = (long)b * SPD + ((long)d * HH + h) * WW_ + w;
    }
    if (n1r < NT) {
        int zd = n1r / 30, zh = (n1r / 5) % 6, zw = n1r % 5;
        int d = iwd * WIN_D + zd, h = iwh * WIN_H + zh, w = iww * WIN_W + zw;
        t1r = (long)b * SPD + ((long)d * HH + h) * WW_ + w;
    }
    #pragma unroll
    for (int nt = 0; nt < 12; nt++) {
        int cp = nt * 8 + tig * 2;
        float b0v = sBp[cp], b1v = sBp[cp + 1];
        if (t0r >= 0) {
            float2 x = *(const float2*)(g_xt + t0r * 96 + cp);
            float2 o = make_float2(x.x + c2r[nt][0] + b0v, x.y + c2r[nt][1] + b1v);
            *(float2*)(g_x2 + t0r * 96 + cp) = o;
        }
        if (t1r >= 0) {
            float2 x = *(const float2*)(g_xt + t1r * 96 + cp);
            float2 o = make_float2(x.x + c2r[nt][2] + b0v, x.y + c2r[nt][3] + b1v);
            *(float2*)(g_x2 + t1r * 96 + cp) = o;
        }
    }
}

// ---------------- K4: fused LN2 + MLP via mma.sync (cp.async weight staging) ----------------
#define ASTR 104
#define W1S  104
#define W2S  136
#define MA_OFF    0
#define MW1_OFF   26624
#define MW2_OFF   53248
#define MB1F_OFF  79360
#define MB2F_OFF  80896
#define MLG_OFF   81280
#define MLB_OFF   81664
#define MLP_SMEM  82048

__global__ void __launch_bounds__(256, 2)
mlp_mma_kernel(const float* __restrict__ g2, const float* __restrict__ b2ln,
               const float* __restrict__ b1, const float* __restrict__ b2) {
    extern __shared__ __align__(16) char smem[];
    __nv_bfloat16* sA   = (__nv_bfloat16*)(smem + MA_OFF);
    __nv_bfloat16* sW1T = (__nv_bfloat16*)(smem + MW1_OFF);
    __nv_bfloat16* sW2T = (__nv_bfloat16*)(smem + MW2_OFF);
    float* sb1f = (float*)(smem + MB1F_OFF);
    float* sb2f = (float*)(smem + MB2F_OFF);
    float* slg  = (float*)(smem + MLG_OFF);
    float* slb  = (float*)(smem + MLB_OFF);

    int tid = threadIdx.x, wid = tid >> 5, lane = tid & 31;
    int g = lane >> 2, tig = lane & 3;
    long t0 = (long)blockIdx.x * 128;
    int r0 = wid * 16;
    uint32_t sb = smem_u32(smem);

    for (int i = tid; i < HID; i += 256) sb1f[i] = b1[i];
    if (tid < 96) { sb2f[tid] = b2[tid]; slg[tid] = g2[tid]; slb[tid] = b2ln[tid]; }
    __syncthreads();

    #pragma unroll 1
    for (int it = 0; it < 16; it++) {
        int r = r0 + it;
        const float* xr = g_x2 + (t0 + r) * 96;
        float v0 = xr[lane], v1 = xr[lane + 32], v2 = xr[lane + 64];
        float mean = warp_sum(v0 + v1 + v2) * (1.0f / 96.0f);
        float var  = warp_sum(v0 * v0 + v1 * v1 + v2 * v2) * (1.0f / 96.0f) - mean * mean;
        float inv  = rsqrtf(var + 1e-5f);
        sA[r * ASTR + lane]      = __float2bfloat16_rn((v0 - mean) * inv * slg[lane]      + slb[lane]);
        sA[r * ASTR + lane + 32] = __float2bfloat16_rn((v1 - mean) * inv * slg[lane + 32] + slb[lane + 32]);
        sA[r * ASTR + lane + 64] = __float2bfloat16_rn((v2 - mean) * inv * slg[lane + 64] + slb[lane + 64]);
    }

    float c2[12][4];
    #pragma unroll
    for (int nt = 0; nt < 12; nt++) { c2[nt][0]=0.f; c2[nt][1]=0.f; c2[nt][2]=0.f; c2[nt][3]=0.f; }

    uint32_t h[16][2];

    for (int j = 0; j < 3; j++) {
        __syncthreads();
        // stage W1 chunk rows [j*128, +128) of g_w1T (96 bf16 each = 12 cp16)
        for (int i = tid; i < 128 * 12; i += 256) {
            int n = i / 12, c = i % 12;
            cp16(sb + MW1_OFF + n * 208 + c * 16,
                 (const char*)(g_w1T + (long)(j * 128 + n) * 96) + c * 16);
        }
        // stage W2 chunk: rows n<96 of g_w2T, k-slice [j*128, +128) (256B = 16 cp16)
        for (int i = tid; i < 96 * 16; i += 256) {
            int n = i / 16, c = i % 16;
            cp16(sb + MW2_OFF + n * 272 + c * 16,
                 (const char*)(g_w2T + (long)n * HID + j * 128) + c * 16);
        }
        CP_COMMIT(); CP_WAIT0();
        __syncthreads();

        #pragma unroll
        for (int half = 0; half < 2; half++) {
            float c1[8][4];
            #pragma unroll
            for (int nt = 0; nt < 8; nt++) { c1[nt][0]=0.f; c1[nt][1]=0.f; c1[nt][2]=0.f; c1[nt][3]=0.f; }
            #pragma unroll
            for (int kk = 0; kk < 6; kk++) {
                int kb = kk * 16 + tig * 2;
                uint32_t a0 = *(const uint32_t*)(sA + (r0 + g) * ASTR + kb);
                uint32_t a1 = *(const uint32_t*)(sA + (r0 + g + 8) * ASTR + kb);
                uint32_t a2 = *(const uint32_t*)(sA + (r0 + g) * ASTR + kb + 8);
                uint32_t a3 = *(const uint32_t*)(sA + (r0 + g + 8) * ASTR + kb + 8);
                #pragma unroll
                for (int nt = 0; nt < 8; nt++) {
                    int n = (half * 8 + nt) * 8 + g;
                    uint32_t b0 = *(const uint32_t*)(sW1T + n * W1S + kb);
                    uint32_t b1v = *(const uint32_t*)(sW1T + n * W1S + kb + 8);
                    mma16816(c1[nt], a0, a1, a2, a3, b0, b1v);
                }
            }
            #pragma unroll
            for (int nt = 0; nt < 8; nt++) {
                int nn = (half * 8 + nt) * 8 + tig * 2;
                float bb0 = sb1f[j * 128 + nn], bb1 = sb1f[j * 128 + nn + 1];
                h[half * 8 + nt][0] = pack_bf16(gelu_fast(c1[nt][0] + bb0), gelu_fast(c1[nt][1] + bb1));
                h[half * 8 + nt][1] = pack_bf16(gelu_fast(c1[nt][2] + bb0), gelu_fast(c1[nt][3] + bb1));
            }
        }

        #pragma unroll
        for (int kk = 0; kk < 8; kk++) {
            uint32_t a0 = h[2 * kk][0], a1 = h[2 * kk][1];
            uint32_t a2 = h[2 * kk + 1][0], a3 = h[2 * kk + 1][1];
            int kb = kk * 16 + tig * 2;
            #pragma unroll
            for (int nt = 0; nt < 12; nt++) {
                int n = nt * 8 + g;
                uint32_t b0 = *(const uint32_t*)(sW2T + n * W2S + kb);
                uint32_t b1v = *(const uint32_t*)(sW2T + n * W2S + kb + 8);
                mma16816(c2[nt], a0, a1, a2, a3, b0, b1v);
            }
        }
    }

    #pragma unroll
    for (int nt = 0; nt < 12; nt++) {
        int n = nt * 8 + tig * 2;
        long ra = t0 + r0 + g;
        float bb0 = sb2f[n], bb1 = sb2f[n + 1];
        float2 x0 = *(const float2*)(g_x2 + ra * 96 + n);
        float2 x1 = *(const float2*)(g_x2 + (ra + 8) * 96 + n);
        float2 o0 = make_float2(x0.x + c2[nt][0] + bb0, x0.y + c2[nt][1] + bb1);
        float2 o1 = make_float2(x1.x + c2[nt][2] + bb0, x1.y + c2[nt][3] + bb1);
        *(float2*)(g_x3 + ra * 96 + n) = o0;
        *(float2*)(g_x3 + (ra + 8) * 96 + n) = o1;
    }
}

// ---------------- K6: conv3d 3x3x3, 96 -> 3 (1 voxel/thread, grid 600) ----------------
__global__ void __launch_bounds__(256)
conv_kernel(const float* __restrict__ cw, const float* __restrict__ cbias,
            float* __restrict__ out) {
    __shared__ __align__(16) float sWc[27 * 3 * 96];
    __shared__ float sCB[3];
    int tid = threadIdx.x;
    for (int i = tid; i < 27 * 3 * 96; i += 256) {
        int k = i / 288, r = i % 288, o = r / 96, c = r % 96;
        sWc[i] = cw[((long)o * 96 + c) * 27 + k];
    }
    if (tid < 3) sCB[tid] = cbias[tid];
    __syncthreads();

    long t = (long)blockIdx.x * 256 + tid;
    int b = (int)(t / SPD);
    int s = (int)(t % SPD);
    int d = s / (HH * WW_), hh = (s / WW_) % HH, ww = s % WW_;

    float acc[3] = {0.f, 0.f, 0.f};
    for (int kd = -1; kd <= 1; kd++)
    for (int kh = -1; kh <= 1; kh++)
    for (int kw = -1; kw <= 1; kw++) {
        int k = (kd + 1) * 9 + (kh + 1) * 3 + (kw + 1);
        int d2 = d + kd, h2 = hh + kh, w2 = ww + kw;
        bool ok = ((unsigned)d2 < DD) && ((unsigned)h2 < HH) && ((unsigned)w2 < WW_);
        long nb = (long)b * SPD + ((long)d2 * HH + h2) * WW_ + w2;
        const float4* src = (const float4*)(g_x3 + nb * 96);
        const float* wk = sWc + k * 288;
        #pragma unroll 4
        for (int c4 = 0; c4 < 24; c4++) {
            float4 xv = ok ? src[c4] : make_float4(0.f, 0.f, 0.f, 0.f);
            #pragma unroll
            for (int o = 0; o < 3; o++) {
                float4 w4 = ((const float4*)(wk + o * 96))[c4];
                acc[o] += xv.x * w4.x + xv.y * w4.y + xv.z * w4.z + xv.w * w4.w;
            }
        }
    }
    #pragma unroll
    for (int o = 0; o < 3; o++)
        out[((long)b * 3 + o) * SPD + s] = acc[o] + sCB[o];
}

// ---------------- launch ----------------
extern "C" void kernel_launch(void* const* d_in, const int* in_sizes, int n_in,
                              void* d_out, int out_size) {
    const float* I_m    = (const float*)d_in[0];
    const float* I_f    = (const float*)d_in[1];
    const float* ln1q_g = (const float*)d_in[2];
    const float* ln1q_b = (const float*)d_in[3];
    const float* ln1kv_g= (const float*)d_in[4];
    const float* ln1kv_b= (const float*)d_in[5];
    const float* wq     = (const float*)d_in[6];
    const float* bq     = (const float*)d_in[7];
    const float* wkv    = (const float*)d_in[8];
    const float* bkv    = (const float*)d_in[9];
    const float* wproj  = (const float*)d_in[10];
    const float* bproj  = (const float*)d_in[11];
    const float* relb   = (const float*)d_in[12];
    const float* ln2_g  = (const float*)d_in[13];
    const float* ln2_b  = (const float*)d_in[14];
    const float* w1     = (const float*)d_in[15];
    const float* b1     = (const float*)d_in[16];
    const float* w2     = (const float*)d_in[17];
    const float* b2     = (const float*)d_in[18];
    const float* cw     = (const float*)d_in[19];
    const float* cb     = (const float*)d_in[20];
    float* out = (float*)d_out;

    const int smem_q  = LB_OFF + 96 * 4 + 768;
    const int smem_kv = LB_OFF + 192 * 4 + 768;

    cudaFuncSetAttribute(lnproj_mma_kernel<96,  true >, cudaFuncAttributeMaxDynamicSharedMemorySize, smem_q);
    cudaFuncSetAttribute(lnproj_mma_kernel<192, false>, cudaFuncAttributeMaxDynamicSharedMemorySize, smem_kv);
    cudaFuncSetAttribute(attn_mma_kernel, cudaFuncAttributeMaxDynamicSharedMemorySize, ATT_SMEM);
    cudaFuncSetAttribute(mlp_mma_kernel, cudaFuncAttributeMaxDynamicSharedMemorySize, MLP_SMEM);

    bias_kernel<<<(NT*NT + 255) / 256, 256>>>(relb);
    prep_w_kernel<<<144, 256>>>(wq, wkv, wproj, w1, w2);
    lnproj_mma_kernel<96,  true ><<<TOT / 128, 256, smem_q >>>(I_m, ln1q_g,  ln1q_b,  bq);
    lnproj_mma_kernel<192, false><<<TOT / 128, 256, smem_kv>>>(I_f, ln1kv_g, ln1kv_b, bkv);
    attn_mma_kernel<<<NWIN * 2, 160, ATT_SMEM>>>(bproj);
    mlp_mma_kernel<<<TOT / 128, 256, MLP_SMEM>>>(ln2_g, ln2_b, b1, b2);
    conv_kernel<<<TOT / 256, 256>>>(cw, cb, out);
}